// round 1
// baseline (speedup 1.0000x reference)
#include <cuda_runtime.h>
#include <math.h>

#define H 128
#define NMAX 100000
#define EMAX 200000
#define GMAX 4096

#define CDIV(a,b) (((a)+(b)-1)/(b))

// ---------------- scratch (device globals; no allocation) ----------------
__device__ float g_node[(size_t)NMAX*H];
__device__ float g_edge[(size_t)EMAX*H];
__device__ float g_agg [(size_t)NMAX*H];
__device__ float g_z   [(size_t)NMAX*H];
__device__ float g_t1  [(size_t)NMAX*H];
__device__ float g_m   [(size_t)NMAX*H];
__device__ float g_gi  [(size_t)NMAX*3*H];
__device__ float g_gh  [(size_t)NMAX*3*H];
__device__ float g_et  [(size_t)EMAX*H];
__device__ float g_qs  [(size_t)GMAX*2*H];
__device__ float g_hl  [(size_t)GMAX*H];
__device__ float g_cl  [(size_t)GMAX*H];
__device__ float g_r   [(size_t)GMAX*H];
__device__ float g_gl  [(size_t)GMAX*4*H];
__device__ float g_fc  [(size_t)GMAX*H];
__device__ float g_e   [NMAX];
__device__ float g_ex  [NMAX];
__device__ unsigned g_emaxk[GMAX];
__device__ float g_denom[GMAX];
// transposed weights (so every GEMM is A[M,K] @ W[K,128])
__device__ float t_gwih[H*3*H];    // [128][384]
__device__ float t_gwhh[H*3*H];    // [128][384]
__device__ float t_lwih[2*H*4*H];  // [256][512]
__device__ float t_lwhh[H*4*H];    // [128][512]

// ---------------- helpers ----------------
__device__ __forceinline__ float sigf(float x) { return 1.f / (1.f + expf(-x)); }

__device__ __forceinline__ unsigned fkey(float f) {
    unsigned u = __float_as_uint(f);
    return (u & 0x80000000u) ? ~u : (u | 0x80000000u);
}
__device__ __forceinline__ float fdec(unsigned k) {
    unsigned u = (k & 0x80000000u) ? (k ^ 0x80000000u) : ~k;
    return __uint_as_float(u);
}

// ---------------- generic GEMM: O[M,128] = act(A[M,K] @ W[K,128] + bias) ----------------
// flags: bit0 = ReLU, bit1 = accumulate into O (O += result; bias still added)
__global__ void __launch_bounds__(256) k_gemm(
    const float* __restrict__ A, int lda,
    const float* __restrict__ W, int ldw,
    const float* __restrict__ bias,
    float* __restrict__ O, int ldo,
    int M, int K, int flags)
{
    __shared__ __align__(16) float As[16][36];   // transposed A tile (pad=36 to avoid bank conflicts)
    __shared__ __align__(16) float Ws[16][128];
    const int tid = threadIdx.x;
    const int tx = tid & 31, ty = tid >> 5;
    const int row0 = blockIdx.x * 32;
    float acc[4][4];
#pragma unroll
    for (int i = 0; i < 4; i++)
#pragma unroll
        for (int j = 0; j < 4; j++) acc[i][j] = 0.f;

    for (int k0 = 0; k0 < K; k0 += 16) {
#pragma unroll
        for (int i = tid; i < 512; i += 256) {
            int r = i >> 4, k = i & 15;
            int row = row0 + r, kk = k0 + k;
            As[k][r] = (row < M && kk < K) ? A[(size_t)row * lda + kk] : 0.f;
        }
#pragma unroll
        for (int i = tid; i < 2048; i += 256) {
            int k = i >> 7, j = i & 127;
            int kk = k0 + k;
            Ws[k][j] = (kk < K) ? W[(size_t)kk * ldw + j] : 0.f;
        }
        __syncthreads();
#pragma unroll
        for (int k = 0; k < 16; k++) {
            float4 a4 = *(const float4*)&As[k][ty << 2];
            float4 w4 = *(const float4*)&Ws[k][tx << 2];
            float a[4] = {a4.x, a4.y, a4.z, a4.w};
            float w[4] = {w4.x, w4.y, w4.z, w4.w};
#pragma unroll
            for (int r = 0; r < 4; r++)
#pragma unroll
                for (int c = 0; c < 4; c++) acc[r][c] = fmaf(a[r], w[c], acc[r][c]);
        }
        __syncthreads();
    }
    const int col = tx << 2;
    float4 b4 = *(const float4*)&bias[col];
    float bb[4] = {b4.x, b4.y, b4.z, b4.w};
#pragma unroll
    for (int r = 0; r < 4; r++) {
        int row = row0 + (ty << 2) + r;
        if (row < M) {
            float v[4];
#pragma unroll
            for (int c = 0; c < 4; c++) v[c] = acc[r][c] + bb[c];
            if (flags & 2) {
                float4 o = *(const float4*)&O[(size_t)row * ldo + col];
                v[0] += o.x; v[1] += o.y; v[2] += o.z; v[3] += o.w;
            }
            if (flags & 1) {
#pragma unroll
                for (int c = 0; c < 4; c++) v[c] = fmaxf(v[c], 0.f);
            }
            float4 ov = {v[0], v[1], v[2], v[3]};
            *(float4*)&O[(size_t)row * ldo + col] = ov;
        }
    }
}

// ---------------- small kernels ----------------
__global__ void k_zero(float* __restrict__ p, int n) {
    int i = blockIdx.x * blockDim.x + threadIdx.x;
    if (i < n) p[i] = 0.f;
}

__global__ void k_transpose(const float* __restrict__ in, float* __restrict__ out,
                            int rows, int cols) {
    int idx = blockIdx.x * blockDim.x + threadIdx.x;
    if (idx < rows * cols) {
        int r = idx / cols, c = idx % cols;
        out[(size_t)c * rows + r] = in[idx];
    }
}

// msg = relu(node[src] + edge); atomic scatter-add into agg[dst]
__global__ void k_scatter(const int* __restrict__ src, const int* __restrict__ dst,
                          const float* __restrict__ node, const float* __restrict__ edge,
                          float* __restrict__ agg, int E)
{
    int tid = blockIdx.x * blockDim.x + threadIdx.x;
    int e = tid >> 5;
    if (e >= E) return;
    int lane = tid & 31;
    int s = src[e], d = dst[e];
    float4 nv = *(const float4*)&node[(size_t)s * H + lane * 4];
    float4 ev = *(const float4*)&edge[(size_t)e * H + lane * 4];
    float m0 = fmaxf(nv.x + ev.x, 0.f);
    float m1 = fmaxf(nv.y + ev.y, 0.f);
    float m2 = fmaxf(nv.z + ev.z, 0.f);
    float m3 = fmaxf(nv.w + ev.w, 0.f);
    float* ap = &agg[(size_t)d * H + lane * 4];
    atomicAdd(ap + 0, m0);
    atomicAdd(ap + 1, m1);
    atomicAdd(ap + 2, m2);
    atomicAdd(ap + 3, m3);
}

__global__ void k_zmix(const float* __restrict__ eps, int l,
                       const float* __restrict__ node, const float* __restrict__ agg,
                       float* __restrict__ z, int n)
{
    int i = blockIdx.x * blockDim.x + threadIdx.x;
    if (i < n) z[i] = (1.f + eps[l]) * node[i] + agg[i];
}

// GRU elementwise: h = (1-z)*n + z*h   (gi/gh are [N,384] packed r|z|n)
__global__ void k_gru(const float* __restrict__ gi, const float* __restrict__ gh,
                      float* __restrict__ h, int n)
{
    int idx = blockIdx.x * blockDim.x + threadIdx.x;
    if (idx >= n) return;
    int row = idx >> 7, j = idx & 127;
    const float* gir = &gi[(size_t)row * 384];
    const float* ghr = &gh[(size_t)row * 384];
    float r  = sigf(gir[j]       + ghr[j]);
    float zt = sigf(gir[j + 128] + ghr[j + 128]);
    float nn = tanhf(gir[j + 256] + r * ghr[j + 256]);
    float hv = h[idx];
    h[idx] = (1.f - zt) * nn + zt * hv;
}

// LSTM elementwise (gl is [G,512] packed i|f|g|o)
__global__ void k_lstm(const float* __restrict__ gl, float* __restrict__ hl,
                       float* __restrict__ cl, int n)
{
    int idx = blockIdx.x * blockDim.x + threadIdx.x;
    if (idx >= n) return;
    int g = idx >> 7, j = idx & 127;
    const float* gr = &gl[(size_t)g * 512];
    float i_ = gr[j], f_ = gr[j + 128], gg = gr[j + 256], o_ = gr[j + 384];
    float c = sigf(f_) * cl[idx] + sigf(i_) * tanhf(gg);
    cl[idx] = c;
    hl[idx] = sigf(o_) * tanhf(c);
}

// e[n] = dot(node[n], q[batch[n]]); atomicMax per-graph (key-encoded)
__global__ void k_edot(const int* __restrict__ batch, const float* __restrict__ node,
                       const float* __restrict__ q, float* __restrict__ e,
                       unsigned* __restrict__ emaxk, int N)
{
    int tid = blockIdx.x * blockDim.x + threadIdx.x;
    int n = tid >> 5;
    if (n >= N) return;
    int lane = tid & 31;
    int b = batch[n];
    float s = 0.f;
#pragma unroll
    for (int t = 0; t < 4; t++) {
        int j = lane + t * 32;
        s += node[(size_t)n * H + j] * q[(size_t)b * H + j];
    }
#pragma unroll
    for (int off = 16; off; off >>= 1) s += __shfl_xor_sync(0xffffffffu, s, off);
    if (lane == 0) {
        e[n] = s;
        atomicMax(&emaxk[b], fkey(s));
    }
}

__global__ void k_expsum(const int* __restrict__ batch, const float* __restrict__ e,
                         float* __restrict__ ex, const unsigned* __restrict__ emaxk,
                         float* __restrict__ denom, int N)
{
    int n = blockIdx.x * blockDim.x + threadIdx.x;
    if (n >= N) return;
    int b = batch[n];
    float v = expf(e[n] - fdec(emaxk[b]));
    ex[n] = v;
    atomicAdd(&denom[b], v);
}

__global__ void k_rscatter(const int* __restrict__ batch, const float* __restrict__ node,
                           const float* __restrict__ ex, const float* __restrict__ denom,
                           float* __restrict__ r, int N)
{
    int tid = blockIdx.x * blockDim.x + threadIdx.x;
    int n = tid >> 5;
    if (n >= N) return;
    int lane = tid & 31;
    int b = batch[n];
    float coef = ex[n] / fmaxf(denom[b], 1e-9f);
    float4 nv = *(const float4*)&node[(size_t)n * H + lane * 4];
    float* rp = &r[(size_t)b * H + lane * 4];
    atomicAdd(rp + 0, coef * nv.x);
    atomicAdd(rp + 1, coef * nv.y);
    atomicAdd(rp + 2, coef * nv.z);
    atomicAdd(rp + 3, coef * nv.w);
}

__global__ void k_qsbuild(const float* __restrict__ hl, const float* __restrict__ r,
                          float* __restrict__ qs, int n)
{
    int idx = blockIdx.x * blockDim.x + threadIdx.x;
    if (idx >= n) return;
    int g = idx >> 8, j = idx & 255;
    qs[idx] = (j < 128) ? hl[(size_t)g * 128 + j] : r[(size_t)g * 128 + (j - 128)];
}

__global__ void k_fc2(const float* __restrict__ fcin, const float* __restrict__ w2,
                      const float* __restrict__ b2, float* __restrict__ out, int G)
{
    int tid = blockIdx.x * blockDim.x + threadIdx.x;
    int g = tid >> 5;
    if (g >= G) return;
    int lane = tid & 31;
    float s = 0.f;
#pragma unroll
    for (int t = 0; t < 4; t++) {
        int j = lane + t * 32;
        s += fcin[(size_t)g * H + j] * w2[j];
    }
#pragma unroll
    for (int off = 16; off; off >>= 1) s += __shfl_xor_sync(0xffffffffu, s, off);
    if (lane == 0) out[g] = s + b2[0];
}

// ---------------- host launcher ----------------
extern "C" void kernel_launch(void* const* d_in, const int* in_sizes, int n_in,
                              void* d_out, int out_size)
{
    const float* x       = (const float*)d_in[0];
    const float* eattr   = (const float*)d_in[1];
    const int*   eindex  = (const int*)d_in[2];
    const int*   batch   = (const int*)d_in[3];
    const float* node_w  = (const float*)d_in[4];
    const float* node_b  = (const float*)d_in[5];
    const float* edge_w  = (const float*)d_in[6];
    const float* edge_b  = (const float*)d_in[7];
    const float* eps     = (const float*)d_in[8];
    const float* gin_w1  = (const float*)d_in[9];
    const float* gin_b1  = (const float*)d_in[10];
    const float* gin_w2  = (const float*)d_in[11];
    const float* gin_b2  = (const float*)d_in[12];
    const float* em_w1   = (const float*)d_in[13];
    const float* em_b1   = (const float*)d_in[14];
    const float* em_w2   = (const float*)d_in[15];
    const float* em_b2   = (const float*)d_in[16];
    const float* gru_wih = (const float*)d_in[17];
    const float* gru_whh = (const float*)d_in[18];
    const float* gru_bih = (const float*)d_in[19];
    const float* gru_bhh = (const float*)d_in[20];
    const float* lstm_wih= (const float*)d_in[21];
    const float* lstm_whh= (const float*)d_in[22];
    const float* lstm_bih= (const float*)d_in[23];
    const float* lstm_bhh= (const float*)d_in[24];
    const float* fc_w1   = (const float*)d_in[25];
    const float* fc_b1   = (const float*)d_in[26];
    const float* fc_w2   = (const float*)d_in[27];
    const float* fc_b2   = (const float*)d_in[28];

    const int N = in_sizes[0] / 14;
    const int E = in_sizes[1] / 4;
    const int G = out_size;

    float *p_node, *p_edge, *p_agg, *p_z, *p_t1, *p_m, *p_gi, *p_gh, *p_et;
    float *p_qs, *p_hl, *p_cl, *p_r, *p_gl, *p_fc, *p_e, *p_ex, *p_den;
    unsigned *p_emaxk;
    float *p_twih, *p_twhh, *p_tlwih, *p_tlwhh;
    cudaGetSymbolAddress((void**)&p_node, g_node);
    cudaGetSymbolAddress((void**)&p_edge, g_edge);
    cudaGetSymbolAddress((void**)&p_agg,  g_agg);
    cudaGetSymbolAddress((void**)&p_z,    g_z);
    cudaGetSymbolAddress((void**)&p_t1,   g_t1);
    cudaGetSymbolAddress((void**)&p_m,    g_m);
    cudaGetSymbolAddress((void**)&p_gi,   g_gi);
    cudaGetSymbolAddress((void**)&p_gh,   g_gh);
    cudaGetSymbolAddress((void**)&p_et,   g_et);
    cudaGetSymbolAddress((void**)&p_qs,   g_qs);
    cudaGetSymbolAddress((void**)&p_hl,   g_hl);
    cudaGetSymbolAddress((void**)&p_cl,   g_cl);
    cudaGetSymbolAddress((void**)&p_r,    g_r);
    cudaGetSymbolAddress((void**)&p_gl,   g_gl);
    cudaGetSymbolAddress((void**)&p_fc,   g_fc);
    cudaGetSymbolAddress((void**)&p_e,    g_e);
    cudaGetSymbolAddress((void**)&p_ex,   g_ex);
    cudaGetSymbolAddress((void**)&p_den,  g_denom);
    cudaGetSymbolAddress((void**)&p_emaxk, g_emaxk);
    cudaGetSymbolAddress((void**)&p_twih, t_gwih);
    cudaGetSymbolAddress((void**)&p_twhh, t_gwhh);
    cudaGetSymbolAddress((void**)&p_tlwih, t_lwih);
    cudaGetSymbolAddress((void**)&p_tlwhh, t_lwhh);

    const int TB = 256;

    // weight transposes (W.T copies so every GEMM is A @ W[K,128])
    k_transpose<<<CDIV(384 * 128, TB), TB>>>(gru_wih,  p_twih,  384, 128);
    k_transpose<<<CDIV(384 * 128, TB), TB>>>(gru_whh,  p_twhh,  384, 128);
    k_transpose<<<CDIV(512 * 256, TB), TB>>>(lstm_wih, p_tlwih, 512, 256);
    k_transpose<<<CDIV(512 * 128, TB), TB>>>(lstm_whh, p_tlwhh, 512, 128);

    // input embeddings
    k_gemm<<<CDIV(N, 32), 256>>>(x, 14, node_w, 128, node_b, p_node, 128, N, 14, 0);
    k_gemm<<<CDIV(E, 32), 256>>>(eattr, 4, edge_w, 128, edge_b, p_edge, 128, E, 4, 0);

    const int* src = eindex;
    const int* dst = eindex + E;

    for (int l = 0; l < 2; l++) {
        // GINEConv aggregation
        k_zero<<<CDIV(N * H, TB), TB>>>(p_agg, N * H);
        k_scatter<<<CDIV(E * 32, TB), TB>>>(src, dst, p_node, p_edge, p_agg, E);
        k_zmix<<<CDIV(N * H, TB), TB>>>(eps, l, p_node, p_agg, p_z, N * H);
        // GIN MLP
        k_gemm<<<CDIV(N, 32), 256>>>(p_z,  128, gin_w1 + l * H * H, 128, gin_b1 + l * H, p_t1, 128, N, 128, 1);
        k_gemm<<<CDIV(N, 32), 256>>>(p_t1, 128, gin_w2 + l * H * H, 128, gin_b2 + l * H, p_m,  128, N, 128, 0);
        // GRU gates (3 column chunks of 128 each)
        for (int c = 0; c < 3; c++) {
            k_gemm<<<CDIV(N, 32), 256>>>(p_m,    128, p_twih + c * 128, 384, gru_bih + c * 128,
                                         p_gi + c * 128, 384, N, 128, 0);
            k_gemm<<<CDIV(N, 32), 256>>>(p_node, 128, p_twhh + c * 128, 384, gru_bhh + c * 128,
                                         p_gh + c * 128, 384, N, 128, 0);
        }
        k_gru<<<CDIV(N * H, TB), TB>>>(p_gi, p_gh, p_node, N * H);
        // edge MLP
        k_gemm<<<CDIV(E, 32), 256>>>(p_edge, 128, em_w1 + l * H * H, 128, em_b1 + l * H, p_et,   128, E, 128, 1);
        k_gemm<<<CDIV(E, 32), 256>>>(p_et,   128, em_w2 + l * H * H, 128, em_b2 + l * H, p_edge, 128, E, 128, 0);
    }

    // Set2Set init
    k_zero<<<CDIV(G * 2 * H, TB), TB>>>(p_qs, G * 2 * H);
    k_zero<<<CDIV(G * H, TB), TB>>>(p_hl, G * H);
    k_zero<<<CDIV(G * H, TB), TB>>>(p_cl, G * H);

    for (int step = 0; step < 3; step++) {
        // LSTM gates: gl = qs @ Wih^T + bih + hl @ Whh^T + bhh   (4 chunks of 128)
        for (int c = 0; c < 4; c++)
            k_gemm<<<CDIV(G, 32), 256>>>(p_qs, 256, p_tlwih + c * 128, 512, lstm_bih + c * 128,
                                         p_gl + c * 128, 512, G, 256, 0);
        for (int c = 0; c < 4; c++)
            k_gemm<<<CDIV(G, 32), 256>>>(p_hl, 128, p_tlwhh + c * 128, 512, lstm_bhh + c * 128,
                                         p_gl + c * 128, 512, G, 128, 2 /*accum*/);
        k_lstm<<<CDIV(G * H, TB), TB>>>(p_gl, p_hl, p_cl, G * H);

        // attention pooling
        k_zero<<<CDIV(G * H, TB), TB>>>(p_r, G * H);
        k_zero<<<CDIV(G, TB), TB>>>(p_den, G);
        k_zero<<<CDIV(G, TB), TB>>>((float*)p_emaxk, G);   // key 0 == -inf identity
        k_edot<<<CDIV(N * 32, TB), TB>>>(batch, p_node, p_hl, p_e, p_emaxk, N);
        k_expsum<<<CDIV(N, TB), TB>>>(batch, p_e, p_ex, p_emaxk, p_den, N);
        k_rscatter<<<CDIV(N * 32, TB), TB>>>(batch, p_node, p_ex, p_den, p_r, N);
        k_qsbuild<<<CDIV(G * 2 * H, TB), TB>>>(p_hl, p_r, p_qs, G * 2 * H);
    }

    // final MLP
    k_gemm<<<CDIV(G, 32), 256>>>(p_qs, 256, fc_w1, 128, fc_b1, p_fc, 128, G, 256, 1);
    k_fc2<<<CDIV(G * 32, TB), TB>>>(p_fc, fc_w2, fc_b2, (float*)d_out, G);
}

// round 2
// speedup vs baseline: 1.2404x; 1.2404x over previous
#include <cuda_runtime.h>
#include <math.h>

#define H 128
#define NMAX 100000
#define EMAX 200000
#define GMAX 4096

#define CDIV(a,b) (((a)+(b)-1)/(b))

// ---------------- scratch (device globals; no allocation) ----------------
__device__ float g_node[(size_t)NMAX*H];
__device__ float g_edge[(size_t)EMAX*H];
__device__ float g_agg [(size_t)NMAX*H];
__device__ float g_t1  [(size_t)NMAX*H];
__device__ float g_m   [(size_t)NMAX*H];
__device__ float g_gi  [(size_t)NMAX*3*H];
__device__ float g_gh  [(size_t)NMAX*3*H];
__device__ float g_et  [(size_t)EMAX*H];
__device__ float g_qs  [(size_t)GMAX*2*H];
__device__ float g_hl  [(size_t)GMAX*H];
__device__ float g_cl  [(size_t)GMAX*H];
__device__ float g_r   [(size_t)GMAX*H];
__device__ float g_gl  [(size_t)GMAX*4*H];
__device__ float g_fc  [(size_t)GMAX*H];
__device__ float g_e   [NMAX];
__device__ float g_ex  [NMAX];
__device__ unsigned g_emaxk[GMAX];
__device__ float g_denom[GMAX];
// transposed weights (so every GEMM is A[M,K] @ W[K,cols])
__device__ float t_gwih[H*3*H];    // [128][384]
__device__ float t_gwhh[H*3*H];    // [128][384]
__device__ float t_lwih[2*H*4*H];  // [256][512]
__device__ float t_lwhh[H*4*H];    // [128][512]

// ---------------- helpers ----------------
__device__ __forceinline__ float sigf(float x) { return 1.f / (1.f + expf(-x)); }

__device__ __forceinline__ unsigned fkey(float f) {
    unsigned u = __float_as_uint(f);
    return (u & 0x80000000u) ? ~u : (u | 0x80000000u);
}
__device__ __forceinline__ float fdec(unsigned k) {
    unsigned u = (k & 0x80000000u) ? (k ^ 0x80000000u) : ~k;
    return __uint_as_float(u);
}

// packed dual FMA: (d.lo,d.hi) = (a.lo*b.lo+c.lo, a.hi*b.hi+c.hi)
__device__ __forceinline__ unsigned long long fma2(unsigned long long a,
                                                   unsigned long long b,
                                                   unsigned long long c) {
    unsigned long long d;
    asm("fma.rn.f32x2 %0, %1, %2, %3;" : "=l"(d) : "l"(a), "l"(b), "l"(c));
    return d;
}

union U64F2 { unsigned long long u; float2 f; };
union U128 { float4 v; unsigned long long u[2]; };

// ---------------- GEMM: O[M, col0:col0+128] = act(A[M,K] @ W[K, ldw] + bias) ----------------
// blockIdx.y selects a 128-col chunk. flags: bit0 = ReLU, bit1 = accumulate into O.
// Tile: 64 rows x 128 cols, 256 threads, each thread 8 rows x 4 cols (as 8x2 f32x2).
__global__ void __launch_bounds__(256) k_gemm(
    const float* __restrict__ A, int lda,
    const float* __restrict__ W, int ldw,
    const float* __restrict__ bias,
    float* __restrict__ O, int ldo,
    int M, int K, int flags)
{
    __shared__ __align__(16) unsigned long long Asd[16][65]; // duplicated (a,a) pairs, padded
    __shared__ __align__(16) float Ws[16][128];
    const int tid = threadIdx.x;
    const int tx = tid & 31, ty = tid >> 5;
    const int row0 = blockIdx.x * 64;
    const int col0 = blockIdx.y * 128;

    unsigned long long acc[8][2];
#pragma unroll
    for (int r = 0; r < 8; r++) { acc[r][0] = 0ULL; acc[r][1] = 0ULL; }

    for (int k0 = 0; k0 < K; k0 += 16) {
        // load A tile (64 rows x 16 k), duplicated into pairs
#pragma unroll
        for (int i = tid; i < 1024; i += 256) {
            int r = i >> 4, k = i & 15;
            int row = row0 + r, kk = k0 + k;
            float v = (row < M && kk < K) ? A[(size_t)row * lda + kk] : 0.f;
            U64F2 p; p.f.x = v; p.f.y = v;
            Asd[k][r] = p.u;
        }
        // load W tile (16 k x 128 cols)
#pragma unroll
        for (int i = tid; i < 2048; i += 256) {
            int k = i >> 7, j = i & 127;
            int kk = k0 + k;
            Ws[k][j] = (kk < K) ? W[(size_t)kk * ldw + col0 + j] : 0.f;
        }
        __syncthreads();
#pragma unroll
        for (int k = 0; k < 16; k++) {
            U128 w; w.v = *(const float4*)&Ws[k][tx << 2];
#pragma unroll
            for (int r = 0; r < 8; r++) {
                unsigned long long a = Asd[k][(ty << 3) + r];   // broadcast LDS.64
                acc[r][0] = fma2(a, w.u[0], acc[r][0]);
                acc[r][1] = fma2(a, w.u[1], acc[r][1]);
            }
        }
        __syncthreads();
    }

    const int col = tx << 2;
    float4 b4 = *(const float4*)&bias[col0 + col];
#pragma unroll
    for (int r = 0; r < 8; r++) {
        int row = row0 + (ty << 3) + r;
        if (row < M) {
            U64F2 p0, p1; p0.u = acc[r][0]; p1.u = acc[r][1];
            float v[4] = {p0.f.x + b4.x, p0.f.y + b4.y, p1.f.x + b4.z, p1.f.y + b4.w};
            float* op = &O[(size_t)row * ldo + col0 + col];
            if (flags & 2) {
                float4 o = *(const float4*)op;
                v[0] += o.x; v[1] += o.y; v[2] += o.z; v[3] += o.w;
            }
            if (flags & 1) {
#pragma unroll
                for (int c = 0; c < 4; c++) v[c] = fmaxf(v[c], 0.f);
            }
            float4 ov = {v[0], v[1], v[2], v[3]};
            *(float4*)op = ov;
        }
    }
}

// ---------------- small kernels ----------------
__global__ void k_zero(float* __restrict__ p, int n) {
    int i = blockIdx.x * blockDim.x + threadIdx.x;
    if (i < n) p[i] = 0.f;
}

__global__ void k_transpose(const float* __restrict__ in, float* __restrict__ out,
                            int rows, int cols) {
    int idx = blockIdx.x * blockDim.x + threadIdx.x;
    if (idx < rows * cols) {
        int r = idx / cols, c = idx % cols;
        out[(size_t)c * rows + r] = in[idx];
    }
}

// agg = (1+eps[l]) * node   (scatter then adds messages; agg IS z afterwards)
__global__ void k_initagg(const float* __restrict__ eps, int l,
                          const float* __restrict__ node, float* __restrict__ agg, int n)
{
    int i = blockIdx.x * blockDim.x + threadIdx.x;
    if (i < n) agg[i] = (1.f + eps[l]) * node[i];
}

// msg = relu(node[src] + edge); atomic scatter-add into agg[dst]
__global__ void k_scatter(const int* __restrict__ src, const int* __restrict__ dst,
                          const float* __restrict__ node, const float* __restrict__ edge,
                          float* __restrict__ agg, int E)
{
    int tid = blockIdx.x * blockDim.x + threadIdx.x;
    int e = tid >> 5;
    if (e >= E) return;
    int lane = tid & 31;
    int s = src[e], d = dst[e];
    float4 nv = *(const float4*)&node[(size_t)s * H + lane * 4];
    float4 ev = *(const float4*)&edge[(size_t)e * H + lane * 4];
    float m0 = fmaxf(nv.x + ev.x, 0.f);
    float m1 = fmaxf(nv.y + ev.y, 0.f);
    float m2 = fmaxf(nv.z + ev.z, 0.f);
    float m3 = fmaxf(nv.w + ev.w, 0.f);
    float* ap = &agg[(size_t)d * H + lane * 4];
    atomicAdd(ap + 0, m0);
    atomicAdd(ap + 1, m1);
    atomicAdd(ap + 2, m2);
    atomicAdd(ap + 3, m3);
}

// GRU elementwise: h = (1-z)*n + z*h   (gi/gh are [N,384] packed r|z|n)
__global__ void k_gru(const float* __restrict__ gi, const float* __restrict__ gh,
                      float* __restrict__ h, int n)
{
    int idx = blockIdx.x * blockDim.x + threadIdx.x;
    if (idx >= n) return;
    int row = idx >> 7, j = idx & 127;
    const float* gir = &gi[(size_t)row * 384];
    const float* ghr = &gh[(size_t)row * 384];
    float r  = sigf(gir[j]       + ghr[j]);
    float zt = sigf(gir[j + 128] + ghr[j + 128]);
    float nn = tanhf(gir[j + 256] + r * ghr[j + 256]);
    float hv = h[idx];
    h[idx] = (1.f - zt) * nn + zt * hv;
}

// LSTM elementwise (gl is [G,512] packed i|f|g|o)
__global__ void k_lstm(const float* __restrict__ gl, float* __restrict__ hl,
                       float* __restrict__ cl, int n)
{
    int idx = blockIdx.x * blockDim.x + threadIdx.x;
    if (idx >= n) return;
    int g = idx >> 7, j = idx & 127;
    const float* gr = &gl[(size_t)g * 512];
    float i_ = gr[j], f_ = gr[j + 128], gg = gr[j + 256], o_ = gr[j + 384];
    float c = sigf(f_) * cl[idx] + sigf(i_) * tanhf(gg);
    cl[idx] = c;
    hl[idx] = sigf(o_) * tanhf(c);
}

// e[n] = dot(node[n], q[batch[n]]); atomicMax per-graph (key-encoded)
__global__ void k_edot(const int* __restrict__ batch, const float* __restrict__ node,
                       const float* __restrict__ q, float* __restrict__ e,
                       unsigned* __restrict__ emaxk, int N)
{
    int tid = blockIdx.x * blockDim.x + threadIdx.x;
    int n = tid >> 5;
    if (n >= N) return;
    int lane = tid & 31;
    int b = batch[n];
    float s = 0.f;
#pragma unroll
    for (int t = 0; t < 4; t++) {
        int j = lane + t * 32;
        s += node[(size_t)n * H + j] * q[(size_t)b * H + j];
    }
#pragma unroll
    for (int off = 16; off; off >>= 1) s += __shfl_xor_sync(0xffffffffu, s, off);
    if (lane == 0) {
        e[n] = s;
        atomicMax(&emaxk[b], fkey(s));
    }
}

__global__ void k_expsum(const int* __restrict__ batch, const float* __restrict__ e,
                         float* __restrict__ ex, const unsigned* __restrict__ emaxk,
                         float* __restrict__ denom, int N)
{
    int n = blockIdx.x * blockDim.x + threadIdx.x;
    if (n >= N) return;
    int b = batch[n];
    float v = expf(e[n] - fdec(emaxk[b]));
    ex[n] = v;
    atomicAdd(&denom[b], v);
}

__global__ void k_rscatter(const int* __restrict__ batch, const float* __restrict__ node,
                           const float* __restrict__ ex, const float* __restrict__ denom,
                           float* __restrict__ r, int N)
{
    int tid = blockIdx.x * blockDim.x + threadIdx.x;
    int n = tid >> 5;
    if (n >= N) return;
    int lane = tid & 31;
    int b = batch[n];
    float coef = ex[n] / fmaxf(denom[b], 1e-9f);
    float4 nv = *(const float4*)&node[(size_t)n * H + lane * 4];
    float* rp = &r[(size_t)b * H + lane * 4];
    atomicAdd(rp + 0, coef * nv.x);
    atomicAdd(rp + 1, coef * nv.y);
    atomicAdd(rp + 2, coef * nv.z);
    atomicAdd(rp + 3, coef * nv.w);
}

__global__ void k_qsbuild(const float* __restrict__ hl, const float* __restrict__ r,
                          float* __restrict__ qs, int n)
{
    int idx = blockIdx.x * blockDim.x + threadIdx.x;
    if (idx >= n) return;
    int g = idx >> 8, j = idx & 255;
    qs[idx] = (j < 128) ? hl[(size_t)g * 128 + j] : r[(size_t)g * 128 + (j - 128)];
}

__global__ void k_fc2(const float* __restrict__ fcin, const float* __restrict__ w2,
                      const float* __restrict__ b2, float* __restrict__ out, int G)
{
    int tid = blockIdx.x * blockDim.x + threadIdx.x;
    int g = tid >> 5;
    if (g >= G) return;
    int lane = tid & 31;
    float s = 0.f;
#pragma unroll
    for (int t = 0; t < 4; t++) {
        int j = lane + t * 32;
        s += fcin[(size_t)g * H + j] * w2[j];
    }
#pragma unroll
    for (int off = 16; off; off >>= 1) s += __shfl_xor_sync(0xffffffffu, s, off);
    if (lane == 0) out[g] = s + b2[0];
}

// ---------------- host launcher ----------------
extern "C" void kernel_launch(void* const* d_in, const int* in_sizes, int n_in,
                              void* d_out, int out_size)
{
    const float* x       = (const float*)d_in[0];
    const float* eattr   = (const float*)d_in[1];
    const int*   eindex  = (const int*)d_in[2];
    const int*   batch   = (const int*)d_in[3];
    const float* node_w  = (const float*)d_in[4];
    const float* node_b  = (const float*)d_in[5];
    const float* edge_w  = (const float*)d_in[6];
    const float* edge_b  = (const float*)d_in[7];
    const float* eps     = (const float*)d_in[8];
    const float* gin_w1  = (const float*)d_in[9];
    const float* gin_b1  = (const float*)d_in[10];
    const float* gin_w2  = (const float*)d_in[11];
    const float* gin_b2  = (const float*)d_in[12];
    const float* em_w1   = (const float*)d_in[13];
    const float* em_b1   = (const float*)d_in[14];
    const float* em_w2   = (const float*)d_in[15];
    const float* em_b2   = (const float*)d_in[16];
    const float* gru_wih = (const float*)d_in[17];
    const float* gru_whh = (const float*)d_in[18];
    const float* gru_bih = (const float*)d_in[19];
    const float* gru_bhh = (const float*)d_in[20];
    const float* lstm_wih= (const float*)d_in[21];
    const float* lstm_whh= (const float*)d_in[22];
    const float* lstm_bih= (const float*)d_in[23];
    const float* lstm_bhh= (const float*)d_in[24];
    const float* fc_w1   = (const float*)d_in[25];
    const float* fc_b1   = (const float*)d_in[26];
    const float* fc_w2   = (const float*)d_in[27];
    const float* fc_b2   = (const float*)d_in[28];

    const int N = in_sizes[0] / 14;
    const int E = in_sizes[1] / 4;
    const int G = out_size;

    float *p_node, *p_edge, *p_agg, *p_t1, *p_m, *p_gi, *p_gh, *p_et;
    float *p_qs, *p_hl, *p_cl, *p_r, *p_gl, *p_fc, *p_e, *p_ex, *p_den;
    unsigned *p_emaxk;
    float *p_twih, *p_twhh, *p_tlwih, *p_tlwhh;
    cudaGetSymbolAddress((void**)&p_node, g_node);
    cudaGetSymbolAddress((void**)&p_edge, g_edge);
    cudaGetSymbolAddress((void**)&p_agg,  g_agg);
    cudaGetSymbolAddress((void**)&p_t1,   g_t1);
    cudaGetSymbolAddress((void**)&p_m,    g_m);
    cudaGetSymbolAddress((void**)&p_gi,   g_gi);
    cudaGetSymbolAddress((void**)&p_gh,   g_gh);
    cudaGetSymbolAddress((void**)&p_et,   g_et);
    cudaGetSymbolAddress((void**)&p_qs,   g_qs);
    cudaGetSymbolAddress((void**)&p_hl,   g_hl);
    cudaGetSymbolAddress((void**)&p_cl,   g_cl);
    cudaGetSymbolAddress((void**)&p_r,    g_r);
    cudaGetSymbolAddress((void**)&p_gl,   g_gl);
    cudaGetSymbolAddress((void**)&p_fc,   g_fc);
    cudaGetSymbolAddress((void**)&p_e,    g_e);
    cudaGetSymbolAddress((void**)&p_ex,   g_ex);
    cudaGetSymbolAddress((void**)&p_den,  g_denom);
    cudaGetSymbolAddress((void**)&p_emaxk, g_emaxk);
    cudaGetSymbolAddress((void**)&p_twih, t_gwih);
    cudaGetSymbolAddress((void**)&p_twhh, t_gwhh);
    cudaGetSymbolAddress((void**)&p_tlwih, t_lwih);
    cudaGetSymbolAddress((void**)&p_tlwhh, t_lwhh);

    const int TB = 256;
    const int BM = 64;

    // weight transposes (W.T copies so every GEMM is A @ W[K,cols])
    k_transpose<<<CDIV(384 * 128, TB), TB>>>(gru_wih,  p_twih,  384, 128);
    k_transpose<<<CDIV(384 * 128, TB), TB>>>(gru_whh,  p_twhh,  384, 128);
    k_transpose<<<CDIV(512 * 256, TB), TB>>>(lstm_wih, p_tlwih, 512, 256);
    k_transpose<<<CDIV(512 * 128, TB), TB>>>(lstm_whh, p_tlwhh, 512, 128);

    // input embeddings
    k_gemm<<<dim3(CDIV(N, BM), 1), 256>>>(x, 14, node_w, 128, node_b, p_node, 128, N, 14, 0);
    k_gemm<<<dim3(CDIV(E, BM), 1), 256>>>(eattr, 4, edge_w, 128, edge_b, p_edge, 128, E, 4, 0);

    const int* src = eindex;
    const int* dst = eindex + E;

    for (int l = 0; l < 2; l++) {
        // GINEConv aggregation: agg = (1+eps)*node, then += scattered messages
        k_initagg<<<CDIV(N * H, TB), TB>>>(eps, l, p_node, p_agg, N * H);
        k_scatter<<<CDIV(E * 32, TB), TB>>>(src, dst, p_node, p_edge, p_agg, E);
        // GIN MLP (reads agg == z)
        k_gemm<<<dim3(CDIV(N, BM), 1), 256>>>(p_agg, 128, gin_w1 + l * H * H, 128, gin_b1 + l * H, p_t1, 128, N, 128, 1);
        k_gemm<<<dim3(CDIV(N, BM), 1), 256>>>(p_t1,  128, gin_w2 + l * H * H, 128, gin_b2 + l * H, p_m,  128, N, 128, 0);
        // GRU gates: gi = m @ Wih^T + bih (384 cols via blockIdx.y), gh = h @ Whh^T + bhh
        k_gemm<<<dim3(CDIV(N, BM), 3), 256>>>(p_m,    128, p_twih, 384, gru_bih, p_gi, 384, N, 128, 0);
        k_gemm<<<dim3(CDIV(N, BM), 3), 256>>>(p_node, 128, p_twhh, 384, gru_bhh, p_gh, 384, N, 128, 0);
        k_gru<<<CDIV(N * H, TB), TB>>>(p_gi, p_gh, p_node, N * H);
        // edge MLP
        k_gemm<<<dim3(CDIV(E, BM), 1), 256>>>(p_edge, 128, em_w1 + l * H * H, 128, em_b1 + l * H, p_et,   128, E, 128, 1);
        k_gemm<<<dim3(CDIV(E, BM), 1), 256>>>(p_et,   128, em_w2 + l * H * H, 128, em_b2 + l * H, p_edge, 128, E, 128, 0);
    }

    // Set2Set init
    k_zero<<<CDIV(G * 2 * H, TB), TB>>>(p_qs, G * 2 * H);
    k_zero<<<CDIV(G * H, TB), TB>>>(p_hl, G * H);
    k_zero<<<CDIV(G * H, TB), TB>>>(p_cl, G * H);

    for (int step = 0; step < 3; step++) {
        // LSTM gates: gl = qs @ Wih^T + bih + hl @ Whh^T + bhh (4 chunks via blockIdx.y)
        k_gemm<<<dim3(CDIV(G, BM), 4), 256>>>(p_qs, 256, p_tlwih, 512, lstm_bih, p_gl, 512, G, 256, 0);
        k_gemm<<<dim3(CDIV(G, BM), 4), 256>>>(p_hl, 128, p_tlwhh, 512, lstm_bhh, p_gl, 512, G, 128, 2);
        k_lstm<<<CDIV(G * H, TB), TB>>>(p_gl, p_hl, p_cl, G * H);

        // attention pooling
        k_zero<<<CDIV(G * H, TB), TB>>>(p_r, G * H);
        k_zero<<<CDIV(G, TB), TB>>>(p_den, G);
        k_zero<<<CDIV(G, TB), TB>>>((float*)p_emaxk, G);   // key 0 == -inf identity
        k_edot<<<CDIV(N * 32, TB), TB>>>(batch, p_node, p_hl, p_e, p_emaxk, N);
        k_expsum<<<CDIV(N, TB), TB>>>(batch, p_e, p_ex, p_emaxk, p_den, N);
        k_rscatter<<<CDIV(N * 32, TB), TB>>>(batch, p_node, p_ex, p_den, p_r, N);
        k_qsbuild<<<CDIV(G * 2 * H, TB), TB>>>(p_hl, p_r, p_qs, G * 2 * H);
    }

    // final MLP
    k_gemm<<<dim3(CDIV(G, BM), 1), 256>>>(p_qs, 256, fc_w1, 128, fc_b1, p_fc, 128, G, 256, 1);
    k_fc2<<<CDIV(G * 32, TB), TB>>>(p_fc, fc_w2, fc_b2, (float*)d_out, G);
}

// round 3
// speedup vs baseline: 1.3097x; 1.0559x over previous
#include <cuda_runtime.h>
#include <math.h>

#define H 128
#define NMAX 100000
#define EMAX 200000
#define GMAX 4096

#define CDIV(a,b) (((a)+(b)-1)/(b))

// ---------------- scratch (device globals; no allocation) ----------------
__device__ float g_node[(size_t)NMAX*H];
__device__ float g_edge[(size_t)EMAX*H];
__device__ float g_agg [(size_t)NMAX*H];
__device__ float g_t1  [(size_t)NMAX*H];
__device__ float g_m   [(size_t)NMAX*H];
__device__ float g_gi  [(size_t)NMAX*3*H];
__device__ float g_gh  [(size_t)NMAX*3*H];
__device__ float g_et  [(size_t)EMAX*H];
__device__ float g_qs  [(size_t)GMAX*2*H];
__device__ float g_hl  [(size_t)GMAX*H];
__device__ float g_cl  [(size_t)GMAX*H];
__device__ float g_gl  [(size_t)GMAX*4*H];
__device__ float g_fc  [(size_t)GMAX*H];
// transposed weights (so every GEMM is A[M,K] @ W[K,cols])
__device__ float t_gwih[H*3*H];    // [128][384]
__device__ float t_gwhh[H*3*H];    // [128][384]
__device__ float t_lwih[2*H*4*H];  // [256][512]
__device__ float t_lwhh[H*4*H];    // [128][512]

// ---------------- helpers ----------------
__device__ __forceinline__ float sigf(float x) { return 1.f / (1.f + expf(-x)); }

// packed dual FMA: (d.lo,d.hi) = (a.lo*b.lo+c.lo, a.hi*b.hi+c.hi)
__device__ __forceinline__ unsigned long long fma2(unsigned long long a,
                                                   unsigned long long b,
                                                   unsigned long long c) {
    unsigned long long d;
    asm("fma.rn.f32x2 %0, %1, %2, %3;" : "=l"(d) : "l"(a), "l"(b), "l"(c));
    return d;
}

union U64F2 { unsigned long long u; float2 f; };
union U128 { float4 v; unsigned long long u[2]; };

// ---------------- GEMM: O[M, col0:col0+128] = act(A[M,K] @ W[K, ldw] + bias) ----------------
// blockIdx.y selects a 128-col chunk. flags: bit0 = ReLU, bit1 = accumulate into O.
// Tile: 64 rows x 128 cols, 256 threads, each thread 8 rows x 4 cols (as 8x2 f32x2).
__global__ void __launch_bounds__(256) k_gemm(
    const float* __restrict__ A, int lda,
    const float* __restrict__ W, int ldw,
    const float* __restrict__ bias,
    float* __restrict__ O, int ldo,
    int M, int K, int flags)
{
    __shared__ __align__(16) unsigned long long Asd[16][65]; // duplicated (a,a) pairs, padded
    __shared__ __align__(16) float Ws[16][128];
    const int tid = threadIdx.x;
    const int tx = tid & 31, ty = tid >> 5;
    const int row0 = blockIdx.x * 64;
    const int col0 = blockIdx.y * 128;

    unsigned long long acc[8][2];
#pragma unroll
    for (int r = 0; r < 8; r++) { acc[r][0] = 0ULL; acc[r][1] = 0ULL; }

    for (int k0 = 0; k0 < K; k0 += 16) {
        // load A tile (64 rows x 16 k), duplicated into pairs
#pragma unroll
        for (int i = tid; i < 1024; i += 256) {
            int r = i >> 4, k = i & 15;
            int row = row0 + r, kk = k0 + k;
            float v = (row < M && kk < K) ? A[(size_t)row * lda + kk] : 0.f;
            U64F2 p; p.f.x = v; p.f.y = v;
            Asd[k][r] = p.u;
        }
        // load W tile (16 k x 128 cols)
#pragma unroll
        for (int i = tid; i < 2048; i += 256) {
            int k = i >> 7, j = i & 127;
            int kk = k0 + k;
            Ws[k][j] = (kk < K) ? W[(size_t)kk * ldw + col0 + j] : 0.f;
        }
        __syncthreads();
#pragma unroll
        for (int k = 0; k < 16; k++) {
            U128 w; w.v = *(const float4*)&Ws[k][tx << 2];
#pragma unroll
            for (int r = 0; r < 8; r++) {
                unsigned long long a = Asd[k][(ty << 3) + r];   // broadcast LDS.64
                acc[r][0] = fma2(a, w.u[0], acc[r][0]);
                acc[r][1] = fma2(a, w.u[1], acc[r][1]);
            }
        }
        __syncthreads();
    }

    const int col = tx << 2;
    float4 b4 = *(const float4*)&bias[col0 + col];
#pragma unroll
    for (int r = 0; r < 8; r++) {
        int row = row0 + (ty << 3) + r;
        if (row < M) {
            U64F2 p0, p1; p0.u = acc[r][0]; p1.u = acc[r][1];
            float v[4] = {p0.f.x + b4.x, p0.f.y + b4.y, p1.f.x + b4.z, p1.f.y + b4.w};
            float* op = &O[(size_t)row * ldo + col0 + col];
            if (flags & 2) {
                float4 o = *(const float4*)op;
                v[0] += o.x; v[1] += o.y; v[2] += o.z; v[3] += o.w;
            }
            if (flags & 1) {
#pragma unroll
                for (int c = 0; c < 4; c++) v[c] = fmaxf(v[c], 0.f);
            }
            float4 ov = {v[0], v[1], v[2], v[3]};
            *(float4*)op = ov;
        }
    }
}

// ---------------- small kernels ----------------
// fused weight transposes: gru_wih(384x128), gru_whh(384x128), lstm_wih(512x256), lstm_whh(512x128)
__global__ void k_prep(const float* __restrict__ gwih, const float* __restrict__ gwhh,
                       const float* __restrict__ lwih, const float* __restrict__ lwhh,
                       float* __restrict__ tgi, float* __restrict__ tgh,
                       float* __restrict__ tli, float* __restrict__ tlh)
{
    int i = blockIdx.x * blockDim.x + threadIdx.x;
    if (i < 49152) {                       // gru_wih: [384,128] -> [128,384]
        int r = i / 128, c = i % 128;
        tgi[(size_t)c * 384 + r] = gwih[i];
    } else if (i < 98304) {                // gru_whh
        int j = i - 49152;
        int r = j / 128, c = j % 128;
        tgh[(size_t)c * 384 + r] = gwhh[j];
    } else if (i < 229376) {               // lstm_wih: [512,256] -> [256,512]
        int j = i - 98304;
        int r = j / 256, c = j % 256;
        tli[(size_t)c * 512 + r] = lwih[j];
    } else if (i < 294912) {               // lstm_whh: [512,128] -> [128,512]
        int j = i - 229376;
        int r = j / 128, c = j % 128;
        tlh[(size_t)c * 512 + r] = lwhh[j];
    }
}

__global__ void k_zero3(float* __restrict__ a, int na, float* __restrict__ b, int nb,
                        float* __restrict__ c, int nc)
{
    int i = blockIdx.x * blockDim.x + threadIdx.x;
    if (i < na) a[i] = 0.f;
    if (i < nb) b[i] = 0.f;
    if (i < nc) c[i] = 0.f;
}

// agg = (1+eps[l]) * node   (scatter then adds messages; agg IS z afterwards)
__global__ void k_initagg(const float* __restrict__ eps, int l,
                          const float* __restrict__ node, float* __restrict__ agg, int n)
{
    int i = blockIdx.x * blockDim.x + threadIdx.x;
    if (i < n) agg[i] = (1.f + eps[l]) * node[i];
}

// msg = relu(node[src] + edge); vector-atomic scatter-add into agg[dst]
__global__ void k_scatter(const int* __restrict__ src, const int* __restrict__ dst,
                          const float* __restrict__ node, const float* __restrict__ edge,
                          float* __restrict__ agg, int E)
{
    int tid = blockIdx.x * blockDim.x + threadIdx.x;
    int e = tid >> 5;
    if (e >= E) return;
    int lane = tid & 31;
    int s = src[e], d = dst[e];
    float4 nv = *(const float4*)&node[(size_t)s * H + lane * 4];
    float4 ev = *(const float4*)&edge[(size_t)e * H + lane * 4];
    float m0 = fmaxf(nv.x + ev.x, 0.f);
    float m1 = fmaxf(nv.y + ev.y, 0.f);
    float m2 = fmaxf(nv.z + ev.z, 0.f);
    float m3 = fmaxf(nv.w + ev.w, 0.f);
    float* ap = &agg[(size_t)d * H + lane * 4];
    asm volatile("red.global.add.v4.f32 [%0], {%1, %2, %3, %4};"
                 :: "l"(ap), "f"(m0), "f"(m1), "f"(m2), "f"(m3) : "memory");
}

// GRU elementwise: h = (1-z)*n + z*h   (gi/gh are [N,384] packed r|z|n)
__global__ void k_gru(const float* __restrict__ gi, const float* __restrict__ gh,
                      float* __restrict__ h, int n)
{
    int idx = blockIdx.x * blockDim.x + threadIdx.x;
    if (idx >= n) return;
    int row = idx >> 7, j = idx & 127;
    const float* gir = &gi[(size_t)row * 384];
    const float* ghr = &gh[(size_t)row * 384];
    float r  = sigf(gir[j]       + ghr[j]);
    float zt = sigf(gir[j + 128] + ghr[j + 128]);
    float nn = tanhf(gir[j + 256] + r * ghr[j + 256]);
    float hv = h[idx];
    h[idx] = (1.f - zt) * nn + zt * hv;
}

// LSTM elementwise (gl is [G,512] packed i|f|g|o)
__global__ void k_lstm(const float* __restrict__ gl, float* __restrict__ hl,
                       float* __restrict__ cl, int n)
{
    int idx = blockIdx.x * blockDim.x + threadIdx.x;
    if (idx >= n) return;
    int g = idx >> 7, j = idx & 127;
    const float* gr = &gl[(size_t)g * 512];
    float i_ = gr[j], f_ = gr[j + 128], gg = gr[j + 256], o_ = gr[j + 384];
    float c = sigf(f_) * cl[idx] + sigf(i_) * tanhf(gg);
    cl[idx] = c;
    hl[idx] = sigf(o_) * tanhf(c);
}

// fused Set2Set attention pooling: one warp per graph (batch is sorted).
// Computes e=dot(node,q), per-graph softmax, r = sum(a*node), writes qs=[q | r].
__global__ void k_set2set(const int* __restrict__ batch, const float* __restrict__ node,
                          const float* __restrict__ hl, float* __restrict__ qs,
                          int N, int G)
{
    int warp = (blockIdx.x * blockDim.x + threadIdx.x) >> 5;
    if (warp >= G) return;
    const int lane = threadIdx.x & 31;
    const int g = warp;

    // segment bounds via binary search (batch sorted ascending)
    int lo = 0, hi = N;
    while (lo < hi) { int mid = (lo + hi) >> 1; if (batch[mid] < g) lo = mid + 1; else hi = mid; }
    const int s0 = lo;
    hi = N;
    while (lo < hi) { int mid = (lo + hi) >> 1; if (batch[mid] < g + 1) lo = mid + 1; else hi = mid; }
    const int s1 = lo;

    float4 qv = *(const float4*)&hl[(size_t)g * H + lane * 4];

    // pass 1: max of dots
    float mx = -INFINITY;
    for (int i = s0; i < s1; i++) {
        float4 nv = *(const float4*)&node[(size_t)i * H + lane * 4];
        float d = nv.x * qv.x + nv.y * qv.y + nv.z * qv.z + nv.w * qv.w;
#pragma unroll
        for (int o = 16; o; o >>= 1) d += __shfl_xor_sync(0xffffffffu, d, o);
        mx = fmaxf(mx, d);
    }
    // pass 2: exp-sum and weighted node sum
    float den = 0.f;
    float4 racc = make_float4(0.f, 0.f, 0.f, 0.f);
    for (int i = s0; i < s1; i++) {
        float4 nv = *(const float4*)&node[(size_t)i * H + lane * 4];
        float d = nv.x * qv.x + nv.y * qv.y + nv.z * qv.z + nv.w * qv.w;
#pragma unroll
        for (int o = 16; o; o >>= 1) d += __shfl_xor_sync(0xffffffffu, d, o);
        float ex = expf(d - mx);
        den += ex;
        racc.x += ex * nv.x; racc.y += ex * nv.y;
        racc.z += ex * nv.z; racc.w += ex * nv.w;
    }
    float inv = 1.f / fmaxf(den, 1e-9f);
    float* qrow = &qs[(size_t)g * 2 * H];
    *(float4*)&qrow[lane * 4] = qv;
    float4 rv = {racc.x * inv, racc.y * inv, racc.z * inv, racc.w * inv};
    *(float4*)&qrow[H + lane * 4] = rv;
}

__global__ void k_fc2(const float* __restrict__ fcin, const float* __restrict__ w2,
                      const float* __restrict__ b2, float* __restrict__ out, int G)
{
    int tid = blockIdx.x * blockDim.x + threadIdx.x;
    int g = tid >> 5;
    if (g >= G) return;
    int lane = tid & 31;
    float s = 0.f;
#pragma unroll
    for (int t = 0; t < 4; t++) {
        int j = lane + t * 32;
        s += fcin[(size_t)g * H + j] * w2[j];
    }
#pragma unroll
    for (int off = 16; off; off >>= 1) s += __shfl_xor_sync(0xffffffffu, s, off);
    if (lane == 0) out[g] = s + b2[0];
}

// ---------------- host launcher ----------------
extern "C" void kernel_launch(void* const* d_in, const int* in_sizes, int n_in,
                              void* d_out, int out_size)
{
    const float* x       = (const float*)d_in[0];
    const float* eattr   = (const float*)d_in[1];
    const int*   eindex  = (const int*)d_in[2];
    const int*   batch   = (const int*)d_in[3];
    const float* node_w  = (const float*)d_in[4];
    const float* node_b  = (const float*)d_in[5];
    const float* edge_w  = (const float*)d_in[6];
    const float* edge_b  = (const float*)d_in[7];
    const float* eps     = (const float*)d_in[8];
    const float* gin_w1  = (const float*)d_in[9];
    const float* gin_b1  = (const float*)d_in[10];
    const float* gin_w2  = (const float*)d_in[11];
    const float* gin_b2  = (const float*)d_in[12];
    const float* em_w1   = (const float*)d_in[13];
    const float* em_b1   = (const float*)d_in[14];
    const float* em_w2   = (const float*)d_in[15];
    const float* em_b2   = (const float*)d_in[16];
    const float* gru_wih = (const float*)d_in[17];
    const float* gru_whh = (const float*)d_in[18];
    const float* gru_bih = (const float*)d_in[19];
    const float* gru_bhh = (const float*)d_in[20];
    const float* lstm_wih= (const float*)d_in[21];
    const float* lstm_whh= (const float*)d_in[22];
    const float* lstm_bih= (const float*)d_in[23];
    const float* lstm_bhh= (const float*)d_in[24];
    const float* fc_w1   = (const float*)d_in[25];
    const float* fc_b1   = (const float*)d_in[26];
    const float* fc_w2   = (const float*)d_in[27];
    const float* fc_b2   = (const float*)d_in[28];

    const int N = in_sizes[0] / 14;
    const int E = in_sizes[1] / 4;
    const int G = out_size;

    float *p_node, *p_edge, *p_agg, *p_t1, *p_m, *p_gi, *p_gh, *p_et;
    float *p_qs, *p_hl, *p_cl, *p_gl, *p_fc;
    float *p_twih, *p_twhh, *p_tlwih, *p_tlwhh;
    cudaGetSymbolAddress((void**)&p_node, g_node);
    cudaGetSymbolAddress((void**)&p_edge, g_edge);
    cudaGetSymbolAddress((void**)&p_agg,  g_agg);
    cudaGetSymbolAddress((void**)&p_t1,   g_t1);
    cudaGetSymbolAddress((void**)&p_m,    g_m);
    cudaGetSymbolAddress((void**)&p_gi,   g_gi);
    cudaGetSymbolAddress((void**)&p_gh,   g_gh);
    cudaGetSymbolAddress((void**)&p_et,   g_et);
    cudaGetSymbolAddress((void**)&p_qs,   g_qs);
    cudaGetSymbolAddress((void**)&p_hl,   g_hl);
    cudaGetSymbolAddress((void**)&p_cl,   g_cl);
    cudaGetSymbolAddress((void**)&p_gl,   g_gl);
    cudaGetSymbolAddress((void**)&p_fc,   g_fc);
    cudaGetSymbolAddress((void**)&p_twih, t_gwih);
    cudaGetSymbolAddress((void**)&p_twhh, t_gwhh);
    cudaGetSymbolAddress((void**)&p_tlwih, t_lwih);
    cudaGetSymbolAddress((void**)&p_tlwhh, t_lwhh);

    const int TB = 256;
    const int BM = 64;

    // fused weight transposes
    k_prep<<<CDIV(294912, TB), TB>>>(gru_wih, gru_whh, lstm_wih, lstm_whh,
                                     p_twih, p_twhh, p_tlwih, p_tlwhh);

    // input embeddings
    k_gemm<<<dim3(CDIV(N, BM), 1), 256>>>(x, 14, node_w, 128, node_b, p_node, 128, N, 14, 0);
    k_gemm<<<dim3(CDIV(E, BM), 1), 256>>>(eattr, 4, edge_w, 128, edge_b, p_edge, 128, E, 4, 0);

    const int* src = eindex;
    const int* dst = eindex + E;

    for (int l = 0; l < 2; l++) {
        // GINEConv aggregation: agg = (1+eps)*node, then += scattered messages
        k_initagg<<<CDIV(N * H, TB), TB>>>(eps, l, p_node, p_agg, N * H);
        k_scatter<<<CDIV(E * 32, TB), TB>>>(src, dst, p_node, p_edge, p_agg, E);
        // GIN MLP (reads agg == z)
        k_gemm<<<dim3(CDIV(N, BM), 1), 256>>>(p_agg, 128, gin_w1 + l * H * H, 128, gin_b1 + l * H, p_t1, 128, N, 128, 1);
        k_gemm<<<dim3(CDIV(N, BM), 1), 256>>>(p_t1,  128, gin_w2 + l * H * H, 128, gin_b2 + l * H, p_m,  128, N, 128, 0);
        // GRU gates: gi = m @ Wih^T + bih (384 cols via blockIdx.y), gh = h @ Whh^T + bhh
        k_gemm<<<dim3(CDIV(N, BM), 3), 256>>>(p_m,    128, p_twih, 384, gru_bih, p_gi, 384, N, 128, 0);
        k_gemm<<<dim3(CDIV(N, BM), 3), 256>>>(p_node, 128, p_twhh, 384, gru_bhh, p_gh, 384, N, 128, 0);
        k_gru<<<CDIV(N * H, TB), TB>>>(p_gi, p_gh, p_node, N * H);
        // edge MLP
        k_gemm<<<dim3(CDIV(E, BM), 1), 256>>>(p_edge, 128, em_w1 + l * H * H, 128, em_b1 + l * H, p_et,   128, E, 128, 1);
        k_gemm<<<dim3(CDIV(E, BM), 1), 256>>>(p_et,   128, em_w2 + l * H * H, 128, em_b2 + l * H, p_edge, 128, E, 128, 0);
    }

    // Set2Set init: qs=0, hl=0, cl=0
    k_zero3<<<CDIV(G * 2 * H, TB), TB>>>(p_qs, G * 2 * H, p_hl, G * H, p_cl, G * H);

    for (int step = 0; step < 3; step++) {
        // LSTM gates: gl = qs @ Wih^T + bih + hl @ Whh^T + bhh (4 chunks via blockIdx.y)
        k_gemm<<<dim3(CDIV(G, BM), 4), 256>>>(p_qs, 256, p_tlwih, 512, lstm_bih, p_gl, 512, G, 256, 0);
        k_gemm<<<dim3(CDIV(G, BM), 4), 256>>>(p_hl, 128, p_tlwhh, 512, lstm_bhh, p_gl, 512, G, 128, 2);
        k_lstm<<<CDIV(G * H, TB), TB>>>(p_gl, p_hl, p_cl, G * H);
        // fused attention pooling (sorted batch -> warp per graph, no atomics)
        k_set2set<<<CDIV(G * 32, TB), TB>>>(batch, p_node, p_hl, p_qs, N, G);
    }

    // final MLP
    k_gemm<<<dim3(CDIV(G, BM), 1), 256>>>(p_qs, 256, fc_w1, 128, fc_b1, p_fc, 128, G, 256, 1);
    k_fc2<<<CDIV(G * 32, TB), TB>>>(p_fc, fc_w2, fc_b2, (float*)d_out, G);
}

// round 5
// speedup vs baseline: 2.4571x; 1.8761x over previous
#include <cuda_runtime.h>
#include <math.h>
#include <stdint.h>

#define H 128
#define NMAX 100000
#define EMAX 200000
#define GMAX 4096

#define CDIV(a,b) (((a)+(b)-1)/(b))

// ---------------- scratch (device globals; no allocation) ----------------
__device__ float g_node[(size_t)NMAX*H];
__device__ float g_edge[(size_t)EMAX*H];
__device__ float g_agg [(size_t)NMAX*H];
__device__ float g_t1  [(size_t)NMAX*H];
__device__ float g_m   [(size_t)NMAX*H];
__device__ float g_gi  [(size_t)NMAX*3*H];
__device__ float g_gh  [(size_t)NMAX*3*H];
__device__ float g_et  [(size_t)EMAX*H];
__device__ float g_qs  [(size_t)GMAX*2*H];
__device__ float g_hl  [(size_t)GMAX*H];
__device__ float g_cl  [(size_t)GMAX*H];
__device__ float g_gl  [(size_t)GMAX*4*H];
__device__ float g_fc  [(size_t)GMAX*H];
// transposed weights [out,in] for tensor GEMM B operands
__device__ float t_gin1[2*H*H];
__device__ float t_gin2[2*H*H];
__device__ float t_em1 [2*H*H];
__device__ float t_em2 [2*H*H];
__device__ float t_fc1 [H*2*H];   // [128,256]

// ---------------- helpers ----------------
__device__ __forceinline__ float sigf(float x) { return 1.f / (1.f + expf(-x)); }

__device__ __forceinline__ unsigned long long fma2(unsigned long long a,
                                                   unsigned long long b,
                                                   unsigned long long c) {
    unsigned long long d;
    asm("fma.rn.f32x2 %0, %1, %2, %3;" : "=l"(d) : "l"(a), "l"(b), "l"(c));
    return d;
}
union U64F2 { unsigned long long u; float2 f; };
union U128 { float4 v; unsigned long long u[2]; };

__device__ __forceinline__ uint32_t tf32cvt(float v) {
    uint32_t t;
    asm("cvt.rna.tf32.f32 %0, %1;" : "=r"(t) : "f"(v));
    return t;
}

// ---------------- tensor-core GEMM via mma.sync tf32 ----------------
// O[M, col0:col0+128] = act(A[M,K] @ B^T + bias), Bt[cols, K] row-major.
// flags: bit0 relu, bit1 accumulate. K multiple of 32, col count multiple of 128.
#define LDK 36
__global__ void __launch_bounds__(256) k_tmma(
    const float* __restrict__ A, int lda,
    const float* __restrict__ Bt, int ldb,
    const float* __restrict__ bias,
    float* __restrict__ O, int ldo,
    int M, int K, int flags)
{
    __shared__ uint32_t As[128 * LDK];
    __shared__ uint32_t Bs[128 * LDK];
    const int tid = threadIdx.x;
    const int wid = tid >> 5, lane = tid & 31;
    const int lr = lane >> 2, lc = lane & 3;
    const int row0 = blockIdx.x * 128;
    const int col0 = blockIdx.y * 128;
    const int rw = (wid & 3) * 32;       // warp row offset in tile
    const int cw = (wid >> 2) * 64;      // warp col offset in tile

    float acc[2][8][4];
#pragma unroll
    for (int m = 0; m < 2; m++)
#pragma unroll
        for (int n = 0; n < 8; n++)
#pragma unroll
            for (int c = 0; c < 4; c++) acc[m][n][c] = 0.f;

    for (int k0 = 0; k0 < K; k0 += 32) {
        // stage A tile [128 rows x 32 k] as tf32
#pragma unroll
        for (int i = 0; i < 4; i++) {
            int idx = tid + i * 256;
            int r = idx >> 3, f4 = idx & 7;
            float4 v = make_float4(0.f, 0.f, 0.f, 0.f);
            int row = row0 + r;
            if (row < M) v = *(const float4*)&A[(size_t)row * lda + k0 + f4 * 4];
            uint32_t* p = &As[r * LDK + f4 * 4];
            p[0] = tf32cvt(v.x); p[1] = tf32cvt(v.y);
            p[2] = tf32cvt(v.z); p[3] = tf32cvt(v.w);
        }
        // stage B tile [128 cols x 32 k] as tf32 (weights: all rows valid)
#pragma unroll
        for (int i = 0; i < 4; i++) {
            int idx = tid + i * 256;
            int r = idx >> 3, f4 = idx & 7;
            float4 v = *(const float4*)&Bt[(size_t)(col0 + r) * ldb + k0 + f4 * 4];
            uint32_t* p = &Bs[r * LDK + f4 * 4];
            p[0] = tf32cvt(v.x); p[1] = tf32cvt(v.y);
            p[2] = tf32cvt(v.z); p[3] = tf32cvt(v.w);
        }
        __syncthreads();
#pragma unroll
        for (int kk = 0; kk < 32; kk += 8) {
            uint32_t af[2][4];
#pragma unroll
            for (int m = 0; m < 2; m++) {
                int base = (rw + m * 16 + lr) * LDK + kk + lc;
                af[m][0] = As[base];
                af[m][1] = As[base + 8 * LDK];
                af[m][2] = As[base + 4];
                af[m][3] = As[base + 8 * LDK + 4];
            }
            uint32_t bf[8][2];
#pragma unroll
            for (int n = 0; n < 8; n++) {
                int base = (cw + n * 8 + lr) * LDK + kk + lc;
                bf[n][0] = Bs[base];
                bf[n][1] = Bs[base + 4];
            }
#pragma unroll
            for (int m = 0; m < 2; m++)
#pragma unroll
                for (int n = 0; n < 8; n++) {
                    asm volatile(
                        "mma.sync.aligned.m16n8k8.row.col.f32.tf32.tf32.f32 "
                        "{%0,%1,%2,%3}, {%4,%5,%6,%7}, {%8,%9}, {%0,%1,%2,%3};"
                        : "+f"(acc[m][n][0]), "+f"(acc[m][n][1]),
                          "+f"(acc[m][n][2]), "+f"(acc[m][n][3])
                        : "r"(af[m][0]), "r"(af[m][1]), "r"(af[m][2]), "r"(af[m][3]),
                          "r"(bf[n][0]), "r"(bf[n][1]));
                }
        }
        __syncthreads();
    }

    // epilogue: c0/c1 -> (row, col..col+1), c2/c3 -> (row+8, ...)
#pragma unroll
    for (int m = 0; m < 2; m++) {
#pragma unroll
        for (int n = 0; n < 8; n++) {
            int col = col0 + cw + n * 8 + lc * 2;
            float b0 = bias[col], b1 = bias[col + 1];
            int r1 = row0 + rw + m * 16 + lr;
            int r2 = r1 + 8;
            if (r1 < M) {
                float v0 = acc[m][n][0] + b0, v1 = acc[m][n][1] + b1;
                float* op = &O[(size_t)r1 * ldo + col];
                if (flags & 2) { v0 += op[0]; v1 += op[1]; }
                if (flags & 1) { v0 = fmaxf(v0, 0.f); v1 = fmaxf(v1, 0.f); }
                float2 ov = {v0, v1};
                *(float2*)op = ov;
            }
            if (r2 < M) {
                float v0 = acc[m][n][2] + b0, v1 = acc[m][n][3] + b1;
                float* op = &O[(size_t)r2 * ldo + col];
                if (flags & 2) { v0 += op[0]; v1 += op[1]; }
                if (flags & 1) { v0 = fmaxf(v0, 0.f); v1 = fmaxf(v1, 0.f); }
                float2 ov = {v0, v1};
                *(float2*)op = ov;
            }
        }
    }
}

// ---------------- FFMA2 GEMM (input embeddings only, small K) ----------------
__global__ void __launch_bounds__(256) k_gemm(
    const float* __restrict__ A, int lda,
    const float* __restrict__ W, int ldw,
    const float* __restrict__ bias,
    float* __restrict__ O, int ldo,
    int M, int K, int flags)
{
    __shared__ __align__(16) unsigned long long Asd[16][65];
    __shared__ __align__(16) float Ws[16][128];
    const int tid = threadIdx.x;
    const int tx = tid & 31, ty = tid >> 5;
    const int row0 = blockIdx.x * 64;
    const int col0 = blockIdx.y * 128;

    unsigned long long acc[8][2];
#pragma unroll
    for (int r = 0; r < 8; r++) { acc[r][0] = 0ULL; acc[r][1] = 0ULL; }

    for (int k0 = 0; k0 < K; k0 += 16) {
#pragma unroll
        for (int i = tid; i < 1024; i += 256) {
            int r = i >> 4, k = i & 15;
            int row = row0 + r, kk = k0 + k;
            float v = (row < M && kk < K) ? A[(size_t)row * lda + kk] : 0.f;
            U64F2 p; p.f.x = v; p.f.y = v;
            Asd[k][r] = p.u;
        }
#pragma unroll
        for (int i = tid; i < 2048; i += 256) {
            int k = i >> 7, j = i & 127;
            int kk = k0 + k;
            Ws[k][j] = (kk < K) ? W[(size_t)kk * ldw + col0 + j] : 0.f;
        }
        __syncthreads();
#pragma unroll
        for (int k = 0; k < 16; k++) {
            U128 w; w.v = *(const float4*)&Ws[k][tx << 2];
#pragma unroll
            for (int r = 0; r < 8; r++) {
                unsigned long long a = Asd[k][(ty << 3) + r];
                acc[r][0] = fma2(a, w.u[0], acc[r][0]);
                acc[r][1] = fma2(a, w.u[1], acc[r][1]);
            }
        }
        __syncthreads();
    }
    const int col = tx << 2;
    float4 b4 = *(const float4*)&bias[col0 + col];
#pragma unroll
    for (int r = 0; r < 8; r++) {
        int row = row0 + (ty << 3) + r;
        if (row < M) {
            U64F2 p0, p1; p0.u = acc[r][0]; p1.u = acc[r][1];
            float v[4] = {p0.f.x + b4.x, p0.f.y + b4.y, p1.f.x + b4.z, p1.f.y + b4.w};
            float* op = &O[(size_t)row * ldo + col0 + col];
            if (flags & 1) {
#pragma unroll
                for (int c = 0; c < 4; c++) v[c] = fmaxf(v[c], 0.f);
            }
            float4 ov = {v[0], v[1], v[2], v[3]};
            *(float4*)op = ov;
        }
    }
}

// ---------------- small kernels ----------------
// transpose gin/em (8 x [128,128], layer-major) and fc_w1 [256,128] -> [128,256]
__global__ void k_prep(const float* __restrict__ gin1, const float* __restrict__ gin2,
                       const float* __restrict__ em1, const float* __restrict__ em2,
                       const float* __restrict__ fcw1,
                       float* __restrict__ tg1, float* __restrict__ tg2,
                       float* __restrict__ te1, float* __restrict__ te2,
                       float* __restrict__ tf1)
{
    int i = blockIdx.x * blockDim.x + threadIdx.x;
    if (i < 131072) {
        int m = i >> 14, j = i & 16383;
        int r = j >> 7, c = j & 127;
        int l = m & 1, which = m >> 1;
        const float* s = (which == 0) ? gin1 : (which == 1) ? gin2 : (which == 2) ? em1 : em2;
        float* d = (which == 0) ? tg1 : (which == 1) ? tg2 : (which == 2) ? te1 : te2;
        d[(size_t)l * 16384 + c * 128 + r] = s[(size_t)l * 16384 + j];
    } else if (i < 163840) {
        int j = i - 131072;            // fc_w1 [256,128]
        int r = j >> 7, c = j & 127;
        tf1[(size_t)c * 256 + r] = fcw1[j];
    }
}

__global__ void k_zero3(float4* __restrict__ a, int na, float4* __restrict__ b, int nb,
                        float4* __restrict__ c, int nc)
{
    int i = blockIdx.x * blockDim.x + threadIdx.x;
    float4 z = make_float4(0.f, 0.f, 0.f, 0.f);
    if (i < na) a[i] = z;
    if (i < nb) b[i] = z;
    if (i < nc) c[i] = z;
}

__global__ void k_initagg(const float* __restrict__ eps, int l,
                          const float4* __restrict__ node, float4* __restrict__ agg, int n4)
{
    int i = blockIdx.x * blockDim.x + threadIdx.x;
    if (i < n4) {
        float s = 1.f + eps[l];
        float4 v = node[i];
        agg[i] = make_float4(s * v.x, s * v.y, s * v.z, s * v.w);
    }
}

__global__ void k_scatter(const int* __restrict__ src, const int* __restrict__ dst,
                          const float* __restrict__ node, const float* __restrict__ edge,
                          float* __restrict__ agg, int E)
{
    int tid = blockIdx.x * blockDim.x + threadIdx.x;
    int e = tid >> 5;
    if (e >= E) return;
    int lane = tid & 31;
    int s = src[e], d = dst[e];
    float4 nv = *(const float4*)&node[(size_t)s * H + lane * 4];
    float4 ev = *(const float4*)&edge[(size_t)e * H + lane * 4];
    float m0 = fmaxf(nv.x + ev.x, 0.f);
    float m1 = fmaxf(nv.y + ev.y, 0.f);
    float m2 = fmaxf(nv.z + ev.z, 0.f);
    float m3 = fmaxf(nv.w + ev.w, 0.f);
    float* ap = &agg[(size_t)d * H + lane * 4];
    asm volatile("red.global.add.v4.f32 [%0], {%1, %2, %3, %4};"
                 :: "l"(ap), "f"(m0), "f"(m1), "f"(m2), "f"(m3) : "memory");
}

__device__ __forceinline__ float gru1(float gir, float giz, float gin_,
                                      float ghr, float ghz, float ghn, float hv) {
    float r  = sigf(gir + ghr);
    float zt = sigf(giz + ghz);
    float nn = tanhf(gin_ + r * ghn);
    return (1.f - zt) * nn + zt * hv;
}

__global__ void k_gru(const float* __restrict__ gi, const float* __restrict__ gh,
                      float* __restrict__ h, int nw)   // nw = N*32
{
    int idx = blockIdx.x * blockDim.x + threadIdx.x;
    if (idx >= nw) return;
    int row = idx >> 5, j = (idx & 31) * 4;
    const float* gir = &gi[(size_t)row * 384];
    const float* ghr = &gh[(size_t)row * 384];
    float4 ir = *(const float4*)&gir[j];
    float4 iz = *(const float4*)&gir[j + 128];
    float4 in_ = *(const float4*)&gir[j + 256];
    float4 hr = *(const float4*)&ghr[j];
    float4 hz = *(const float4*)&ghr[j + 128];
    float4 hn = *(const float4*)&ghr[j + 256];
    float4* hp = (float4*)&h[(size_t)row * 128 + j];
    float4 hv = *hp;
    float4 o;
    o.x = gru1(ir.x, iz.x, in_.x, hr.x, hz.x, hn.x, hv.x);
    o.y = gru1(ir.y, iz.y, in_.y, hr.y, hz.y, hn.y, hv.y);
    o.z = gru1(ir.z, iz.z, in_.z, hr.z, hz.z, hn.z, hv.z);
    o.w = gru1(ir.w, iz.w, in_.w, hr.w, hz.w, hn.w, hv.w);
    *hp = o;
}

__device__ __forceinline__ void lstm1(float i_, float f_, float g_, float o_,
                                      float& c, float& hh) {
    c = sigf(f_) * c + sigf(i_) * tanhf(g_);
    hh = sigf(o_) * tanhf(c);
}

__global__ void k_lstm(const float* __restrict__ gl, float* __restrict__ hl,
                       float* __restrict__ cl, int nw)   // nw = G*32
{
    int idx = blockIdx.x * blockDim.x + threadIdx.x;
    if (idx >= nw) return;
    int g = idx >> 5, j = (idx & 31) * 4;
    const float* gr = &gl[(size_t)g * 512];
    float4 i_ = *(const float4*)&gr[j];
    float4 f_ = *(const float4*)&gr[j + 128];
    float4 g_ = *(const float4*)&gr[j + 256];
    float4 o_ = *(const float4*)&gr[j + 384];
    float4* cp = (float4*)&cl[(size_t)g * 128 + j];
    float4* hp = (float4*)&hl[(size_t)g * 128 + j];
    float4 c = *cp, hh;
    lstm1(i_.x, f_.x, g_.x, o_.x, c.x, hh.x);
    lstm1(i_.y, f_.y, g_.y, o_.y, c.y, hh.y);
    lstm1(i_.z, f_.z, g_.z, o_.z, c.z, hh.z);
    lstm1(i_.w, f_.w, g_.w, o_.w, c.w, hh.w);
    *cp = c;
    *hp = hh;
}

__global__ void k_set2set(const int* __restrict__ batch, const float* __restrict__ node,
                          const float* __restrict__ hl, float* __restrict__ qs,
                          int N, int G)
{
    int warp = (blockIdx.x * blockDim.x + threadIdx.x) >> 5;
    if (warp >= G) return;
    const int lane = threadIdx.x & 31;
    const int g = warp;

    int lo = 0, hi = N;
    while (lo < hi) { int mid = (lo + hi) >> 1; if (batch[mid] < g) lo = mid + 1; else hi = mid; }
    const int s0 = lo;
    hi = N;
    while (lo < hi) { int mid = (lo + hi) >> 1; if (batch[mid] < g + 1) lo = mid + 1; else hi = mid; }
    const int s1 = lo;

    float4 qv = *(const float4*)&hl[(size_t)g * H + lane * 4];

    float mx = -INFINITY;
    for (int i = s0; i < s1; i++) {
        float4 nv = *(const float4*)&node[(size_t)i * H + lane * 4];
        float d = nv.x * qv.x + nv.y * qv.y + nv.z * qv.z + nv.w * qv.w;
#pragma unroll
        for (int o = 16; o; o >>= 1) d += __shfl_xor_sync(0xffffffffu, d, o);
        mx = fmaxf(mx, d);
    }
    float den = 0.f;
    float4 racc = make_float4(0.f, 0.f, 0.f, 0.f);
    for (int i = s0; i < s1; i++) {
        float4 nv = *(const float4*)&node[(size_t)i * H + lane * 4];
        float d = nv.x * qv.x + nv.y * qv.y + nv.z * qv.z + nv.w * qv.w;
#pragma unroll
        for (int o = 16; o; o >>= 1) d += __shfl_xor_sync(0xffffffffu, d, o);
        float ex = expf(d - mx);
        den += ex;
        racc.x += ex * nv.x; racc.y += ex * nv.y;
        racc.z += ex * nv.z; racc.w += ex * nv.w;
    }
    float inv = 1.f / fmaxf(den, 1e-9f);
    float* qrow = &qs[(size_t)g * 2 * H];
    *(float4*)&qrow[lane * 4] = qv;
    float4 rv = {racc.x * inv, racc.y * inv, racc.z * inv, racc.w * inv};
    *(float4*)&qrow[H + lane * 4] = rv;
}

__global__ void k_fc2(const float* __restrict__ fcin, const float* __restrict__ w2,
                      const float* __restrict__ b2, float* __restrict__ out, int G)
{
    int tid = blockIdx.x * blockDim.x + threadIdx.x;
    int g = tid >> 5;
    if (g >= G) return;
    int lane = tid & 31;
    float s = 0.f;
#pragma unroll
    for (int t = 0; t < 4; t++) {
        int j = lane + t * 32;
        s += fcin[(size_t)g * H + j] * w2[j];
    }
#pragma unroll
    for (int off = 16; off; off >>= 1) s += __shfl_xor_sync(0xffffffffu, s, off);
    if (lane == 0) out[g] = s + b2[0];
}

// ---------------- host launcher ----------------
extern "C" void kernel_launch(void* const* d_in, const int* in_sizes, int n_in,
                              void* d_out, int out_size)
{
    const float* x       = (const float*)d_in[0];
    const float* eattr   = (const float*)d_in[1];
    const int*   eindex  = (const int*)d_in[2];
    const int*   batch   = (const int*)d_in[3];
    const float* node_w  = (const float*)d_in[4];
    const float* node_b  = (const float*)d_in[5];
    const float* edge_w  = (const float*)d_in[6];
    const float* edge_b  = (const float*)d_in[7];
    const float* eps     = (const float*)d_in[8];
    const float* gin_w1  = (const float*)d_in[9];
    const float* gin_b1  = (const float*)d_in[10];
    const float* gin_w2  = (const float*)d_in[11];
    const float* gin_b2  = (const float*)d_in[12];
    const float* em_w1   = (const float*)d_in[13];
    const float* em_b1   = (const float*)d_in[14];
    const float* em_w2   = (const float*)d_in[15];
    const float* em_b2   = (const float*)d_in[16];
    const float* gru_wih = (const float*)d_in[17];
    const float* gru_whh = (const float*)d_in[18];
    const float* gru_bih = (const float*)d_in[19];
    const float* gru_bhh = (const float*)d_in[20];
    const float* lstm_wih= (const float*)d_in[21];
    const float* lstm_whh= (const float*)d_in[22];
    const float* lstm_bih= (const float*)d_in[23];
    const float* lstm_bhh= (const float*)d_in[24];
    const float* fc_w1   = (const float*)d_in[25];
    const float* fc_b1   = (const float*)d_in[26];
    const float* fc_w2   = (const float*)d_in[27];
    const float* fc_b2   = (const float*)d_in[28];

    const int N = in_sizes[0] / 14;
    const int E = in_sizes[1] / 4;
    const int G = out_size;

    float *p_node, *p_edge, *p_agg, *p_t1, *p_m, *p_gi, *p_gh, *p_et;
    float *p_qs, *p_hl, *p_cl, *p_gl, *p_fc;
    float *p_tg1, *p_tg2, *p_te1, *p_te2, *p_tf1;
    cudaGetSymbolAddress((void**)&p_node, g_node);
    cudaGetSymbolAddress((void**)&p_edge, g_edge);
    cudaGetSymbolAddress((void**)&p_agg,  g_agg);
    cudaGetSymbolAddress((void**)&p_t1,   g_t1);
    cudaGetSymbolAddress((void**)&p_m,    g_m);
    cudaGetSymbolAddress((void**)&p_gi,   g_gi);
    cudaGetSymbolAddress((void**)&p_gh,   g_gh);
    cudaGetSymbolAddress((void**)&p_et,   g_et);
    cudaGetSymbolAddress((void**)&p_qs,   g_qs);
    cudaGetSymbolAddress((void**)&p_hl,   g_hl);
    cudaGetSymbolAddress((void**)&p_cl,   g_cl);
    cudaGetSymbolAddress((void**)&p_gl,   g_gl);
    cudaGetSymbolAddress((void**)&p_fc,   g_fc);
    cudaGetSymbolAddress((void**)&p_tg1,  t_gin1);
    cudaGetSymbolAddress((void**)&p_tg2,  t_gin2);
    cudaGetSymbolAddress((void**)&p_te1,  t_em1);
    cudaGetSymbolAddress((void**)&p_te2,  t_em2);
    cudaGetSymbolAddress((void**)&p_tf1,  t_fc1);

    const int TB = 256;

    // weight transposes for tensor-B operands
    k_prep<<<CDIV(163840, TB), TB>>>(gin_w1, gin_w2, em_w1, em_w2, fc_w1,
                                     p_tg1, p_tg2, p_te1, p_te2, p_tf1);

    // input embeddings (small K -> FFMA2 kernel)
    k_gemm<<<dim3(CDIV(N, 64), 1), 256>>>(x, 14, node_w, 128, node_b, p_node, 128, N, 14, 0);
    k_gemm<<<dim3(CDIV(E, 64), 1), 256>>>(eattr, 4, edge_w, 128, edge_b, p_edge, 128, E, 4, 0);

    const int* src = eindex;
    const int* dst = eindex + E;
    const int NT = CDIV(N, 128), ET = CDIV(E, 128), GT = CDIV(G, 128);

    for (int l = 0; l < 2; l++) {
        k_initagg<<<CDIV(N * 32, TB), TB>>>(eps, l, (const float4*)p_node, (float4*)p_agg, N * 32);
        k_scatter<<<CDIV(E * 32, TB), TB>>>(src, dst, p_node, p_edge, p_agg, E);
        // GIN MLP
        k_tmma<<<dim3(NT, 1), 256>>>(p_agg, 128, p_tg1 + l * 16384, 128, gin_b1 + l * H, p_t1, 128, N, 128, 1);
        k_tmma<<<dim3(NT, 1), 256>>>(p_t1,  128, p_tg2 + l * 16384, 128, gin_b2 + l * H, p_m,  128, N, 128, 0);
        // GRU gates (gru_w* are natively [out=384, in=128] -> direct B operand)
        k_tmma<<<dim3(NT, 3), 256>>>(p_m,    128, gru_wih, 128, gru_bih, p_gi, 384, N, 128, 0);
        k_tmma<<<dim3(NT, 3), 256>>>(p_node, 128, gru_whh, 128, gru_bhh, p_gh, 384, N, 128, 0);
        k_gru<<<CDIV(N * 32, TB), TB>>>(p_gi, p_gh, p_node, N * 32);
        // edge MLP
        k_tmma<<<dim3(ET, 1), 256>>>(p_edge, 128, p_te1 + l * 16384, 128, em_b1 + l * H, p_et,   128, E, 128, 1);
        k_tmma<<<dim3(ET, 1), 256>>>(p_et,   128, p_te2 + l * 16384, 128, em_b2 + l * H, p_edge, 128, E, 128, 0);
    }

    // Set2Set init
    k_zero3<<<CDIV(G * 64, TB), TB>>>((float4*)p_qs, G * 64, (float4*)p_hl, G * 32, (float4*)p_cl, G * 32);

    for (int step = 0; step < 3; step++) {
        k_tmma<<<dim3(GT, 4), 256>>>(p_qs, 256, lstm_wih, 256, lstm_bih, p_gl, 512, G, 256, 0);
        k_tmma<<<dim3(GT, 4), 256>>>(p_hl, 128, lstm_whh, 128, lstm_bhh, p_gl, 512, G, 128, 2);
        k_lstm<<<CDIV(G * 32, TB), TB>>>(p_gl, p_hl, p_cl, G * 32);
        k_set2set<<<CDIV(G * 32, TB), TB>>>(batch, p_node, p_hl, p_qs, N, G);
    }

    // final MLP
    k_tmma<<<dim3(GT, 1), 256>>>(p_qs, 256, p_tf1, 256, fc_b1, p_fc, 128, G, 256, 1);
    k_fc2<<<CDIV(G * 32, TB), TB>>>(p_fc, fc_w2, fc_b2, (float*)d_out, G);
}

// round 6
// speedup vs baseline: 3.4413x; 1.4006x over previous
#include <cuda_runtime.h>
#include <math.h>
#include <stdint.h>

#define H 128
#define NMAX 100000
#define EMAX 200000
#define GMAX 4096

#define CDIV(a,b) (((a)+(b)-1)/(b))

// ---------------- scratch ----------------
__device__ float g_node[(size_t)NMAX*H];
__device__ float g_edge[(size_t)EMAX*H];
__device__ float g_agg [(size_t)NMAX*H];
__device__ float g_m   [(size_t)NMAX*H];
__device__ float g_grz [(size_t)NMAX*2*H];
__device__ float g_gin [(size_t)NMAX*H];
__device__ float g_ghn [(size_t)NMAX*H];
__device__ float g_qs  [(size_t)GMAX*2*H];
__device__ float g_hl  [(size_t)GMAX*H];
__device__ float g_cl  [(size_t)GMAX*H];
__device__ float g_gl  [(size_t)GMAX*4*H];
__device__ float g_fc  [(size_t)GMAX*H];
// prepared weights
__device__ float t_gin1[2*H*H];
__device__ float t_gin2[2*H*H];
__device__ float t_em1 [2*H*H];
__device__ float t_em2 [2*H*H];
__device__ float t_fc1 [H*2*H];      // [128,256]
__device__ float t_grz [256*256];    // [256 cols][K=256: wih|whh rows 0..255]
__device__ float t_lw  [512*384];    // [512 cols][K=384: lwih(256)|lwhh(128)]
__device__ float t_grzb[256];
__device__ float t_lb  [512];

// ---------------- helpers ----------------
__device__ __forceinline__ float sigf(float x) { return 1.f / (1.f + expf(-x)); }

__device__ __forceinline__ unsigned long long fma2(unsigned long long a,
                                                   unsigned long long b,
                                                   unsigned long long c) {
    unsigned long long d;
    asm("fma.rn.f32x2 %0, %1, %2, %3;" : "=l"(d) : "l"(a), "l"(b), "l"(c));
    return d;
}
union U64F2 { unsigned long long u; float2 f; };
union U128 { float4 v; unsigned long long u[2]; };

__device__ __forceinline__ uint32_t tf32cvt(float v) {
    uint32_t t;
    asm("cvt.rna.tf32.f32 %0, %1;" : "=r"(t) : "f"(v));
    return t;
}
__device__ __forceinline__ void mma8(float* c, const uint32_t* a, const uint32_t* b) {
    asm volatile(
        "mma.sync.aligned.m16n8k8.row.col.f32.tf32.tf32.f32 "
        "{%0,%1,%2,%3}, {%4,%5,%6,%7}, {%8,%9}, {%0,%1,%2,%3};"
        : "+f"(c[0]), "+f"(c[1]), "+f"(c[2]), "+f"(c[3])
        : "r"(a[0]), "r"(a[1]), "r"(a[2]), "r"(a[3]), "r"(b[0]), "r"(b[1]));
}

#define LDK 36
#define LD2 132

// ---------------- k_tmma: O[M, col0+128] = act(concat(A,A2)[M,K] @ Bt^T + bias) ----------------
// A supplies k in [0,K1), A2 supplies [K1,K). Bt[col][k] row-major, ldb.
// flags: bit0 relu, bit1 accumulate. K,K1 multiples of 32.
__global__ void __launch_bounds__(256) k_tmma(
    const float* __restrict__ A, int lda, int K1,
    const float* __restrict__ A2, int lda2,
    const float* __restrict__ Bt, int ldb,
    const float* __restrict__ bias,
    float* __restrict__ O, int ldo,
    int M, int K, int flags)
{
    __shared__ uint32_t As[128 * LDK];
    __shared__ uint32_t Bs[128 * LDK];
    const int tid = threadIdx.x;
    const int wid = tid >> 5, lane = tid & 31;
    const int lr = lane >> 2, lc = lane & 3;
    const int row0 = blockIdx.x * 128;
    const int col0 = blockIdx.y * 128;
    const int rw = (wid & 3) * 32;
    const int cw = (wid >> 2) * 64;

    float acc[2][8][4];
#pragma unroll
    for (int m = 0; m < 2; m++)
#pragma unroll
        for (int n = 0; n < 8; n++)
#pragma unroll
            for (int c = 0; c < 4; c++) acc[m][n][c] = 0.f;

    for (int k0 = 0; k0 < K; k0 += 32) {
        const float* srcA = (k0 < K1) ? A : A2;
        const int koff = (k0 < K1) ? k0 : k0 - K1;
        const int ldx = (k0 < K1) ? lda : lda2;
#pragma unroll
        for (int i = 0; i < 4; i++) {
            int idx = tid + i * 256;
            int r = idx >> 3, f4 = idx & 7;
            float4 v = make_float4(0.f, 0.f, 0.f, 0.f);
            int row = row0 + r;
            if (row < M) v = *(const float4*)&srcA[(size_t)row * ldx + koff + f4 * 4];
            uint32_t* p = &As[r * LDK + f4 * 4];
            p[0] = tf32cvt(v.x); p[1] = tf32cvt(v.y);
            p[2] = tf32cvt(v.z); p[3] = tf32cvt(v.w);
        }
#pragma unroll
        for (int i = 0; i < 4; i++) {
            int idx = tid + i * 256;
            int r = idx >> 3, f4 = idx & 7;
            float4 v = *(const float4*)&Bt[(size_t)(col0 + r) * ldb + k0 + f4 * 4];
            uint32_t* p = &Bs[r * LDK + f4 * 4];
            p[0] = tf32cvt(v.x); p[1] = tf32cvt(v.y);
            p[2] = tf32cvt(v.z); p[3] = tf32cvt(v.w);
        }
        __syncthreads();
#pragma unroll
        for (int kk = 0; kk < 32; kk += 8) {
            uint32_t af[2][4];
#pragma unroll
            for (int m = 0; m < 2; m++) {
                int base = (rw + m * 16 + lr) * LDK + kk + lc;
                af[m][0] = As[base];
                af[m][1] = As[base + 8 * LDK];
                af[m][2] = As[base + 4];
                af[m][3] = As[base + 8 * LDK + 4];
            }
            uint32_t bf[8][2];
#pragma unroll
            for (int n = 0; n < 8; n++) {
                int base = (cw + n * 8 + lr) * LDK + kk + lc;
                bf[n][0] = Bs[base];
                bf[n][1] = Bs[base + 4];
            }
#pragma unroll
            for (int m = 0; m < 2; m++)
#pragma unroll
                for (int n = 0; n < 8; n++) mma8(acc[m][n], af[m], bf[n]);
        }
        __syncthreads();
    }

#pragma unroll
    for (int m = 0; m < 2; m++) {
#pragma unroll
        for (int n = 0; n < 8; n++) {
            int col = col0 + cw + n * 8 + lc * 2;
            float b0 = bias[col], b1 = bias[col + 1];
            int r1 = row0 + rw + m * 16 + lr;
            int r2 = r1 + 8;
            if (r1 < M) {
                float v0 = acc[m][n][0] + b0, v1 = acc[m][n][1] + b1;
                float* op = &O[(size_t)r1 * ldo + col];
                if (flags & 2) { v0 += op[0]; v1 += op[1]; }
                if (flags & 1) { v0 = fmaxf(v0, 0.f); v1 = fmaxf(v1, 0.f); }
                float2 ov = {v0, v1};
                *(float2*)op = ov;
            }
            if (r2 < M) {
                float v0 = acc[m][n][2] + b0, v1 = acc[m][n][3] + b1;
                float* op = &O[(size_t)r2 * ldo + col];
                if (flags & 2) { v0 += op[0]; v1 += op[1]; }
                if (flags & 1) { v0 = fmaxf(v0, 0.f); v1 = fmaxf(v1, 0.f); }
                float2 ov = {v0, v1};
                *(float2*)op = ov;
            }
        }
    }
}

// ---------------- k_mlp2: O = relu(A@W1^T+b1)@W2^T + b2, all dims 128 ----------------
__global__ void __launch_bounds__(256) k_mlp2(
    const float* __restrict__ A, int lda,
    const float* __restrict__ W1t, const float* __restrict__ b1,
    const float* __restrict__ W2t, const float* __restrict__ b2,
    float* __restrict__ O, int ldo, int M)
{
    extern __shared__ uint32_t sm[];
    uint32_t* As  = sm;                     // 128*LDK
    uint32_t* Bs  = sm + 128 * LDK;         // 128*LDK
    uint32_t* As2 = sm + 2 * 128 * LDK;     // 128*LD2
    const int tid = threadIdx.x;
    const int wid = tid >> 5, lane = tid & 31;
    const int lr = lane >> 2, lc = lane & 3;
    const int row0 = blockIdx.x * 128;
    const int rw = (wid & 3) * 32;
    const int cw = (wid >> 2) * 64;

    float acc[2][8][4];
#pragma unroll
    for (int m = 0; m < 2; m++)
#pragma unroll
        for (int n = 0; n < 8; n++)
#pragma unroll
            for (int c = 0; c < 4; c++) acc[m][n][c] = 0.f;

    // ---- GEMM1: A @ W1t ----
    for (int k0 = 0; k0 < 128; k0 += 32) {
#pragma unroll
        for (int i = 0; i < 4; i++) {
            int idx = tid + i * 256;
            int r = idx >> 3, f4 = idx & 7;
            float4 v = make_float4(0.f, 0.f, 0.f, 0.f);
            int row = row0 + r;
            if (row < M) v = *(const float4*)&A[(size_t)row * lda + k0 + f4 * 4];
            uint32_t* p = &As[r * LDK + f4 * 4];
            p[0] = tf32cvt(v.x); p[1] = tf32cvt(v.y);
            p[2] = tf32cvt(v.z); p[3] = tf32cvt(v.w);
        }
#pragma unroll
        for (int i = 0; i < 4; i++) {
            int idx = tid + i * 256;
            int r = idx >> 3, f4 = idx & 7;
            float4 v = *(const float4*)&W1t[(size_t)r * 128 + k0 + f4 * 4];
            uint32_t* p = &Bs[r * LDK + f4 * 4];
            p[0] = tf32cvt(v.x); p[1] = tf32cvt(v.y);
            p[2] = tf32cvt(v.z); p[3] = tf32cvt(v.w);
        }
        __syncthreads();
#pragma unroll
        for (int kk = 0; kk < 32; kk += 8) {
            uint32_t af[2][4];
#pragma unroll
            for (int m = 0; m < 2; m++) {
                int base = (rw + m * 16 + lr) * LDK + kk + lc;
                af[m][0] = As[base];
                af[m][1] = As[base + 8 * LDK];
                af[m][2] = As[base + 4];
                af[m][3] = As[base + 8 * LDK + 4];
            }
            uint32_t bf[8][2];
#pragma unroll
            for (int n = 0; n < 8; n++) {
                int base = (cw + n * 8 + lr) * LDK + kk + lc;
                bf[n][0] = Bs[base];
                bf[n][1] = Bs[base + 4];
            }
#pragma unroll
            for (int m = 0; m < 2; m++)
#pragma unroll
                for (int n = 0; n < 8; n++) mma8(acc[m][n], af[m], bf[n]);
        }
        __syncthreads();
    }

    // ---- epilogue1: relu(+b1) -> As2 (tf32) ----
#pragma unroll
    for (int m = 0; m < 2; m++) {
#pragma unroll
        for (int n = 0; n < 8; n++) {
            int col = cw + n * 8 + lc * 2;
            float b0 = b1[col], bb1 = b1[col + 1];
            int r1 = rw + m * 16 + lr, r2 = r1 + 8;
            As2[r1 * LD2 + col]     = tf32cvt(fmaxf(acc[m][n][0] + b0, 0.f));
            As2[r1 * LD2 + col + 1] = tf32cvt(fmaxf(acc[m][n][1] + bb1, 0.f));
            As2[r2 * LD2 + col]     = tf32cvt(fmaxf(acc[m][n][2] + b0, 0.f));
            As2[r2 * LD2 + col + 1] = tf32cvt(fmaxf(acc[m][n][3] + bb1, 0.f));
            acc[m][n][0] = acc[m][n][1] = acc[m][n][2] = acc[m][n][3] = 0.f;
        }
    }
    __syncthreads();

    // ---- GEMM2: As2 @ W2t ----
    for (int k0 = 0; k0 < 128; k0 += 32) {
#pragma unroll
        for (int i = 0; i < 4; i++) {
            int idx = tid + i * 256;
            int r = idx >> 3, f4 = idx & 7;
            float4 v = *(const float4*)&W2t[(size_t)r * 128 + k0 + f4 * 4];
            uint32_t* p = &Bs[r * LDK + f4 * 4];
            p[0] = tf32cvt(v.x); p[1] = tf32cvt(v.y);
            p[2] = tf32cvt(v.z); p[3] = tf32cvt(v.w);
        }
        __syncthreads();
#pragma unroll
        for (int kk = 0; kk < 32; kk += 8) {
            uint32_t af[2][4];
#pragma unroll
            for (int m = 0; m < 2; m++) {
                int base = (rw + m * 16 + lr) * LD2 + k0 + kk + lc;
                af[m][0] = As2[base];
                af[m][1] = As2[base + 8 * LD2];
                af[m][2] = As2[base + 4];
                af[m][3] = As2[base + 8 * LD2 + 4];
            }
            uint32_t bf[8][2];
#pragma unroll
            for (int n = 0; n < 8; n++) {
                int base = (cw + n * 8 + lr) * LDK + kk + lc;
                bf[n][0] = Bs[base];
                bf[n][1] = Bs[base + 4];
            }
#pragma unroll
            for (int m = 0; m < 2; m++)
#pragma unroll
                for (int n = 0; n < 8; n++) mma8(acc[m][n], af[m], bf[n]);
        }
        __syncthreads();
    }

    // ---- epilogue2 ----
#pragma unroll
    for (int m = 0; m < 2; m++) {
#pragma unroll
        for (int n = 0; n < 8; n++) {
            int col = cw + n * 8 + lc * 2;
            float b0 = b2[col], bb1 = b2[col + 1];
            int r1 = row0 + rw + m * 16 + lr;
            int r2 = r1 + 8;
            if (r1 < M) {
                float2 ov = {acc[m][n][0] + b0, acc[m][n][1] + bb1};
                *(float2*)&O[(size_t)r1 * ldo + col] = ov;
            }
            if (r2 < M) {
                float2 ov = {acc[m][n][2] + b0, acc[m][n][3] + bb1};
                *(float2*)&O[(size_t)r2 * ldo + col] = ov;
            }
        }
    }
}

// ---------------- FFMA2 GEMM (input embeddings, small K) ----------------
__global__ void __launch_bounds__(256) k_gemm(
    const float* __restrict__ A, int lda,
    const float* __restrict__ W, int ldw,
    const float* __restrict__ bias,
    float* __restrict__ O, int ldo,
    int M, int K, int flags)
{
    __shared__ __align__(16) unsigned long long Asd[16][65];
    __shared__ __align__(16) float Ws[16][128];
    const int tid = threadIdx.x;
    const int tx = tid & 31, ty = tid >> 5;
    const int row0 = blockIdx.x * 64;
    const int col0 = blockIdx.y * 128;

    unsigned long long acc[8][2];
#pragma unroll
    for (int r = 0; r < 8; r++) { acc[r][0] = 0ULL; acc[r][1] = 0ULL; }

    for (int k0 = 0; k0 < K; k0 += 16) {
#pragma unroll
        for (int i = tid; i < 1024; i += 256) {
            int r = i >> 4, k = i & 15;
            int row = row0 + r, kk = k0 + k;
            float v = (row < M && kk < K) ? A[(size_t)row * lda + kk] : 0.f;
            U64F2 p; p.f.x = v; p.f.y = v;
            Asd[k][r] = p.u;
        }
#pragma unroll
        for (int i = tid; i < 2048; i += 256) {
            int k = i >> 7, j = i & 127;
            int kk = k0 + k;
            Ws[k][j] = (kk < K) ? W[(size_t)kk * ldw + col0 + j] : 0.f;
        }
        __syncthreads();
#pragma unroll
        for (int k = 0; k < 16; k++) {
            U128 w; w.v = *(const float4*)&Ws[k][tx << 2];
#pragma unroll
            for (int r = 0; r < 8; r++) {
                unsigned long long a = Asd[k][(ty << 3) + r];
                acc[r][0] = fma2(a, w.u[0], acc[r][0]);
                acc[r][1] = fma2(a, w.u[1], acc[r][1]);
            }
        }
        __syncthreads();
    }
    const int col = tx << 2;
    float4 b4 = *(const float4*)&bias[col0 + col];
#pragma unroll
    for (int r = 0; r < 8; r++) {
        int row = row0 + (ty << 3) + r;
        if (row < M) {
            U64F2 p0, p1; p0.u = acc[r][0]; p1.u = acc[r][1];
            float v[4] = {p0.f.x + b4.x, p0.f.y + b4.y, p1.f.x + b4.z, p1.f.y + b4.w};
            float* op = &O[(size_t)row * ldo + col0 + col];
            if (flags & 1) {
#pragma unroll
                for (int c = 0; c < 4; c++) v[c] = fmaxf(v[c], 0.f);
            }
            float4 ov = {v[0], v[1], v[2], v[3]};
            *(float4*)op = ov;
        }
    }
}

// ---------------- prep: transposes + stacked GRU/LSTM weights + combined biases ----------------
__global__ void k_prep(const float* __restrict__ gin1, const float* __restrict__ gin2,
                       const float* __restrict__ em1, const float* __restrict__ em2,
                       const float* __restrict__ fcw1,
                       const float* __restrict__ gwih, const float* __restrict__ gwhh,
                       const float* __restrict__ gbih, const float* __restrict__ gbhh,
                       const float* __restrict__ lwih, const float* __restrict__ lwhh,
                       const float* __restrict__ lbih, const float* __restrict__ lbhh,
                       float* __restrict__ tg1, float* __restrict__ tg2,
                       float* __restrict__ te1, float* __restrict__ te2,
                       float* __restrict__ tf1,
                       float* __restrict__ tgrz, float* __restrict__ tlw,
                       float* __restrict__ tgrzb, float* __restrict__ tlb)
{
    int i = blockIdx.x * blockDim.x + threadIdx.x;
    if (i < 131072) {
        int m = i >> 14, j = i & 16383;
        int r = j >> 7, c = j & 127;
        int l = m & 1, which = m >> 1;
        const float* s = (which == 0) ? gin1 : (which == 1) ? gin2 : (which == 2) ? em1 : em2;
        float* d = (which == 0) ? tg1 : (which == 1) ? tg2 : (which == 2) ? te1 : te2;
        d[(size_t)l * 16384 + c * 128 + r] = s[(size_t)l * 16384 + j];
    } else if (i < 163840) {
        int j = i - 131072;            // fc_w1 [256,128] -> [128,256]
        int r = j >> 7, c = j & 127;
        tf1[(size_t)c * 256 + r] = fcw1[j];
    } else if (i < 229376) {
        int j = i - 163840;            // t_grz [256][256]
        int c = j >> 8, k = j & 255;
        tgrz[j] = (k < 128) ? gwih[c * 128 + k] : gwhh[c * 128 + (k - 128)];
    } else if (i < 425984) {
        int j = i - 229376;            // t_lw [512][384]
        int c = j / 384, k = j % 384;
        tlw[j] = (k < 256) ? lwih[c * 256 + k] : lwhh[c * 128 + (k - 256)];
    } else if (i < 426240) {
        int j = i - 425984;
        tgrzb[j] = gbih[j] + gbhh[j];
    } else if (i < 426752) {
        int j = i - 426240;
        tlb[j] = lbih[j] + lbhh[j];
    }
}

__global__ void k_zero3(float4* __restrict__ a, int na, float4* __restrict__ b, int nb,
                        float4* __restrict__ c, int nc)
{
    int i = blockIdx.x * blockDim.x + threadIdx.x;
    float4 z = make_float4(0.f, 0.f, 0.f, 0.f);
    if (i < na) a[i] = z;
    if (i < nb) b[i] = z;
    if (i < nc) c[i] = z;
}

__global__ void k_initagg(const float* __restrict__ eps, int l,
                          const float4* __restrict__ node, float4* __restrict__ agg, int n4)
{
    int i = blockIdx.x * blockDim.x + threadIdx.x;
    if (i < n4) {
        float s = 1.f + eps[l];
        float4 v = node[i];
        agg[i] = make_float4(s * v.x, s * v.y, s * v.z, s * v.w);
    }
}

__global__ void k_scatter(const int* __restrict__ src, const int* __restrict__ dst,
                          const float* __restrict__ node, const float* __restrict__ edge,
                          float* __restrict__ agg, int E)
{
    int tid = blockIdx.x * blockDim.x + threadIdx.x;
    int e = tid >> 5;
    if (e >= E) return;
    int lane = tid & 31;
    int s = src[e], d = dst[e];
    float4 nv = *(const float4*)&node[(size_t)s * H + lane * 4];
    float4 ev = *(const float4*)&edge[(size_t)e * H + lane * 4];
    float m0 = fmaxf(nv.x + ev.x, 0.f);
    float m1 = fmaxf(nv.y + ev.y, 0.f);
    float m2 = fmaxf(nv.z + ev.z, 0.f);
    float m3 = fmaxf(nv.w + ev.w, 0.f);
    float* ap = &agg[(size_t)d * H + lane * 4];
    asm volatile("red.global.add.v4.f32 [%0], {%1, %2, %3, %4};"
                 :: "l"(ap), "f"(m0), "f"(m1), "f"(m2), "f"(m3) : "memory");
}

// GRU elementwise with pre-summed r,z gates
__global__ void k_gru(const float* __restrict__ grz, const float* __restrict__ gin,
                      const float* __restrict__ ghn, float* __restrict__ h, int nw)
{
    int idx = blockIdx.x * blockDim.x + threadIdx.x;
    if (idx >= nw) return;
    int row = idx >> 5, j = (idx & 31) * 4;
    float4 rz_r = *(const float4*)&grz[(size_t)row * 256 + j];
    float4 rz_z = *(const float4*)&grz[(size_t)row * 256 + 128 + j];
    float4 gi = *(const float4*)&gin[(size_t)row * 128 + j];
    float4 gh = *(const float4*)&ghn[(size_t)row * 128 + j];
    float4* hp = (float4*)&h[(size_t)row * 128 + j];
    float4 hv = *hp;
    float4 o;
    {
        float r = sigf(rz_r.x), z = sigf(rz_z.x);
        float n = tanhf(gi.x + r * gh.x);
        o.x = (1.f - z) * n + z * hv.x;
    }
    {
        float r = sigf(rz_r.y), z = sigf(rz_z.y);
        float n = tanhf(gi.y + r * gh.y);
        o.y = (1.f - z) * n + z * hv.y;
    }
    {
        float r = sigf(rz_r.z), z = sigf(rz_z.z);
        float n = tanhf(gi.z + r * gh.z);
        o.z = (1.f - z) * n + z * hv.z;
    }
    {
        float r = sigf(rz_r.w), z = sigf(rz_z.w);
        float n = tanhf(gi.w + r * gh.w);
        o.w = (1.f - z) * n + z * hv.w;
    }
    *hp = o;
}

__device__ __forceinline__ void lstm1(float i_, float f_, float g_, float o_,
                                      float& c, float& hh) {
    c = sigf(f_) * c + sigf(i_) * tanhf(g_);
    hh = sigf(o_) * tanhf(c);
}

__global__ void k_lstm(const float* __restrict__ gl, float* __restrict__ hl,
                       float* __restrict__ cl, int nw)
{
    int idx = blockIdx.x * blockDim.x + threadIdx.x;
    if (idx >= nw) return;
    int g = idx >> 5, j = (idx & 31) * 4;
    const float* gr = &gl[(size_t)g * 512];
    float4 i_ = *(const float4*)&gr[j];
    float4 f_ = *(const float4*)&gr[j + 128];
    float4 g_ = *(const float4*)&gr[j + 256];
    float4 o_ = *(const float4*)&gr[j + 384];
    float4* cp = (float4*)&cl[(size_t)g * 128 + j];
    float4* hp = (float4*)&hl[(size_t)g * 128 + j];
    float4 c = *cp, hh;
    lstm1(i_.x, f_.x, g_.x, o_.x, c.x, hh.x);
    lstm1(i_.y, f_.y, g_.y, o_.y, c.y, hh.y);
    lstm1(i_.z, f_.z, g_.z, o_.z, c.z, hh.z);
    lstm1(i_.w, f_.w, g_.w, o_.w, c.w, hh.w);
    *cp = c;
    *hp = hh;
}

// one warp per graph, single-pass online softmax
__global__ void k_set2set(const int* __restrict__ batch, const float* __restrict__ node,
                          const float* __restrict__ hl, float* __restrict__ qs,
                          int N, int G)
{
    int warp = (blockIdx.x * blockDim.x + threadIdx.x) >> 5;
    if (warp >= G) return;
    const int lane = threadIdx.x & 31;
    const int g = warp;

    int lo = 0, hi = N;
    while (lo < hi) { int mid = (lo + hi) >> 1; if (batch[mid] < g) lo = mid + 1; else hi = mid; }
    const int s0 = lo;
    hi = N;
    while (lo < hi) { int mid = (lo + hi) >> 1; if (batch[mid] < g + 1) lo = mid + 1; else hi = mid; }
    const int s1 = lo;

    float4 qv = *(const float4*)&hl[(size_t)g * H + lane * 4];

    float mx = -INFINITY, den = 0.f;
    float4 racc = make_float4(0.f, 0.f, 0.f, 0.f);
    for (int i = s0; i < s1; i++) {
        float4 nv = *(const float4*)&node[(size_t)i * H + lane * 4];
        float d = nv.x * qv.x + nv.y * qv.y + nv.z * qv.z + nv.w * qv.w;
#pragma unroll
        for (int o = 16; o; o >>= 1) d += __shfl_xor_sync(0xffffffffu, d, o);
        float nm = fmaxf(mx, d);
        float sc = expf(mx - nm);       // 0 when mx=-inf
        float ex = expf(d - nm);
        den = den * sc + ex;
        racc.x = racc.x * sc + ex * nv.x;
        racc.y = racc.y * sc + ex * nv.y;
        racc.z = racc.z * sc + ex * nv.z;
        racc.w = racc.w * sc + ex * nv.w;
        mx = nm;
    }
    float inv = 1.f / fmaxf(den, 1e-9f);
    float* qrow = &qs[(size_t)g * 2 * H];
    *(float4*)&qrow[lane * 4] = qv;
    float4 rv = {racc.x * inv, racc.y * inv, racc.z * inv, racc.w * inv};
    *(float4*)&qrow[H + lane * 4] = rv;
}

__global__ void k_fc2(const float* __restrict__ fcin, const float* __restrict__ w2,
                      const float* __restrict__ b2, float* __restrict__ out, int G)
{
    int tid = blockIdx.x * blockDim.x + threadIdx.x;
    int g = tid >> 5;
    if (g >= G) return;
    int lane = tid & 31;
    float s = 0.f;
#pragma unroll
    for (int t = 0; t < 4; t++) {
        int j = lane + t * 32;
        s += fcin[(size_t)g * H + j] * w2[j];
    }
#pragma unroll
    for (int off = 16; off; off >>= 1) s += __shfl_xor_sync(0xffffffffu, s, off);
    if (lane == 0) out[g] = s + b2[0];
}

// ---------------- host launcher ----------------
extern "C" void kernel_launch(void* const* d_in, const int* in_sizes, int n_in,
                              void* d_out, int out_size)
{
    const float* x       = (const float*)d_in[0];
    const float* eattr   = (const float*)d_in[1];
    const int*   eindex  = (const int*)d_in[2];
    const int*   batch   = (const int*)d_in[3];
    const float* node_w  = (const float*)d_in[4];
    const float* node_b  = (const float*)d_in[5];
    const float* edge_w  = (const float*)d_in[6];
    const float* edge_b  = (const float*)d_in[7];
    const float* eps     = (const float*)d_in[8];
    const float* gin_w1  = (const float*)d_in[9];
    const float* gin_b1  = (const float*)d_in[10];
    const float* gin_w2  = (const float*)d_in[11];
    const float* gin_b2  = (const float*)d_in[12];
    const float* em_w1   = (const float*)d_in[13];
    const float* em_b1   = (const float*)d_in[14];
    const float* em_w2   = (const float*)d_in[15];
    const float* em_b2   = (const float*)d_in[16];
    const float* gru_wih = (const float*)d_in[17];
    const float* gru_whh = (const float*)d_in[18];
    const float* gru_bih = (const float*)d_in[19];
    const float* gru_bhh = (const float*)d_in[20];
    const float* lstm_wih= (const float*)d_in[21];
    const float* lstm_whh= (const float*)d_in[22];
    const float* lstm_bih= (const float*)d_in[23];
    const float* lstm_bhh= (const float*)d_in[24];
    const float* fc_w1   = (const float*)d_in[25];
    const float* fc_b1   = (const float*)d_in[26];
    const float* fc_w2   = (const float*)d_in[27];
    const float* fc_b2   = (const float*)d_in[28];

    const int N = in_sizes[0] / 14;
    const int E = in_sizes[1] / 4;
    const int G = out_size;

    float *p_node, *p_edge, *p_agg, *p_m, *p_grz, *p_gin, *p_ghn;
    float *p_qs, *p_hl, *p_cl, *p_gl, *p_fc;
    float *p_tg1, *p_tg2, *p_te1, *p_te2, *p_tf1, *p_tgrz, *p_tlw, *p_tgrzb, *p_tlb;
    cudaGetSymbolAddress((void**)&p_node, g_node);
    cudaGetSymbolAddress((void**)&p_edge, g_edge);
    cudaGetSymbolAddress((void**)&p_agg,  g_agg);
    cudaGetSymbolAddress((void**)&p_m,    g_m);
    cudaGetSymbolAddress((void**)&p_grz,  g_grz);
    cudaGetSymbolAddress((void**)&p_gin,  g_gin);
    cudaGetSymbolAddress((void**)&p_ghn,  g_ghn);
    cudaGetSymbolAddress((void**)&p_qs,   g_qs);
    cudaGetSymbolAddress((void**)&p_hl,   g_hl);
    cudaGetSymbolAddress((void**)&p_cl,   g_cl);
    cudaGetSymbolAddress((void**)&p_gl,   g_gl);
    cudaGetSymbolAddress((void**)&p_fc,   g_fc);
    cudaGetSymbolAddress((void**)&p_tg1,  t_gin1);
    cudaGetSymbolAddress((void**)&p_tg2,  t_gin2);
    cudaGetSymbolAddress((void**)&p_te1,  t_em1);
    cudaGetSymbolAddress((void**)&p_te2,  t_em2);
    cudaGetSymbolAddress((void**)&p_tf1,  t_fc1);
    cudaGetSymbolAddress((void**)&p_tgrz, t_grz);
    cudaGetSymbolAddress((void**)&p_tlw,  t_lw);
    cudaGetSymbolAddress((void**)&p_tgrzb, t_grzb);
    cudaGetSymbolAddress((void**)&p_tlb,  t_lb);

    const int TB = 256;
    const int SMEM_MLP2 = (2 * 128 * LDK + 128 * LD2) * 4;
    cudaFuncSetAttribute(k_mlp2, cudaFuncAttributeMaxDynamicSharedMemorySize, SMEM_MLP2);

    k_prep<<<CDIV(426752, TB), TB>>>(gin_w1, gin_w2, em_w1, em_w2, fc_w1,
                                     gru_wih, gru_whh, gru_bih, gru_bhh,
                                     lstm_wih, lstm_whh, lstm_bih, lstm_bhh,
                                     p_tg1, p_tg2, p_te1, p_te2, p_tf1,
                                     p_tgrz, p_tlw, p_tgrzb, p_tlb);

    // input embeddings
    k_gemm<<<dim3(CDIV(N, 64), 1), 256>>>(x, 14, node_w, 128, node_b, p_node, 128, N, 14, 0);
    k_gemm<<<dim3(CDIV(E, 64), 1), 256>>>(eattr, 4, edge_w, 128, edge_b, p_edge, 128, E, 4, 0);

    const int* src = eindex;
    const int* dst = eindex + E;
    const int NT = CDIV(N, 128), ET = CDIV(E, 128), GT = CDIV(G, 128);

    for (int l = 0; l < 2; l++) {
        k_initagg<<<CDIV(N * 32, TB), TB>>>(eps, l, (const float4*)p_node, (float4*)p_agg, N * 32);
        k_scatter<<<CDIV(E * 32, TB), TB>>>(src, dst, p_node, p_edge, p_agg, E);
        // GIN MLP fused
        k_mlp2<<<NT, 256, SMEM_MLP2>>>(p_agg, 128, p_tg1 + l * 16384, gin_b1 + l * H,
                                       p_tg2 + l * 16384, gin_b2 + l * H, p_m, 128, N);
        // GRU: grz = [m|h] @ t_grz^T (pre-summed r,z), gin/ghn separately
        k_tmma<<<dim3(NT, 2), 256>>>(p_m, 128, 128, p_node, 128, p_tgrz, 256, p_tgrzb,
                                     p_grz, 256, N, 256, 0);
        k_tmma<<<dim3(NT, 1), 256>>>(p_m, 128, 128, p_m, 128, gru_wih + 256 * 128, 128,
                                     gru_bih + 256, p_gin, 128, N, 128, 0);
        k_tmma<<<dim3(NT, 1), 256>>>(p_node, 128, 128, p_node, 128, gru_whh + 256 * 128, 128,
                                     gru_bhh + 256, p_ghn, 128, N, 128, 0);
        k_gru<<<CDIV(N * 32, TB), TB>>>(p_grz, p_gin, p_ghn, p_node, N * 32);
        // edge MLP fused, in-place
        k_mlp2<<<ET, 256, SMEM_MLP2>>>(p_edge, 128, p_te1 + l * 16384, em_b1 + l * H,
                                       p_te2 + l * 16384, em_b2 + l * H, p_edge, 128, E);
    }

    // Set2Set
    k_zero3<<<CDIV(G * 64, TB), TB>>>((float4*)p_qs, G * 64, (float4*)p_hl, G * 32, (float4*)p_cl, G * 32);
    for (int step = 0; step < 3; step++) {
        k_tmma<<<dim3(GT, 4), 256>>>(p_qs, 256, 256, p_hl, 128, p_tlw, 384, p_tlb,
                                     p_gl, 512, G, 384, 0);
        k_lstm<<<CDIV(G * 32, TB), TB>>>(p_gl, p_hl, p_cl, G * 32);
        k_set2set<<<CDIV(G * 32, TB), TB>>>(batch, p_node, p_hl, p_qs, N, G);
    }

    // final MLP
    k_tmma<<<dim3(GT, 1), 256>>>(p_qs, 256, 256, p_qs, 256, p_tf1, 256, fc_b1,
                                 p_fc, 128, G, 256, 1);
    k_fc2<<<CDIV(G * 32, TB), TB>>>(p_fc, fc_w2, fc_b2, (float*)d_out, G);
}

// round 7
// speedup vs baseline: 3.5135x; 1.0210x over previous
#include <cuda_runtime.h>
#include <math.h>
#include <stdint.h>

#define H 128
#define NMAX 100000
#define EMAX 200000
#define GMAX 4096

#define CDIV(a,b) (((a)+(b)-1)/(b))

// ---------------- scratch ----------------
__device__ float g_node[(size_t)NMAX*H];
__device__ float g_edge[(size_t)EMAX*H];
__device__ float g_agg [(size_t)NMAX*H];
__device__ float g_m   [(size_t)NMAX*H];
__device__ float g_gates[(size_t)NMAX*3*H];   // [N][384]: r | z | n_i
__device__ float g_qs  [(size_t)GMAX*2*H];
__device__ float g_hl  [(size_t)GMAX*H];
__device__ float g_cl  [(size_t)GMAX*H];
__device__ float g_gl  [(size_t)GMAX*4*H];
__device__ float g_fc  [(size_t)GMAX*H];
// prepared weights
__device__ float t_gin1[2*H*H];
__device__ float t_gin2[2*H*H];
__device__ float t_em1 [2*H*H];
__device__ float t_em2 [2*H*H];
__device__ float t_fc1 [H*2*H];       // [128,256]
__device__ float t_gall[384*256];     // [384 cols][K=256]: rz (wih|whh) + n_i (wih|0)
__device__ float t_gallb[384];
__device__ float t_lw  [512*384];     // [512 cols][K=384: lwih(256)|lwhh(128)]
__device__ float t_lb  [512];

// ---------------- helpers ----------------
__device__ __forceinline__ float sigf(float x) { return 1.f / (1.f + expf(-x)); }

__device__ __forceinline__ unsigned long long fma2(unsigned long long a,
                                                   unsigned long long b,
                                                   unsigned long long c) {
    unsigned long long d;
    asm("fma.rn.f32x2 %0, %1, %2, %3;" : "=l"(d) : "l"(a), "l"(b), "l"(c));
    return d;
}
union U64F2 { unsigned long long u; float2 f; };
union U128 { float4 v; unsigned long long u[2]; };

__device__ __forceinline__ uint32_t tf32cvt(float v) {
    uint32_t t;
    asm("cvt.rna.tf32.f32 %0, %1;" : "=r"(t) : "f"(v));
    return t;
}
__device__ __forceinline__ void mma8(float* c, const uint32_t* a, const uint32_t* b) {
    asm volatile(
        "mma.sync.aligned.m16n8k8.row.col.f32.tf32.tf32.f32 "
        "{%0,%1,%2,%3}, {%4,%5,%6,%7}, {%8,%9}, {%0,%1,%2,%3};"
        : "+f"(c[0]), "+f"(c[1]), "+f"(c[2]), "+f"(c[3])
        : "r"(a[0]), "r"(a[1]), "r"(a[2]), "r"(a[3]), "r"(b[0]), "r"(b[1]));
}
__device__ __forceinline__ void redv4(float* p, float a, float b, float c, float d) {
    asm volatile("red.global.add.v4.f32 [%0], {%1, %2, %3, %4};"
                 :: "l"(p), "f"(a), "f"(b), "f"(c), "f"(d) : "memory");
}
__device__ __forceinline__ void redv2(float* p, float a, float b) {
    asm volatile("red.global.add.v2.f32 [%0], {%1, %2};"
                 :: "l"(p), "f"(a), "f"(b) : "memory");
}

#define LDK 36
#define LD2 132

// ---------------- k_tmma: O[M, col0+128] = act(concat(A,A2)[M,K] @ Bt^T + bias) ----------------
// flags: bit0 relu, bit1 accumulate, bit2 GRU-finalize epilogue.
// GRU-finalize: O = h buffer; acc+bias = n_h; uses gates[row][384], writes h (+agg if epsidx>=0).
__global__ void __launch_bounds__(256) k_tmma(
    const float* __restrict__ A, int lda, int K1,
    const float* __restrict__ A2, int lda2,
    const float* __restrict__ Bt, int ldb,
    const float* __restrict__ bias,
    float* __restrict__ O, int ldo,
    int M, int K, int flags,
    const float* __restrict__ gates, float* __restrict__ aggw,
    const float* __restrict__ eps, int epsidx)
{
    __shared__ uint32_t As[128 * LDK];
    __shared__ uint32_t Bs[128 * LDK];
    const int tid = threadIdx.x;
    const int wid = tid >> 5, lane = tid & 31;
    const int lr = lane >> 2, lc = lane & 3;
    const int row0 = blockIdx.x * 128;
    const int col0 = blockIdx.y * 128;
    const int rw = (wid & 3) * 32;
    const int cw = (wid >> 2) * 64;

    float acc[2][8][4];
#pragma unroll
    for (int m = 0; m < 2; m++)
#pragma unroll
        for (int n = 0; n < 8; n++)
#pragma unroll
            for (int c = 0; c < 4; c++) acc[m][n][c] = 0.f;

    for (int k0 = 0; k0 < K; k0 += 32) {
        const float* srcA = (k0 < K1) ? A : A2;
        const int koff = (k0 < K1) ? k0 : k0 - K1;
        const int ldx = (k0 < K1) ? lda : lda2;
#pragma unroll
        for (int i = 0; i < 4; i++) {
            int idx = tid + i * 256;
            int r = idx >> 3, f4 = idx & 7;
            float4 v = make_float4(0.f, 0.f, 0.f, 0.f);
            int row = row0 + r;
            if (row < M) v = *(const float4*)&srcA[(size_t)row * ldx + koff + f4 * 4];
            uint32_t* p = &As[r * LDK + f4 * 4];
            p[0] = tf32cvt(v.x); p[1] = tf32cvt(v.y);
            p[2] = tf32cvt(v.z); p[3] = tf32cvt(v.w);
        }
#pragma unroll
        for (int i = 0; i < 4; i++) {
            int idx = tid + i * 256;
            int r = idx >> 3, f4 = idx & 7;
            float4 v = *(const float4*)&Bt[(size_t)(col0 + r) * ldb + k0 + f4 * 4];
            uint32_t* p = &Bs[r * LDK + f4 * 4];
            p[0] = tf32cvt(v.x); p[1] = tf32cvt(v.y);
            p[2] = tf32cvt(v.z); p[3] = tf32cvt(v.w);
        }
        __syncthreads();
#pragma unroll
        for (int kk = 0; kk < 32; kk += 8) {
            uint32_t af[2][4];
#pragma unroll
            for (int m = 0; m < 2; m++) {
                int base = (rw + m * 16 + lr) * LDK + kk + lc;
                af[m][0] = As[base];
                af[m][1] = As[base + 8 * LDK];
                af[m][2] = As[base + 4];
                af[m][3] = As[base + 8 * LDK + 4];
            }
            uint32_t bf[8][2];
#pragma unroll
            for (int n = 0; n < 8; n++) {
                int base = (cw + n * 8 + lr) * LDK + kk + lc;
                bf[n][0] = Bs[base];
                bf[n][1] = Bs[base + 4];
            }
#pragma unroll
            for (int m = 0; m < 2; m++)
#pragma unroll
                for (int n = 0; n < 8; n++) mma8(acc[m][n], af[m], bf[n]);
        }
        __syncthreads();
    }

    if (flags & 4) {
        // GRU finalize: n_h = acc + bias; h_new = (1-z)*tanh(n_i + r*n_h) + z*h_old
        float escale = (epsidx >= 0) ? (1.f + eps[epsidx]) : 0.f;
#pragma unroll
        for (int m = 0; m < 2; m++) {
#pragma unroll
            for (int n = 0; n < 8; n++) {
                int col = cw + n * 8 + lc * 2;
                float b0 = bias[col], b1 = bias[col + 1];
#pragma unroll
                for (int half = 0; half < 2; half++) {
                    int row = row0 + rw + m * 16 + lr + half * 8;
                    if (row < M) {
                        float nh0 = acc[m][n][half * 2] + b0;
                        float nh1 = acc[m][n][half * 2 + 1] + b1;
                        const float* gr = &gates[(size_t)row * 384];
                        float2 rr = *(const float2*)&gr[col];
                        float2 zz = *(const float2*)&gr[col + 128];
                        float2 ni = *(const float2*)&gr[col + 256];
                        float* hp = &O[(size_t)row * ldo + col];
                        float2 hv = *(float2*)hp;
                        float r0 = sigf(rr.x), z0 = sigf(zz.x);
                        float nn0 = tanhf(ni.x + r0 * nh0);
                        float h0 = (1.f - z0) * nn0 + z0 * hv.x;
                        float r1 = sigf(rr.y), z1 = sigf(zz.y);
                        float nn1 = tanhf(ni.y + r1 * nh1);
                        float h1 = (1.f - z1) * nn1 + z1 * hv.y;
                        float2 ho = {h0, h1};
                        *(float2*)hp = ho;
                        if (epsidx >= 0) {
                            float2 ao = {escale * h0, escale * h1};
                            *(float2*)&aggw[(size_t)row * 128 + col] = ao;
                        }
                    }
                }
            }
        }
        return;
    }

#pragma unroll
    for (int m = 0; m < 2; m++) {
#pragma unroll
        for (int n = 0; n < 8; n++) {
            int col = col0 + cw + n * 8 + lc * 2;
            float b0 = bias[col], b1 = bias[col + 1];
            int r1 = row0 + rw + m * 16 + lr;
            int r2 = r1 + 8;
            if (r1 < M) {
                float v0 = acc[m][n][0] + b0, v1 = acc[m][n][1] + b1;
                float* op = &O[(size_t)r1 * ldo + col];
                if (flags & 2) { v0 += op[0]; v1 += op[1]; }
                if (flags & 1) { v0 = fmaxf(v0, 0.f); v1 = fmaxf(v1, 0.f); }
                float2 ov = {v0, v1};
                *(float2*)op = ov;
            }
            if (r2 < M) {
                float v0 = acc[m][n][2] + b0, v1 = acc[m][n][3] + b1;
                float* op = &O[(size_t)r2 * ldo + col];
                if (flags & 2) { v0 += op[0]; v1 += op[1]; }
                if (flags & 1) { v0 = fmaxf(v0, 0.f); v1 = fmaxf(v1, 0.f); }
                float2 ov = {v0, v1};
                *(float2*)op = ov;
            }
        }
    }
}

// ---------------- fused 2-layer MLP core (shared by k_mlp2 / k_mlp2s) ----------------
__device__ __forceinline__ void mlp2_core(
    const float* __restrict__ A, int lda,
    const float* __restrict__ W1t, const float* __restrict__ b1,
    const float* __restrict__ W2t, int M, int row0,
    uint32_t* As, uint32_t* Bs, uint32_t* As2, float acc[2][8][4])
{
    const int tid = threadIdx.x;
    const int wid = tid >> 5, lane = tid & 31;
    const int lr = lane >> 2, lc = lane & 3;
    const int rw = (wid & 3) * 32;
    const int cw = (wid >> 2) * 64;

#pragma unroll
    for (int m = 0; m < 2; m++)
#pragma unroll
        for (int n = 0; n < 8; n++)
#pragma unroll
            for (int c = 0; c < 4; c++) acc[m][n][c] = 0.f;

    for (int k0 = 0; k0 < 128; k0 += 32) {
#pragma unroll
        for (int i = 0; i < 4; i++) {
            int idx = tid + i * 256;
            int r = idx >> 3, f4 = idx & 7;
            float4 v = make_float4(0.f, 0.f, 0.f, 0.f);
            int row = row0 + r;
            if (row < M) v = *(const float4*)&A[(size_t)row * lda + k0 + f4 * 4];
            uint32_t* p = &As[r * LDK + f4 * 4];
            p[0] = tf32cvt(v.x); p[1] = tf32cvt(v.y);
            p[2] = tf32cvt(v.z); p[3] = tf32cvt(v.w);
        }
#pragma unroll
        for (int i = 0; i < 4; i++) {
            int idx = tid + i * 256;
            int r = idx >> 3, f4 = idx & 7;
            float4 v = *(const float4*)&W1t[(size_t)r * 128 + k0 + f4 * 4];
            uint32_t* p = &Bs[r * LDK + f4 * 4];
            p[0] = tf32cvt(v.x); p[1] = tf32cvt(v.y);
            p[2] = tf32cvt(v.z); p[3] = tf32cvt(v.w);
        }
        __syncthreads();
#pragma unroll
        for (int kk = 0; kk < 32; kk += 8) {
            uint32_t af[2][4];
#pragma unroll
            for (int m = 0; m < 2; m++) {
                int base = (rw + m * 16 + lr) * LDK + kk + lc;
                af[m][0] = As[base];
                af[m][1] = As[base + 8 * LDK];
                af[m][2] = As[base + 4];
                af[m][3] = As[base + 8 * LDK + 4];
            }
            uint32_t bf[8][2];
#pragma unroll
            for (int n = 0; n < 8; n++) {
                int base = (cw + n * 8 + lr) * LDK + kk + lc;
                bf[n][0] = Bs[base];
                bf[n][1] = Bs[base + 4];
            }
#pragma unroll
            for (int m = 0; m < 2; m++)
#pragma unroll
                for (int n = 0; n < 8; n++) mma8(acc[m][n], af[m], bf[n]);
        }
        __syncthreads();
    }

    // mid epilogue: relu(+b1) -> As2
#pragma unroll
    for (int m = 0; m < 2; m++) {
#pragma unroll
        for (int n = 0; n < 8; n++) {
            int col = cw + n * 8 + lc * 2;
            float b0 = b1[col], bb1 = b1[col + 1];
            int r1 = rw + m * 16 + lr, r2 = r1 + 8;
            As2[r1 * LD2 + col]     = tf32cvt(fmaxf(acc[m][n][0] + b0, 0.f));
            As2[r1 * LD2 + col + 1] = tf32cvt(fmaxf(acc[m][n][1] + bb1, 0.f));
            As2[r2 * LD2 + col]     = tf32cvt(fmaxf(acc[m][n][2] + b0, 0.f));
            As2[r2 * LD2 + col + 1] = tf32cvt(fmaxf(acc[m][n][3] + bb1, 0.f));
            acc[m][n][0] = acc[m][n][1] = acc[m][n][2] = acc[m][n][3] = 0.f;
        }
    }
    __syncthreads();

    // GEMM2: As2 @ W2t
    for (int k0 = 0; k0 < 128; k0 += 32) {
#pragma unroll
        for (int i = 0; i < 4; i++) {
            int idx = tid + i * 256;
            int r = idx >> 3, f4 = idx & 7;
            float4 v = *(const float4*)&W2t[(size_t)r * 128 + k0 + f4 * 4];
            uint32_t* p = &Bs[r * LDK + f4 * 4];
            p[0] = tf32cvt(v.x); p[1] = tf32cvt(v.y);
            p[2] = tf32cvt(v.z); p[3] = tf32cvt(v.w);
        }
        __syncthreads();
#pragma unroll
        for (int kk = 0; kk < 32; kk += 8) {
            uint32_t af[2][4];
#pragma unroll
            for (int m = 0; m < 2; m++) {
                int base = (rw + m * 16 + lr) * LD2 + k0 + kk + lc;
                af[m][0] = As2[base];
                af[m][1] = As2[base + 8 * LD2];
                af[m][2] = As2[base + 4];
                af[m][3] = As2[base + 8 * LD2 + 4];
            }
            uint32_t bf[8][2];
#pragma unroll
            for (int n = 0; n < 8; n++) {
                int base = (cw + n * 8 + lr) * LDK + kk + lc;
                bf[n][0] = Bs[base];
                bf[n][1] = Bs[base + 4];
            }
#pragma unroll
            for (int m = 0; m < 2; m++)
#pragma unroll
                for (int n = 0; n < 8; n++) mma8(acc[m][n], af[m], bf[n]);
        }
        __syncthreads();
    }
}

// GIN MLP: plain output
__global__ void __launch_bounds__(256) k_mlp2(
    const float* __restrict__ A, int lda,
    const float* __restrict__ W1t, const float* __restrict__ b1,
    const float* __restrict__ W2t, const float* __restrict__ b2,
    float* __restrict__ O, int ldo, int M)
{
    extern __shared__ uint32_t sm[];
    uint32_t* As  = sm;
    uint32_t* Bs  = sm + 128 * LDK;
    uint32_t* As2 = sm + 2 * 128 * LDK;
    float acc[2][8][4];
    const int row0 = blockIdx.x * 128;
    mlp2_core(A, lda, W1t, b1, W2t, M, row0, As, Bs, As2, acc);

    const int tid = threadIdx.x;
    const int wid = tid >> 5, lane = tid & 31;
    const int lr = lane >> 2, lc = lane & 3;
    const int rw = (wid & 3) * 32, cw = (wid >> 2) * 64;
#pragma unroll
    for (int m = 0; m < 2; m++) {
#pragma unroll
        for (int n = 0; n < 8; n++) {
            int col = cw + n * 8 + lc * 2;
            float b0 = b2[col], bb1 = b2[col + 1];
            int r1 = row0 + rw + m * 16 + lr;
            int r2 = r1 + 8;
            if (r1 < M) {
                float2 ov = {acc[m][n][0] + b0, acc[m][n][1] + bb1};
                *(float2*)&O[(size_t)r1 * ldo + col] = ov;
            }
            if (r2 < M) {
                float2 ov = {acc[m][n][2] + b0, acc[m][n][3] + bb1};
                *(float2*)&O[(size_t)r2 * ldo + col] = ov;
            }
        }
    }
}

// edge MLP + fused GINE scatter: edge_new never hits DRAM
__global__ void __launch_bounds__(256) k_mlp2s(
    const float* __restrict__ A, int lda,
    const float* __restrict__ W1t, const float* __restrict__ b1,
    const float* __restrict__ W2t, const float* __restrict__ b2,
    const int* __restrict__ src, const int* __restrict__ dst,
    const float* __restrict__ node, float* __restrict__ agg, int M)
{
    extern __shared__ uint32_t sm[];
    uint32_t* As  = sm;
    uint32_t* Bs  = sm + 128 * LDK;
    uint32_t* As2 = sm + 2 * 128 * LDK;
    float acc[2][8][4];
    const int row0 = blockIdx.x * 128;
    mlp2_core(A, lda, W1t, b1, W2t, M, row0, As, Bs, As2, acc);

    const int tid = threadIdx.x;
    const int wid = tid >> 5, lane = tid & 31;
    const int lr = lane >> 2, lc = lane & 3;
    const int rw = (wid & 3) * 32, cw = (wid >> 2) * 64;
#pragma unroll
    for (int m = 0; m < 2; m++) {
#pragma unroll
        for (int n = 0; n < 8; n++) {
            int col = cw + n * 8 + lc * 2;
            float b0 = b2[col], bb1 = b2[col + 1];
#pragma unroll
            for (int half = 0; half < 2; half++) {
                int e = row0 + rw + m * 16 + lr + half * 8;
                if (e < M) {
                    float v0 = acc[m][n][half * 2] + b0;
                    float v1 = acc[m][n][half * 2 + 1] + bb1;
                    int s = src[e], d = dst[e];
                    float2 nv = *(const float2*)&node[(size_t)s * 128 + col];
                    float m0 = fmaxf(nv.x + v0, 0.f);
                    float m1 = fmaxf(nv.y + v1, 0.f);
                    redv2(&agg[(size_t)d * 128 + col], m0, m1);
                }
            }
        }
    }
}

// ---------------- FFMA2 GEMM for embeddings; mode 0: node(+agg init), mode 1: edge(+scatter)
__global__ void __launch_bounds__(256) k_gemm(
    const float* __restrict__ A, int lda,
    const float* __restrict__ W, int ldw,
    const float* __restrict__ bias,
    float* __restrict__ O, int M, int K, int mode,
    const float* __restrict__ eps, float* __restrict__ agg,
    const int* __restrict__ src, const int* __restrict__ dst,
    const float* __restrict__ node)
{
    __shared__ __align__(16) unsigned long long Asd[16][65];
    __shared__ __align__(16) float Ws[16][128];
    const int tid = threadIdx.x;
    const int tx = tid & 31, ty = tid >> 5;
    const int row0 = blockIdx.x * 64;

    unsigned long long acc[8][2];
#pragma unroll
    for (int r = 0; r < 8; r++) { acc[r][0] = 0ULL; acc[r][1] = 0ULL; }

    for (int k0 = 0; k0 < K; k0 += 16) {
#pragma unroll
        for (int i = tid; i < 1024; i += 256) {
            int r = i >> 4, k = i & 15;
            int row = row0 + r, kk = k0 + k;
            float v = (row < M && kk < K) ? A[(size_t)row * lda + kk] : 0.f;
            U64F2 p; p.f.x = v; p.f.y = v;
            Asd[k][r] = p.u;
        }
#pragma unroll
        for (int i = tid; i < 2048; i += 256) {
            int k = i >> 7, j = i & 127;
            int kk = k0 + k;
            Ws[k][j] = (kk < K) ? W[(size_t)kk * ldw + j] : 0.f;
        }
        __syncthreads();
#pragma unroll
        for (int k = 0; k < 16; k++) {
            U128 w; w.v = *(const float4*)&Ws[k][tx << 2];
#pragma unroll
            for (int r = 0; r < 8; r++) {
                unsigned long long a = Asd[k][(ty << 3) + r];
                acc[r][0] = fma2(a, w.u[0], acc[r][0]);
                acc[r][1] = fma2(a, w.u[1], acc[r][1]);
            }
        }
        __syncthreads();
    }
    const int col = tx << 2;
    float4 b4 = *(const float4*)&bias[col];
    float escale = (mode == 0) ? (1.f + eps[0]) : 0.f;
#pragma unroll
    for (int r = 0; r < 8; r++) {
        int row = row0 + (ty << 3) + r;
        if (row < M) {
            U64F2 p0, p1; p0.u = acc[r][0]; p1.u = acc[r][1];
            float v0 = p0.f.x + b4.x, v1 = p0.f.y + b4.y;
            float v2 = p1.f.x + b4.z, v3 = p1.f.y + b4.w;
            float4 ov = {v0, v1, v2, v3};
            *(float4*)&O[(size_t)row * 128 + col] = ov;
            if (mode == 0) {
                float4 av = {escale * v0, escale * v1, escale * v2, escale * v3};
                *(float4*)&agg[(size_t)row * 128 + col] = av;
            } else {
                int s = src[row], d = dst[row];
                float4 nv = *(const float4*)&node[(size_t)s * 128 + col];
                redv4(&agg[(size_t)d * 128 + col],
                      fmaxf(nv.x + v0, 0.f), fmaxf(nv.y + v1, 0.f),
                      fmaxf(nv.z + v2, 0.f), fmaxf(nv.w + v3, 0.f));
            }
        }
    }
}

// ---------------- prep ----------------
__global__ void k_prep(const float* __restrict__ gin1, const float* __restrict__ gin2,
                       const float* __restrict__ em1, const float* __restrict__ em2,
                       const float* __restrict__ fcw1,
                       const float* __restrict__ gwih, const float* __restrict__ gwhh,
                       const float* __restrict__ gbih, const float* __restrict__ gbhh,
                       const float* __restrict__ lwih, const float* __restrict__ lwhh,
                       const float* __restrict__ lbih, const float* __restrict__ lbhh,
                       float* __restrict__ tg1, float* __restrict__ tg2,
                       float* __restrict__ te1, float* __restrict__ te2,
                       float* __restrict__ tf1,
                       float* __restrict__ tgall, float* __restrict__ tgallb,
                       float* __restrict__ tlw, float* __restrict__ tlb)
{
    int i = blockIdx.x * blockDim.x + threadIdx.x;
    if (i < 131072) {
        int m = i >> 14, j = i & 16383;
        int r = j >> 7, c = j & 127;
        int l = m & 1, which = m >> 1;
        const float* s = (which == 0) ? gin1 : (which == 1) ? gin2 : (which == 2) ? em1 : em2;
        float* d = (which == 0) ? tg1 : (which == 1) ? tg2 : (which == 2) ? te1 : te2;
        d[(size_t)l * 16384 + c * 128 + r] = s[(size_t)l * 16384 + j];
    } else if (i < 163840) {
        int j = i - 131072;
        int r = j >> 7, c = j & 127;
        tf1[(size_t)c * 256 + r] = fcw1[j];
    } else if (i < 262144) {
        int j = i - 163840;                 // t_gall [384][256]
        int c = j >> 8, k = j & 255;
        tgall[j] = (k < 128) ? gwih[c * 128 + k]
                             : ((c < 256) ? gwhh[c * 128 + (k - 128)] : 0.f);
    } else if (i < 458752) {
        int j = i - 262144;                 // t_lw [512][384]
        int c = j / 384, k = j % 384;
        tlw[j] = (k < 256) ? lwih[c * 256 + k] : lwhh[c * 128 + (k - 256)];
    } else if (i < 459136) {
        int j = i - 458752;                 // t_gallb [384]
        tgallb[j] = (j < 256) ? gbih[j] + gbhh[j] : gbih[j];
    } else if (i < 459648) {
        int j = i - 459136;
        tlb[j] = lbih[j] + lbhh[j];
    }
}

__global__ void k_zero3(float4* __restrict__ a, int na, float4* __restrict__ b, int nb,
                        float4* __restrict__ c, int nc)
{
    int i = blockIdx.x * blockDim.x + threadIdx.x;
    float4 z = make_float4(0.f, 0.f, 0.f, 0.f);
    if (i < na) a[i] = z;
    if (i < nb) b[i] = z;
    if (i < nc) c[i] = z;
}

__device__ __forceinline__ void lstm1(float i_, float f_, float g_, float o_,
                                      float& c, float& hh) {
    c = sigf(f_) * c + sigf(i_) * tanhf(g_);
    hh = sigf(o_) * tanhf(c);
}

__global__ void k_lstm(const float* __restrict__ gl, float* __restrict__ hl,
                       float* __restrict__ cl, int nw)
{
    int idx = blockIdx.x * blockDim.x + threadIdx.x;
    if (idx >= nw) return;
    int g = idx >> 5, j = (idx & 31) * 4;
    const float* gr = &gl[(size_t)g * 512];
    float4 i_ = *(const float4*)&gr[j];
    float4 f_ = *(const float4*)&gr[j + 128];
    float4 g_ = *(const float4*)&gr[j + 256];
    float4 o_ = *(const float4*)&gr[j + 384];
    float4* cp = (float4*)&cl[(size_t)g * 128 + j];
    float4* hp = (float4*)&hl[(size_t)g * 128 + j];
    float4 c = *cp, hh;
    lstm1(i_.x, f_.x, g_.x, o_.x, c.x, hh.x);
    lstm1(i_.y, f_.y, g_.y, o_.y, c.y, hh.y);
    lstm1(i_.z, f_.z, g_.z, o_.z, c.z, hh.z);
    lstm1(i_.w, f_.w, g_.w, o_.w, c.w, hh.w);
    *cp = c;
    *hp = hh;
}

__global__ void k_set2set(const int* __restrict__ batch, const float* __restrict__ node,
                          const float* __restrict__ hl, float* __restrict__ qs,
                          int N, int G)
{
    int warp = (blockIdx.x * blockDim.x + threadIdx.x) >> 5;
    if (warp >= G) return;
    const int lane = threadIdx.x & 31;
    const int g = warp;

    int lo = 0, hi = N;
    while (lo < hi) { int mid = (lo + hi) >> 1; if (batch[mid] < g) lo = mid + 1; else hi = mid; }
    const int s0 = lo;
    hi = N;
    while (lo < hi) { int mid = (lo + hi) >> 1; if (batch[mid] < g + 1) lo = mid + 1; else hi = mid; }
    const int s1 = lo;

    float4 qv = *(const float4*)&hl[(size_t)g * H + lane * 4];

    float mx = -INFINITY, den = 0.f;
    float4 racc = make_float4(0.f, 0.f, 0.f, 0.f);
    for (int i = s0; i < s1; i++) {
        float4 nv = *(const float4*)&node[(size_t)i * H + lane * 4];
        float d = nv.x * qv.x + nv.y * qv.y + nv.z * qv.z + nv.w * qv.w;
#pragma unroll
        for (int o = 16; o; o >>= 1) d += __shfl_xor_sync(0xffffffffu, d, o);
        float nm = fmaxf(mx, d);
        float sc = expf(mx - nm);
        float ex = expf(d - nm);
        den = den * sc + ex;
        racc.x = racc.x * sc + ex * nv.x;
        racc.y = racc.y * sc + ex * nv.y;
        racc.z = racc.z * sc + ex * nv.z;
        racc.w = racc.w * sc + ex * nv.w;
        mx = nm;
    }
    float inv = 1.f / fmaxf(den, 1e-9f);
    float* qrow = &qs[(size_t)g * 2 * H];
    *(float4*)&qrow[lane * 4] = qv;
    float4 rv = {racc.x * inv, racc.y * inv, racc.z * inv, racc.w * inv};
    *(float4*)&qrow[H + lane * 4] = rv;
}

__global__ void k_fc2(const float* __restrict__ fcin, const float* __restrict__ w2,
                      const float* __restrict__ b2, float* __restrict__ out, int G)
{
    int tid = blockIdx.x * blockDim.x + threadIdx.x;
    int g = tid >> 5;
    if (g >= G) return;
    int lane = tid & 31;
    float s = 0.f;
#pragma unroll
    for (int t = 0; t < 4; t++) {
        int j = lane + t * 32;
        s += fcin[(size_t)g * H + j] * w2[j];
    }
#pragma unroll
    for (int off = 16; off; off >>= 1) s += __shfl_xor_sync(0xffffffffu, s, off);
    if (lane == 0) out[g] = s + b2[0];
}

// ---------------- host launcher ----------------
extern "C" void kernel_launch(void* const* d_in, const int* in_sizes, int n_in,
                              void* d_out, int out_size)
{
    const float* x       = (const float*)d_in[0];
    const float* eattr   = (const float*)d_in[1];
    const int*   eindex  = (const int*)d_in[2];
    const int*   batch   = (const int*)d_in[3];
    const float* node_w  = (const float*)d_in[4];
    const float* node_b  = (const float*)d_in[5];
    const float* edge_w  = (const float*)d_in[6];
    const float* edge_b  = (const float*)d_in[7];
    const float* eps     = (const float*)d_in[8];
    const float* gin_w1  = (const float*)d_in[9];
    const float* gin_b1  = (const float*)d_in[10];
    const float* gin_w2  = (const float*)d_in[11];
    const float* gin_b2  = (const float*)d_in[12];
    const float* em_w1   = (const float*)d_in[13];
    const float* em_b1   = (const float*)d_in[14];
    const float* em_w2   = (const float*)d_in[15];
    const float* em_b2   = (const float*)d_in[16];
    const float* gru_wih = (const float*)d_in[17];
    const float* gru_whh = (const float*)d_in[18];
    const float* gru_bih = (const float*)d_in[19];
    const float* gru_bhh = (const float*)d_in[20];
    const float* lstm_wih= (const float*)d_in[21];
    const float* lstm_whh= (const float*)d_in[22];
    const float* lstm_bih= (const float*)d_in[23];
    const float* lstm_bhh= (const float*)d_in[24];
    const float* fc_w1   = (const float*)d_in[25];
    const float* fc_b1   = (const float*)d_in[26];
    const float* fc_w2   = (const float*)d_in[27];
    const float* fc_b2   = (const float*)d_in[28];

    const int N = in_sizes[0] / 14;
    const int E = in_sizes[1] / 4;
    const int G = out_size;

    float *p_node, *p_edge, *p_agg, *p_m, *p_gates;
    float *p_qs, *p_hl, *p_cl, *p_gl, *p_fc;
    float *p_tg1, *p_tg2, *p_te1, *p_te2, *p_tf1, *p_tgall, *p_tgallb, *p_tlw, *p_tlb;
    cudaGetSymbolAddress((void**)&p_node, g_node);
    cudaGetSymbolAddress((void**)&p_edge, g_edge);
    cudaGetSymbolAddress((void**)&p_agg,  g_agg);
    cudaGetSymbolAddress((void**)&p_m,    g_m);
    cudaGetSymbolAddress((void**)&p_gates, g_gates);
    cudaGetSymbolAddress((void**)&p_qs,   g_qs);
    cudaGetSymbolAddress((void**)&p_hl,   g_hl);
    cudaGetSymbolAddress((void**)&p_cl,   g_cl);
    cudaGetSymbolAddress((void**)&p_gl,   g_gl);
    cudaGetSymbolAddress((void**)&p_fc,   g_fc);
    cudaGetSymbolAddress((void**)&p_tg1,  t_gin1);
    cudaGetSymbolAddress((void**)&p_tg2,  t_gin2);
    cudaGetSymbolAddress((void**)&p_te1,  t_em1);
    cudaGetSymbolAddress((void**)&p_te2,  t_em2);
    cudaGetSymbolAddress((void**)&p_tf1,  t_fc1);
    cudaGetSymbolAddress((void**)&p_tgall, t_gall);
    cudaGetSymbolAddress((void**)&p_tgallb, t_gallb);
    cudaGetSymbolAddress((void**)&p_tlw,  t_lw);
    cudaGetSymbolAddress((void**)&p_tlb,  t_lb);

    const int TB = 256;
    const int SMEM_MLP2 = (2 * 128 * LDK + 128 * LD2) * 4;
    cudaFuncSetAttribute(k_mlp2, cudaFuncAttributeMaxDynamicSharedMemorySize, SMEM_MLP2);
    cudaFuncSetAttribute(k_mlp2s, cudaFuncAttributeMaxDynamicSharedMemorySize, SMEM_MLP2);

    k_prep<<<CDIV(459648, TB), TB>>>(gin_w1, gin_w2, em_w1, em_w2, fc_w1,
                                     gru_wih, gru_whh, gru_bih, gru_bhh,
                                     lstm_wih, lstm_whh, lstm_bih, lstm_bhh,
                                     p_tg1, p_tg2, p_te1, p_te2, p_tf1,
                                     p_tgall, p_tgallb, p_tlw, p_tlb);

    const int* src = eindex;
    const int* dst = eindex + E;

    // node embed (writes node + agg=(1+eps0)*node), then edge embed (+scatter into agg)
    k_gemm<<<CDIV(N, 64), 256>>>(x, 14, node_w, 128, node_b, p_node, N, 14, 0,
                                 eps, p_agg, nullptr, nullptr, nullptr);
    k_gemm<<<CDIV(E, 64), 256>>>(eattr, 4, edge_w, 128, edge_b, p_edge, E, 4, 1,
                                 eps, p_agg, src, dst, p_node);

    const int NT = CDIV(N, 128), ET = CDIV(E, 128), GT = CDIV(G, 128);

    for (int l = 0; l < 2; l++) {
        // GIN MLP: m = MLP(agg)
        k_mlp2<<<NT, 256, SMEM_MLP2>>>(p_agg, 128, p_tg1 + l * 16384, gin_b1 + l * H,
                                       p_tg2 + l * 16384, gin_b2 + l * H, p_m, 128, N);
        // gates = [m|h] @ t_gall^T : r(pre-summed) | z(pre-summed) | n_i
        k_tmma<<<dim3(NT, 3), 256>>>(p_m, 128, 128, p_node, 128, p_tgall, 256, p_tgallb,
                                     p_gates, 384, N, 256, 0, nullptr, nullptr, nullptr, 0);
        // n_h GEMM + fused GRU update (writes node; if l==0 also agg=(1+eps1)*h)
        k_tmma<<<dim3(NT, 1), 256>>>(p_node, 128, 128, p_node, 128, gru_whh + 256 * 128, 128,
                                     gru_bhh + 256, p_node, 128, N, 128, 4,
                                     p_gates, p_agg, eps, (l == 0) ? 1 : -1);
        // layer-0 only: edge MLP with fused scatter (edge_1 never stored); layer-1 edge MLP is dead code
        if (l == 0) {
            k_mlp2s<<<ET, 256, SMEM_MLP2>>>(p_edge, 128, p_te1, em_b1, p_te2, em_b2,
                                            src, dst, p_node, p_agg, E);
        }
    }

    // Set2Set
    k_zero3<<<CDIV(G * 64, TB), TB>>>((float4*)p_qs, G * 64, (float4*)p_hl, G * 32, (float4*)p_cl, G * 32);
    for (int step = 0; step < 3; step++) {
        k_tmma<<<dim3(GT, 4), 256>>>(p_qs, 256, 256, p_hl, 128, p_tlw, 384, p_tlb,
                                     p_gl, 512, G, 384, 0, nullptr, nullptr, nullptr, 0);
        k_lstm<<<CDIV(G * 32, TB), TB>>>(p_gl, p_hl, p_cl, G * 32);
        k_set2set<<<CDIV(G * 32, TB), TB>>>(batch, p_node, p_hl, p_qs, N, G);
    }

    // final MLP
    k_tmma<<<dim3(GT, 1), 256>>>(p_qs, 256, 256, p_qs, 256, p_tf1, 256, fc_b1,
                                 p_fc, 128, G, 256, 1, nullptr, nullptr, nullptr, 0);
    k_fc2<<<CDIV(G * 32, TB), TB>>>(p_fc, fc_w2, fc_b2, (float*)d_out, G);
}

// round 8
// speedup vs baseline: 3.7653x; 1.0717x over previous
#include <cuda_runtime.h>
#include <math.h>
#include <stdint.h>

#define H 128
#define NMAX 100000
#define EMAX 200000
#define GMAX 4096

#define CDIV(a,b) (((a)+(b)-1)/(b))

// ---------------- scratch ----------------
__device__ __align__(16) float g_node[(size_t)NMAX*H];
__device__ __align__(16) float g_edge[(size_t)EMAX*H];
__device__ __align__(16) float g_agg [(size_t)NMAX*H];
__device__ __align__(16) float g_m   [(size_t)NMAX*H];
__device__ __align__(16) float g_gates[(size_t)NMAX*3*H];   // [N][384]: r | z | n_i
__device__ __align__(16) float g_qs  [(size_t)GMAX*2*H];
__device__ __align__(16) float g_hl  [(size_t)GMAX*H];
__device__ __align__(16) float g_cl  [(size_t)GMAX*H];
__device__ __align__(16) float g_gl  [(size_t)GMAX*4*H];
__device__ __align__(16) float g_fc  [(size_t)GMAX*H];
// prepared weights (tf32 bit patterns)
__device__ __align__(16) float t_gin1[2*H*H];
__device__ __align__(16) float t_gin2[2*H*H];
__device__ __align__(16) float t_em1 [2*H*H];
__device__ __align__(16) float t_em2 [2*H*H];
__device__ __align__(16) float t_fc1 [H*2*H];       // [128,256]
__device__ __align__(16) float t_gall[384*256];     // rz (wih|whh) + n_i (wih|0)
__device__ __align__(16) float t_gnh [H*H];         // gru_whh n-part [128,128]
__device__ __align__(16) float t_lw  [512*384];     // lwih(256)|lwhh(128)
__device__ __align__(16) float t_gallb[384];
__device__ __align__(16) float t_lb  [512];

// ---------------- helpers ----------------
__device__ __forceinline__ float sigf(float x) { return 1.f / (1.f + expf(-x)); }

__device__ __forceinline__ unsigned long long fma2(unsigned long long a,
                                                   unsigned long long b,
                                                   unsigned long long c) {
    unsigned long long d;
    asm("fma.rn.f32x2 %0, %1, %2, %3;" : "=l"(d) : "l"(a), "l"(b), "l"(c));
    return d;
}
union U64F2 { unsigned long long u; float2 f; };
union U128 { float4 v; unsigned long long u[2]; };

__device__ __forceinline__ uint32_t tf32cvt(float v) {
    uint32_t t;
    asm("cvt.rna.tf32.f32 %0, %1;" : "=r"(t) : "f"(v));
    return t;
}
__device__ __forceinline__ void mma8(float* c, const uint32_t* a, const uint32_t* b) {
    asm volatile(
        "mma.sync.aligned.m16n8k8.row.col.f32.tf32.tf32.f32 "
        "{%0,%1,%2,%3}, {%4,%5,%6,%7}, {%8,%9}, {%0,%1,%2,%3};"
        : "+f"(c[0]), "+f"(c[1]), "+f"(c[2]), "+f"(c[3])
        : "r"(a[0]), "r"(a[1]), "r"(a[2]), "r"(a[3]), "r"(b[0]), "r"(b[1]));
}
__device__ __forceinline__ void redv4(float* p, float a, float b, float c, float d) {
    asm volatile("red.global.add.v4.f32 [%0], {%1, %2, %3, %4};"
                 :: "l"(p), "f"(a), "f"(b), "f"(c), "f"(d) : "memory");
}
__device__ __forceinline__ void redv2(float* p, float a, float b) {
    asm volatile("red.global.add.v2.f32 [%0], {%1, %2};"
                 :: "l"(p), "f"(a), "f"(b) : "memory");
}
__device__ __forceinline__ void cpasync16(uint32_t saddr, const void* g) {
    asm volatile("cp.async.cg.shared.global [%0], [%1], 16;" :: "r"(saddr), "l"(g));
}

#define LDK 36
#define LD2 132

// mma inner loop on staged tiles (As, Bs in LDK layout)
__device__ __forceinline__ void mma_block(const uint32_t* As, const uint32_t* Bs,
                                          float acc[2][8][4], int rw, int cw,
                                          int lr, int lc)
{
#pragma unroll
    for (int kk = 0; kk < 32; kk += 8) {
        uint32_t af[2][4];
#pragma unroll
        for (int m = 0; m < 2; m++) {
            int base = (rw + m * 16 + lr) * LDK + kk + lc;
            af[m][0] = As[base];
            af[m][1] = As[base + 8 * LDK];
            af[m][2] = As[base + 4];
            af[m][3] = As[base + 8 * LDK + 4];
        }
        uint32_t bf[8][2];
#pragma unroll
        for (int n = 0; n < 8; n++) {
            int base = (cw + n * 8 + lr) * LDK + kk + lc;
            bf[n][0] = Bs[base];
            bf[n][1] = Bs[base + 4];
        }
#pragma unroll
        for (int m = 0; m < 2; m++)
#pragma unroll
            for (int n = 0; n < 8; n++) mma8(acc[m][n], af[m], bf[n]);
    }
}

// ---------------- k_tmma: O[M, col0+128] = act(concat(A,A2)[M,K] @ Bt^T + bias) ----------------
// Bt holds tf32 bit patterns. flags: bit0 relu, bit1 accumulate, bit2 GRU-finalize.
__global__ void __launch_bounds__(256, 2) k_tmma(
    const float* __restrict__ A, int lda, int K1,
    const float* __restrict__ A2, int lda2,
    const float* __restrict__ Bt, int ldb,
    const float* __restrict__ bias,
    float* __restrict__ O, int ldo,
    int M, int K, int flags,
    const float* __restrict__ gates, float* __restrict__ aggw,
    const float* __restrict__ eps, int epsidx)
{
    __shared__ uint32_t As[128 * LDK];
    __shared__ uint32_t Bs[128 * LDK];
    const int tid = threadIdx.x;
    const int wid = tid >> 5, lane = tid & 31;
    const int lr = lane >> 2, lc = lane & 3;
    const int row0 = blockIdx.x * 128;
    const int col0 = blockIdx.y * 128;
    const int rw = (wid & 3) * 32;
    const int cw = (wid >> 2) * 64;
    const int r_ = tid >> 3, f4_ = tid & 7;   // staging coords (each thread: 4 rows stride 32)

    float acc[2][8][4];
#pragma unroll
    for (int m = 0; m < 2; m++)
#pragma unroll
        for (int n = 0; n < 8; n++)
#pragma unroll
            for (int c = 0; c < 4; c++) acc[m][n][c] = 0.f;

    float4 aR[4];
    // prologue: prefetch A block 0
    {
        const float* srcA = (0 < K1) ? A : A2;
        int ldx = (0 < K1) ? lda : lda2;
#pragma unroll
        for (int i = 0; i < 4; i++) {
            int r = r_ + i * 32;
            int row = row0 + r;
            aR[i] = make_float4(0.f, 0.f, 0.f, 0.f);
            if (row < M) aR[i] = *(const float4*)&srcA[(size_t)row * ldx + f4_ * 4];
        }
    }

    for (int k0 = 0; k0 < K; k0 += 32) {
        // B: raw 16B async copies (already tf32)
#pragma unroll
        for (int i = 0; i < 4; i++) {
            int r = r_ + i * 32;
            uint32_t sa = (uint32_t)__cvta_generic_to_shared(&Bs[r * LDK + f4_ * 4]);
            cpasync16(sa, &Bt[(size_t)(col0 + r) * ldb + k0 + f4_ * 4]);
        }
        asm volatile("cp.async.commit_group;" ::: "memory");
        // A: cvt + STS from prefetched regs
#pragma unroll
        for (int i = 0; i < 4; i++) {
            int r = r_ + i * 32;
            uint32_t* p = &As[r * LDK + f4_ * 4];
            p[0] = tf32cvt(aR[i].x); p[1] = tf32cvt(aR[i].y);
            p[2] = tf32cvt(aR[i].z); p[3] = tf32cvt(aR[i].w);
        }
        // prefetch next A block
        int kn = k0 + 32;
        if (kn < K) {
            const float* srcA = (kn < K1) ? A : A2;
            int koff = (kn < K1) ? kn : kn - K1;
            int ldx = (kn < K1) ? lda : lda2;
#pragma unroll
            for (int i = 0; i < 4; i++) {
                int r = r_ + i * 32;
                int row = row0 + r;
                aR[i] = make_float4(0.f, 0.f, 0.f, 0.f);
                if (row < M) aR[i] = *(const float4*)&srcA[(size_t)row * ldx + koff + f4_ * 4];
            }
        }
        asm volatile("cp.async.wait_group 0;" ::: "memory");
        __syncthreads();
        mma_block(As, Bs, acc, rw, cw, lr, lc);
        __syncthreads();
    }

    if (flags & 4) {
        float escale = (epsidx >= 0) ? (1.f + eps[epsidx]) : 0.f;
#pragma unroll
        for (int m = 0; m < 2; m++) {
#pragma unroll
            for (int n = 0; n < 8; n++) {
                int col = cw + n * 8 + lc * 2;
                float b0 = bias[col], b1 = bias[col + 1];
#pragma unroll
                for (int half = 0; half < 2; half++) {
                    int row = row0 + rw + m * 16 + lr + half * 8;
                    if (row < M) {
                        float nh0 = acc[m][n][half * 2] + b0;
                        float nh1 = acc[m][n][half * 2 + 1] + b1;
                        const float* gr = &gates[(size_t)row * 384];
                        float2 rr = *(const float2*)&gr[col];
                        float2 zz = *(const float2*)&gr[col + 128];
                        float2 ni = *(const float2*)&gr[col + 256];
                        float* hp = &O[(size_t)row * ldo + col];
                        float2 hv = *(float2*)hp;
                        float r0 = sigf(rr.x), z0 = sigf(zz.x);
                        float nn0 = tanhf(ni.x + r0 * nh0);
                        float h0 = (1.f - z0) * nn0 + z0 * hv.x;
                        float r1 = sigf(rr.y), z1 = sigf(zz.y);
                        float nn1 = tanhf(ni.y + r1 * nh1);
                        float h1 = (1.f - z1) * nn1 + z1 * hv.y;
                        float2 ho = {h0, h1};
                        *(float2*)hp = ho;
                        if (epsidx >= 0) {
                            float2 ao = {escale * h0, escale * h1};
                            *(float2*)&aggw[(size_t)row * 128 + col] = ao;
                        }
                    }
                }
            }
        }
        return;
    }

#pragma unroll
    for (int m = 0; m < 2; m++) {
#pragma unroll
        for (int n = 0; n < 8; n++) {
            int col = col0 + cw + n * 8 + lc * 2;
            float b0 = bias[col], b1 = bias[col + 1];
            int r1 = row0 + rw + m * 16 + lr;
            int r2 = r1 + 8;
            if (r1 < M) {
                float v0 = acc[m][n][0] + b0, v1 = acc[m][n][1] + b1;
                float* op = &O[(size_t)r1 * ldo + col];
                if (flags & 2) { v0 += op[0]; v1 += op[1]; }
                if (flags & 1) { v0 = fmaxf(v0, 0.f); v1 = fmaxf(v1, 0.f); }
                float2 ov = {v0, v1};
                *(float2*)op = ov;
            }
            if (r2 < M) {
                float v0 = acc[m][n][2] + b0, v1 = acc[m][n][3] + b1;
                float* op = &O[(size_t)r2 * ldo + col];
                if (flags & 2) { v0 += op[0]; v1 += op[1]; }
                if (flags & 1) { v0 = fmaxf(v0, 0.f); v1 = fmaxf(v1, 0.f); }
                float2 ov = {v0, v1};
                *(float2*)op = ov;
            }
        }
    }
}

// ---------------- fused 2-layer MLP core ----------------
__device__ __forceinline__ void mlp2_core(
    const float* __restrict__ A, int lda,
    const float* __restrict__ W1t, const float* __restrict__ b1,
    const float* __restrict__ W2t, int M, int row0,
    uint32_t* As, uint32_t* Bs, uint32_t* As2, float acc[2][8][4])
{
    const int tid = threadIdx.x;
    const int wid = tid >> 5, lane = tid & 31;
    const int lr = lane >> 2, lc = lane & 3;
    const int rw = (wid & 3) * 32;
    const int cw = (wid >> 2) * 64;
    const int r_ = tid >> 3, f4_ = tid & 7;

#pragma unroll
    for (int m = 0; m < 2; m++)
#pragma unroll
        for (int n = 0; n < 8; n++)
#pragma unroll
            for (int c = 0; c < 4; c++) acc[m][n][c] = 0.f;

    float4 aR[4];
#pragma unroll
    for (int i = 0; i < 4; i++) {
        int row = row0 + r_ + i * 32;
        aR[i] = make_float4(0.f, 0.f, 0.f, 0.f);
        if (row < M) aR[i] = *(const float4*)&A[(size_t)row * lda + f4_ * 4];
    }

    // GEMM1
    for (int k0 = 0; k0 < 128; k0 += 32) {
#pragma unroll
        for (int i = 0; i < 4; i++) {
            int r = r_ + i * 32;
            uint32_t sa = (uint32_t)__cvta_generic_to_shared(&Bs[r * LDK + f4_ * 4]);
            cpasync16(sa, &W1t[(size_t)r * 128 + k0 + f4_ * 4]);
        }
        asm volatile("cp.async.commit_group;" ::: "memory");
#pragma unroll
        for (int i = 0; i < 4; i++) {
            int r = r_ + i * 32;
            uint32_t* p = &As[r * LDK + f4_ * 4];
            p[0] = tf32cvt(aR[i].x); p[1] = tf32cvt(aR[i].y);
            p[2] = tf32cvt(aR[i].z); p[3] = tf32cvt(aR[i].w);
        }
        int kn = k0 + 32;
        if (kn < 128) {
#pragma unroll
            for (int i = 0; i < 4; i++) {
                int row = row0 + r_ + i * 32;
                aR[i] = make_float4(0.f, 0.f, 0.f, 0.f);
                if (row < M) aR[i] = *(const float4*)&A[(size_t)row * lda + kn + f4_ * 4];
            }
        }
        asm volatile("cp.async.wait_group 0;" ::: "memory");
        __syncthreads();
        mma_block(As, Bs, acc, rw, cw, lr, lc);
        __syncthreads();
    }

    // mid epilogue: relu(+b1) -> As2
#pragma unroll
    for (int m = 0; m < 2; m++) {
#pragma unroll
        for (int n = 0; n < 8; n++) {
            int col = cw + n * 8 + lc * 2;
            float b0 = b1[col], bb1 = b1[col + 1];
            int r1 = rw + m * 16 + lr, r2 = r1 + 8;
            As2[r1 * LD2 + col]     = tf32cvt(fmaxf(acc[m][n][0] + b0, 0.f));
            As2[r1 * LD2 + col + 1] = tf32cvt(fmaxf(acc[m][n][1] + bb1, 0.f));
            As2[r2 * LD2 + col]     = tf32cvt(fmaxf(acc[m][n][2] + b0, 0.f));
            As2[r2 * LD2 + col + 1] = tf32cvt(fmaxf(acc[m][n][3] + bb1, 0.f));
            acc[m][n][0] = acc[m][n][1] = acc[m][n][2] = acc[m][n][3] = 0.f;
        }
    }
    __syncthreads();

    // GEMM2: As2 @ W2t  (A in smem; B async per block)
    for (int k0 = 0; k0 < 128; k0 += 32) {
#pragma unroll
        for (int i = 0; i < 4; i++) {
            int r = r_ + i * 32;
            uint32_t sa = (uint32_t)__cvta_generic_to_shared(&Bs[r * LDK + f4_ * 4]);
            cpasync16(sa, &W2t[(size_t)r * 128 + k0 + f4_ * 4]);
        }
        asm volatile("cp.async.commit_group;" ::: "memory");
        asm volatile("cp.async.wait_group 0;" ::: "memory");
        __syncthreads();
#pragma unroll
        for (int kk = 0; kk < 32; kk += 8) {
            uint32_t af[2][4];
#pragma unroll
            for (int m = 0; m < 2; m++) {
                int base = (rw + m * 16 + lr) * LD2 + k0 + kk + lc;
                af[m][0] = As2[base];
                af[m][1] = As2[base + 8 * LD2];
                af[m][2] = As2[base + 4];
                af[m][3] = As2[base + 8 * LD2 + 4];
            }
            uint32_t bf[8][2];
#pragma unroll
            for (int n = 0; n < 8; n++) {
                int base = (cw + n * 8 + lr) * LDK + kk + lc;
                bf[n][0] = Bs[base];
                bf[n][1] = Bs[base + 4];
            }
#pragma unroll
            for (int m = 0; m < 2; m++)
#pragma unroll
                for (int n = 0; n < 8; n++) mma8(acc[m][n], af[m], bf[n]);
        }
        __syncthreads();
    }
}

// GIN MLP: plain output
__global__ void __launch_bounds__(256, 2) k_mlp2(
    const float* __restrict__ A, int lda,
    const float* __restrict__ W1t, const float* __restrict__ b1,
    const float* __restrict__ W2t, const float* __restrict__ b2,
    float* __restrict__ O, int ldo, int M)
{
    extern __shared__ uint32_t sm[];
    uint32_t* As  = sm;
    uint32_t* Bs  = sm + 128 * LDK;
    uint32_t* As2 = sm + 2 * 128 * LDK;
    float acc[2][8][4];
    const int row0 = blockIdx.x * 128;
    mlp2_core(A, lda, W1t, b1, W2t, M, row0, As, Bs, As2, acc);

    const int tid = threadIdx.x;
    const int wid = tid >> 5, lane = tid & 31;
    const int lr = lane >> 2, lc = lane & 3;
    const int rw = (wid & 3) * 32, cw = (wid >> 2) * 64;
#pragma unroll
    for (int m = 0; m < 2; m++) {
#pragma unroll
        for (int n = 0; n < 8; n++) {
            int col = cw + n * 8 + lc * 2;
            float b0 = b2[col], bb1 = b2[col + 1];
            int r1 = row0 + rw + m * 16 + lr;
            int r2 = r1 + 8;
            if (r1 < M) {
                float2 ov = {acc[m][n][0] + b0, acc[m][n][1] + bb1};
                *(float2*)&O[(size_t)r1 * ldo + col] = ov;
            }
            if (r2 < M) {
                float2 ov = {acc[m][n][2] + b0, acc[m][n][3] + bb1};
                *(float2*)&O[(size_t)r2 * ldo + col] = ov;
            }
        }
    }
}

// edge MLP + fused GINE scatter
__global__ void __launch_bounds__(256, 2) k_mlp2s(
    const float* __restrict__ A, int lda,
    const float* __restrict__ W1t, const float* __restrict__ b1,
    const float* __restrict__ W2t, const float* __restrict__ b2,
    const int* __restrict__ src, const int* __restrict__ dst,
    const float* __restrict__ node, float* __restrict__ agg, int M)
{
    extern __shared__ uint32_t sm[];
    uint32_t* As  = sm;
    uint32_t* Bs  = sm + 128 * LDK;
    uint32_t* As2 = sm + 2 * 128 * LDK;
    float acc[2][8][4];
    const int row0 = blockIdx.x * 128;
    mlp2_core(A, lda, W1t, b1, W2t, M, row0, As, Bs, As2, acc);

    const int tid = threadIdx.x;
    const int wid = tid >> 5, lane = tid & 31;
    const int lr = lane >> 2, lc = lane & 3;
    const int rw = (wid & 3) * 32, cw = (wid >> 2) * 64;
#pragma unroll
    for (int m = 0; m < 2; m++) {
#pragma unroll
        for (int n = 0; n < 8; n++) {
            int col = cw + n * 8 + lc * 2;
            float b0 = b2[col], bb1 = b2[col + 1];
#pragma unroll
            for (int half = 0; half < 2; half++) {
                int e = row0 + rw + m * 16 + lr + half * 8;
                if (e < M) {
                    float v0 = acc[m][n][half * 2] + b0;
                    float v1 = acc[m][n][half * 2 + 1] + bb1;
                    int s = src[e], d = dst[e];
                    float2 nv = *(const float2*)&node[(size_t)s * 128 + col];
                    float m0 = fmaxf(nv.x + v0, 0.f);
                    float m1 = fmaxf(nv.y + v1, 0.f);
                    redv2(&agg[(size_t)d * 128 + col], m0, m1);
                }
            }
        }
    }
}

// ---------------- FFMA2 GEMM for embeddings; mode 0: node(+agg init), mode 1: edge(+scatter)
__global__ void __launch_bounds__(256) k_gemm(
    const float* __restrict__ A, int lda,
    const float* __restrict__ W, int ldw,
    const float* __restrict__ bias,
    float* __restrict__ O, int M, int K, int mode,
    const float* __restrict__ eps, float* __restrict__ agg,
    const int* __restrict__ src, const int* __restrict__ dst,
    const float* __restrict__ node)
{
    __shared__ __align__(16) unsigned long long Asd[16][65];
    __shared__ __align__(16) float Ws[16][128];
    const int tid = threadIdx.x;
    const int tx = tid & 31, ty = tid >> 5;
    const int row0 = blockIdx.x * 64;

    unsigned long long acc[8][2];
#pragma unroll
    for (int r = 0; r < 8; r++) { acc[r][0] = 0ULL; acc[r][1] = 0ULL; }

    for (int k0 = 0; k0 < K; k0 += 16) {
#pragma unroll
        for (int i = tid; i < 1024; i += 256) {
            int r = i >> 4, k = i & 15;
            int row = row0 + r, kk = k0 + k;
            float v = (row < M && kk < K) ? A[(size_t)row * lda + kk] : 0.f;
            U64F2 p; p.f.x = v; p.f.y = v;
            Asd[k][r] = p.u;
        }
#pragma unroll
        for (int i = tid; i < 2048; i += 256) {
            int k = i >> 7, j = i & 127;
            int kk = k0 + k;
            Ws[k][j] = (kk < K) ? W[(size_t)kk * ldw + j] : 0.f;
        }
        __syncthreads();
#pragma unroll
        for (int k = 0; k < 16; k++) {
            U128 w; w.v = *(const float4*)&Ws[k][tx << 2];
#pragma unroll
            for (int r = 0; r < 8; r++) {
                unsigned long long a = Asd[k][(ty << 3) + r];
                acc[r][0] = fma2(a, w.u[0], acc[r][0]);
                acc[r][1] = fma2(a, w.u[1], acc[r][1]);
            }
        }
        __syncthreads();
    }
    const int col = tx << 2;
    float4 b4 = *(const float4*)&bias[col];
    float escale = (mode == 0) ? (1.f + eps[0]) : 0.f;
#pragma unroll
    for (int r = 0; r < 8; r++) {
        int row = row0 + (ty << 3) + r;
        if (row < M) {
            U64F2 p0, p1; p0.u = acc[r][0]; p1.u = acc[r][1];
            float v0 = p0.f.x + b4.x, v1 = p0.f.y + b4.y;
            float v2 = p1.f.x + b4.z, v3 = p1.f.y + b4.w;
            float4 ov = {v0, v1, v2, v3};
            *(float4*)&O[(size_t)row * 128 + col] = ov;
            if (mode == 0) {
                float4 av = {escale * v0, escale * v1, escale * v2, escale * v3};
                *(float4*)&agg[(size_t)row * 128 + col] = av;
            } else {
                int s = src[row], d = dst[row];
                float4 nv = *(const float4*)&node[(size_t)s * 128 + col];
                redv4(&agg[(size_t)d * 128 + col],
                      fmaxf(nv.x + v0, 0.f), fmaxf(nv.y + v1, 0.f),
                      fmaxf(nv.z + v2, 0.f), fmaxf(nv.w + v3, 0.f));
            }
        }
    }
}

// ---------------- prep: weight transposes/stacks, pre-converted to tf32 ----------------
__device__ __forceinline__ float tf32f(float v) {
    return __uint_as_float(tf32cvt(v));
}
__global__ void k_prep(const float* __restrict__ gin1, const float* __restrict__ gin2,
                       const float* __restrict__ em1, const float* __restrict__ em2,
                       const float* __restrict__ fcw1,
                       const float* __restrict__ gwih, const float* __restrict__ gwhh,
                       const float* __restrict__ gbih, const float* __restrict__ gbhh,
                       const float* __restrict__ lwih, const float* __restrict__ lwhh,
                       const float* __restrict__ lbih, const float* __restrict__ lbhh,
                       float* __restrict__ tg1, float* __restrict__ tg2,
                       float* __restrict__ te1, float* __restrict__ te2,
                       float* __restrict__ tf1,
                       float* __restrict__ tgall, float* __restrict__ tgallb,
                       float* __restrict__ tgnh,
                       float* __restrict__ tlw, float* __restrict__ tlb)
{
    int i = blockIdx.x * blockDim.x + threadIdx.x;
    if (i < 131072) {
        int m = i >> 14, j = i & 16383;
        int r = j >> 7, c = j & 127;
        int l = m & 1, which = m >> 1;
        const float* s = (which == 0) ? gin1 : (which == 1) ? gin2 : (which == 2) ? em1 : em2;
        float* d = (which == 0) ? tg1 : (which == 1) ? tg2 : (which == 2) ? te1 : te2;
        d[(size_t)l * 16384 + c * 128 + r] = tf32f(s[(size_t)l * 16384 + j]);
    } else if (i < 163840) {
        int j = i - 131072;
        int r = j >> 7, c = j & 127;
        tf1[(size_t)c * 256 + r] = tf32f(fcw1[j]);
    } else if (i < 262144) {
        int j = i - 163840;                 // t_gall [384][256]
        int c = j >> 8, k = j & 255;
        float v = (k < 128) ? gwih[c * 128 + k]
                            : ((c < 256) ? gwhh[c * 128 + (k - 128)] : 0.f);
        tgall[j] = tf32f(v);
    } else if (i < 458752) {
        int j = i - 262144;                 // t_lw [512][384]
        int c = j / 384, k = j % 384;
        tlw[j] = tf32f((k < 256) ? lwih[c * 256 + k] : lwhh[c * 128 + (k - 256)]);
    } else if (i < 475136) {
        int j = i - 458752;                 // t_gnh [128][128] = gru_whh rows 256..383
        tgnh[j] = tf32f(gwhh[256 * 128 + j]);
    } else if (i < 475520) {
        int j = i - 475136;                 // t_gallb [384]
        tgallb[j] = (j < 256) ? gbih[j] + gbhh[j] : gbih[j];
    } else if (i < 476032) {
        int j = i - 475520;
        tlb[j] = lbih[j] + lbhh[j];
    }
}

__global__ void k_zero3(float4* __restrict__ a, int na, float4* __restrict__ b, int nb,
                        float4* __restrict__ c, int nc)
{
    int i = blockIdx.x * blockDim.x + threadIdx.x;
    float4 z = make_float4(0.f, 0.f, 0.f, 0.f);
    if (i < na) a[i] = z;
    if (i < nb) b[i] = z;
    if (i < nc) c[i] = z;
}

__device__ __forceinline__ void lstm1(float i_, float f_, float g_, float o_,
                                      float& c, float& hh) {
    c = sigf(f_) * c + sigf(i_) * tanhf(g_);
    hh = sigf(o_) * tanhf(c);
}

__global__ void k_lstm(const float* __restrict__ gl, float* __restrict__ hl,
                       float* __restrict__ cl, int nw)
{
    int idx = blockIdx.x * blockDim.x + threadIdx.x;
    if (idx >= nw) return;
    int g = idx >> 5, j = (idx & 31) * 4;
    const float* gr = &gl[(size_t)g * 512];
    float4 i_ = *(const float4*)&gr[j];
    float4 f_ = *(const float4*)&gr[j + 128];
    float4 g_ = *(const float4*)&gr[j + 256];
    float4 o_ = *(const float4*)&gr[j + 384];
    float4* cp = (float4*)&cl[(size_t)g * 128 + j];
    float4* hp = (float4*)&hl[(size_t)g * 128 + j];
    float4 c = *cp, hh;
    lstm1(i_.x, f_.x, g_.x, o_.x, c.x, hh.x);
    lstm1(i_.y, f_.y, g_.y, o_.y, c.y, hh.y);
    lstm1(i_.z, f_.z, g_.z, o_.z, c.z, hh.z);
    lstm1(i_.w, f_.w, g_.w, o_.w, c.w, hh.w);
    *cp = c;
    *hp = hh;
}

__global__ void k_set2set(const int* __restrict__ batch, const float* __restrict__ node,
                          const float* __restrict__ hl, float* __restrict__ qs,
                          int N, int G)
{
    int warp = (blockIdx.x * blockDim.x + threadIdx.x) >> 5;
    if (warp >= G) return;
    const int lane = threadIdx.x & 31;
    const int g = warp;

    int lo = 0, hi = N;
    while (lo < hi) { int mid = (lo + hi) >> 1; if (batch[mid] < g) lo = mid + 1; else hi = mid; }
    const int s0 = lo;
    hi = N;
    while (lo < hi) { int mid = (lo + hi) >> 1; if (batch[mid] < g + 1) lo = mid + 1; else hi = mid; }
    const int s1 = lo;

    float4 qv = *(const float4*)&hl[(size_t)g * H + lane * 4];

    float mx = -INFINITY, den = 0.f;
    float4 racc = make_float4(0.f, 0.f, 0.f, 0.f);
    for (int i = s0; i < s1; i++) {
        float4 nv = *(const float4*)&node[(size_t)i * H + lane * 4];
        float d = nv.x * qv.x + nv.y * qv.y + nv.z * qv.z + nv.w * qv.w;
#pragma unroll
        for (int o = 16; o; o >>= 1) d += __shfl_xor_sync(0xffffffffu, d, o);
        float nm = fmaxf(mx, d);
        float sc = expf(mx - nm);
        float ex = expf(d - nm);
        den = den * sc + ex;
        racc.x = racc.x * sc + ex * nv.x;
        racc.y = racc.y * sc + ex * nv.y;
        racc.z = racc.z * sc + ex * nv.z;
        racc.w = racc.w * sc + ex * nv.w;
        mx = nm;
    }
    float inv = 1.f / fmaxf(den, 1e-9f);
    float* qrow = &qs[(size_t)g * 2 * H];
    *(float4*)&qrow[lane * 4] = qv;
    float4 rv = {racc.x * inv, racc.y * inv, racc.z * inv, racc.w * inv};
    *(float4*)&qrow[H + lane * 4] = rv;
}

__global__ void k_fc2(const float* __restrict__ fcin, const float* __restrict__ w2,
                      const float* __restrict__ b2, float* __restrict__ out, int G)
{
    int tid = blockIdx.x * blockDim.x + threadIdx.x;
    int g = tid >> 5;
    if (g >= G) return;
    int lane = tid & 31;
    float s = 0.f;
#pragma unroll
    for (int t = 0; t < 4; t++) {
        int j = lane + t * 32;
        s += fcin[(size_t)g * H + j] * w2[j];
    }
#pragma unroll
    for (int off = 16; off; off >>= 1) s += __shfl_xor_sync(0xffffffffu, s, off);
    if (lane == 0) out[g] = s + b2[0];
}

// ---------------- host launcher ----------------
extern "C" void kernel_launch(void* const* d_in, const int* in_sizes, int n_in,
                              void* d_out, int out_size)
{
    const float* x       = (const float*)d_in[0];
    const float* eattr   = (const float*)d_in[1];
    const int*   eindex  = (const int*)d_in[2];
    const int*   batch   = (const int*)d_in[3];
    const float* node_w  = (const float*)d_in[4];
    const float* node_b  = (const float*)d_in[5];
    const float* edge_w  = (const float*)d_in[6];
    const float* edge_b  = (const float*)d_in[7];
    const float* eps     = (const float*)d_in[8];
    const float* gin_w1  = (const float*)d_in[9];
    const float* gin_b1  = (const float*)d_in[10];
    const float* gin_w2  = (const float*)d_in[11];
    const float* gin_b2  = (const float*)d_in[12];
    const float* em_w1   = (const float*)d_in[13];
    const float* em_b1   = (const float*)d_in[14];
    const float* em_w2   = (const float*)d_in[15];
    const float* em_b2   = (const float*)d_in[16];
    const float* gru_wih = (const float*)d_in[17];
    const float* gru_whh = (const float*)d_in[18];
    const float* gru_bih = (const float*)d_in[19];
    const float* gru_bhh = (const float*)d_in[20];
    const float* lstm_wih= (const float*)d_in[21];
    const float* lstm_whh= (const float*)d_in[22];
    const float* lstm_bih= (const float*)d_in[23];
    const float* lstm_bhh= (const float*)d_in[24];
    const float* fc_w1   = (const float*)d_in[25];
    const float* fc_b1   = (const float*)d_in[26];
    const float* fc_w2   = (const float*)d_in[27];
    const float* fc_b2   = (const float*)d_in[28];

    const int N = in_sizes[0] / 14;
    const int E = in_sizes[1] / 4;
    const int G = out_size;

    float *p_node, *p_edge, *p_agg, *p_m, *p_gates;
    float *p_qs, *p_hl, *p_cl, *p_gl, *p_fc;
    float *p_tg1, *p_tg2, *p_te1, *p_te2, *p_tf1, *p_tgall, *p_tgallb, *p_tgnh, *p_tlw, *p_tlb;
    cudaGetSymbolAddress((void**)&p_node, g_node);
    cudaGetSymbolAddress((void**)&p_edge, g_edge);
    cudaGetSymbolAddress((void**)&p_agg,  g_agg);
    cudaGetSymbolAddress((void**)&p_m,    g_m);
    cudaGetSymbolAddress((void**)&p_gates, g_gates);
    cudaGetSymbolAddress((void**)&p_qs,   g_qs);
    cudaGetSymbolAddress((void**)&p_hl,   g_hl);
    cudaGetSymbolAddress((void**)&p_cl,   g_cl);
    cudaGetSymbolAddress((void**)&p_gl,   g_gl);
    cudaGetSymbolAddress((void**)&p_fc,   g_fc);
    cudaGetSymbolAddress((void**)&p_tg1,  t_gin1);
    cudaGetSymbolAddress((void**)&p_tg2,  t_gin2);
    cudaGetSymbolAddress((void**)&p_te1,  t_em1);
    cudaGetSymbolAddress((void**)&p_te2,  t_em2);
    cudaGetSymbolAddress((void**)&p_tf1,  t_fc1);
    cudaGetSymbolAddress((void**)&p_tgall, t_gall);
    cudaGetSymbolAddress((void**)&p_tgallb, t_gallb);
    cudaGetSymbolAddress((void**)&p_tgnh, t_gnh);
    cudaGetSymbolAddress((void**)&p_tlw,  t_lw);
    cudaGetSymbolAddress((void**)&p_tlb,  t_lb);

    const int TB = 256;
    const int SMEM_MLP2 = (2 * 128 * LDK + 128 * LD2) * 4;
    cudaFuncSetAttribute(k_mlp2, cudaFuncAttributeMaxDynamicSharedMemorySize, SMEM_MLP2);
    cudaFuncSetAttribute(k_mlp2s, cudaFuncAttributeMaxDynamicSharedMemorySize, SMEM_MLP2);

    k_prep<<<CDIV(476032, TB), TB>>>(gin_w1, gin_w2, em_w1, em_w2, fc_w1,
                                     gru_wih, gru_whh, gru_bih, gru_bhh,
                                     lstm_wih, lstm_whh, lstm_bih, lstm_bhh,
                                     p_tg1, p_tg2, p_te1, p_te2, p_tf1,
                                     p_tgall, p_tgallb, p_tgnh, p_tlw, p_tlb);

    const int* src = eindex;
    const int* dst = eindex + E;

    k_gemm<<<CDIV(N, 64), 256>>>(x, 14, node_w, 128, node_b, p_node, N, 14, 0,
                                 eps, p_agg, nullptr, nullptr, nullptr);
    k_gemm<<<CDIV(E, 64), 256>>>(eattr, 4, edge_w, 128, edge_b, p_edge, E, 4, 1,
                                 eps, p_agg, src, dst, p_node);

    const int NT = CDIV(N, 128), ET = CDIV(E, 128), GT = CDIV(G, 128);

    for (int l = 0; l < 2; l++) {
        k_mlp2<<<NT, 256, SMEM_MLP2>>>(p_agg, 128, p_tg1 + l * 16384, gin_b1 + l * H,
                                       p_tg2 + l * 16384, gin_b2 + l * H, p_m, 128, N);
        k_tmma<<<dim3(NT, 3), 256>>>(p_m, 128, 128, p_node, 128, p_tgall, 256, p_tgallb,
                                     p_gates, 384, N, 256, 0, nullptr, nullptr, nullptr, 0);
        k_tmma<<<dim3(NT, 1), 256>>>(p_node, 128, 128, p_node, 128, p_tgnh, 128,
                                     gru_bhh + 256, p_node, 128, N, 128, 4,
                                     p_gates, p_agg, eps, (l == 0) ? 1 : -1);
        if (l == 0) {
            k_mlp2s<<<ET, 256, SMEM_MLP2>>>(p_edge, 128, p_te1, em_b1, p_te2, em_b2,
                                            src, dst, p_node, p_agg, E);
        }
    }

    // Set2Set
    k_zero3<<<CDIV(G * 64, TB), TB>>>((float4*)p_qs, G * 64, (float4*)p_hl, G * 32, (float4*)p_cl, G * 32);
    for (int step = 0; step < 3; step++) {
        k_tmma<<<dim3(GT, 4), 256>>>(p_qs, 256, 256, p_hl, 128, p_tlw, 384, p_tlb,
                                     p_gl, 512, G, 384, 0, nullptr, nullptr, nullptr, 0);
        k_lstm<<<CDIV(G * 32, TB), TB>>>(p_gl, p_hl, p_cl, G * 32);
        k_set2set<<<CDIV(G * 32, TB), TB>>>(batch, p_node, p_hl, p_qs, N, G);
    }

    // final MLP
    k_tmma<<<dim3(GT, 1), 256>>>(p_qs, 256, 256, p_qs, 256, p_tf1, 256, fc_b1,
                                 p_fc, 128, G, 256, 1, nullptr, nullptr, nullptr, 0);
    k_fc2<<<CDIV(G * 32, TB), TB>>>(p_fc, fc_w2, fc_b2, (float*)d_out, G);
}

// round 9
// speedup vs baseline: 4.5841x; 1.2175x over previous
#include <cuda_runtime.h>
#include <cuda_fp16.h>
#include <math.h>
#include <stdint.h>

#define H 128
#define NMAX 100000
#define EMAX 200000
#define GMAX 4096

#define CDIV(a,b) (((a)+(b)-1)/(b))

// ---------------- scratch ----------------
__device__ __align__(16) float g_node[(size_t)NMAX*H];
__device__ __align__(16) float g_edge[(size_t)EMAX*H];
__device__ __align__(16) float g_agg [(size_t)NMAX*H];
__device__ __align__(16) float g_m   [(size_t)NMAX*H];
__device__ __align__(16) float g_gates[(size_t)NMAX*3*H];   // [N][384]: r | z | n_i
__device__ __align__(16) float g_qs  [(size_t)GMAX*2*H];
__device__ __align__(16) float g_hl  [(size_t)GMAX*H];
__device__ __align__(16) float g_cl  [(size_t)GMAX*H];
__device__ __align__(16) float g_gl  [(size_t)GMAX*4*H];
__device__ __align__(16) float g_fc  [(size_t)GMAX*H];
// prepared weights (fp16)
__device__ __align__(16) __half t_gin1[2*H*H];
__device__ __align__(16) __half t_gin2[2*H*H];
__device__ __align__(16) __half t_em1 [2*H*H];
__device__ __align__(16) __half t_em2 [2*H*H];
__device__ __align__(16) __half t_fc1 [H*2*H];       // [128,256]
__device__ __align__(16) __half t_gall[384*256];     // rz (wih|whh) + n_i (wih|0)
__device__ __align__(16) __half t_gnh [H*H];         // gru_whh n-part [128,128]
__device__ __align__(16) __half t_lw  [512*384];     // lwih(256)|lwhh(128)
__device__ __align__(16) float t_gallb[384];
__device__ __align__(16) float t_lb  [512];

// ---------------- helpers ----------------
__device__ __forceinline__ float sigf(float x) { return 1.f / (1.f + expf(-x)); }

__device__ __forceinline__ unsigned long long fma2(unsigned long long a,
                                                   unsigned long long b,
                                                   unsigned long long c) {
    unsigned long long d;
    asm("fma.rn.f32x2 %0, %1, %2, %3;" : "=l"(d) : "l"(a), "l"(b), "l"(c));
    return d;
}
union U64F2 { unsigned long long u; float2 f; };
union U128 { float4 v; unsigned long long u[2]; };

__device__ __forceinline__ uint32_t h2pack(float a, float b) {
    __half2 h = __floats2half2_rn(a, b);
    return *(uint32_t*)&h;
}
__device__ __forceinline__ void mma16(float* c, const uint32_t* a, const uint32_t* b) {
    asm volatile(
        "mma.sync.aligned.m16n8k16.row.col.f32.f16.f16.f32 "
        "{%0,%1,%2,%3}, {%4,%5,%6,%7}, {%8,%9}, {%0,%1,%2,%3};"
        : "+f"(c[0]), "+f"(c[1]), "+f"(c[2]), "+f"(c[3])
        : "r"(a[0]), "r"(a[1]), "r"(a[2]), "r"(a[3]), "r"(b[0]), "r"(b[1]));
}
__device__ __forceinline__ void redv4(float* p, float a, float b, float c, float d) {
    asm volatile("red.global.add.v4.f32 [%0], {%1, %2, %3, %4};"
                 :: "l"(p), "f"(a), "f"(b), "f"(c), "f"(d) : "memory");
}
__device__ __forceinline__ void redv2(float* p, float a, float b) {
    asm volatile("red.global.add.v2.f32 [%0], {%1, %2};"
                 :: "l"(p), "f"(a), "f"(b) : "memory");
}
__device__ __forceinline__ void cpasync8(uint32_t saddr, const void* g) {
    asm volatile("cp.async.ca.shared.global [%0], [%1], 8;" :: "r"(saddr), "l"(g));
}

#define LDA2 20   // half2 units per row (16 data + 4 pad): conflict-free frag loads
#define LD2H 68   // mid-stage half2 row stride (64 data + 4 pad)

// fp16 mma inner loop on staged tiles ([row][k2] layout, LDA2 stride)
__device__ __forceinline__ void mma_block(const uint32_t* As, const uint32_t* Bs,
                                          float acc[2][8][4], int rw, int cw,
                                          int lr, int lc)
{
#pragma unroll
    for (int kk2 = 0; kk2 < 16; kk2 += 8) {
        uint32_t af[2][4];
#pragma unroll
        for (int m = 0; m < 2; m++) {
            int base = (rw + m * 16 + lr) * LDA2 + kk2 + lc;
            af[m][0] = As[base];
            af[m][1] = As[base + 8 * LDA2];
            af[m][2] = As[base + 4];
            af[m][3] = As[base + 8 * LDA2 + 4];
        }
        uint32_t bf[8][2];
#pragma unroll
        for (int n = 0; n < 8; n++) {
            int base = (cw + n * 8 + lr) * LDA2 + kk2 + lc;
            bf[n][0] = Bs[base];
            bf[n][1] = Bs[base + 4];
        }
#pragma unroll
        for (int m = 0; m < 2; m++)
#pragma unroll
            for (int n = 0; n < 8; n++) mma16(acc[m][n], af[m], bf[n]);
    }
}

// stage B tile [128 cols x 32 k] from fp16 weights via cp.async (8B chunks)
__device__ __forceinline__ void stage_B(uint32_t* Bs, const __half* Bt, int ldb,
                                        int col0, int k0, int tid)
{
#pragma unroll
    for (int i = 0; i < 4; i++) {
        int r = (tid >> 3) + i * 32;
        int e = tid & 7;
        uint32_t sa = (uint32_t)__cvta_generic_to_shared(&Bs[r * LDA2 + e * 2]);
        cpasync8(sa, &Bt[(size_t)(col0 + r) * ldb + k0 + e * 4]);
    }
}

// ---------------- k_tmma: O[M, col0+128] = act(concat(A,A2)[M,K] @ Bt^T + bias) ----------------
// flags: bit0 relu, bit1 accumulate, bit2 GRU-finalize.
__global__ void __launch_bounds__(256, 2) k_tmma(
    const float* __restrict__ A, int lda, int K1,
    const float* __restrict__ A2, int lda2,
    const __half* __restrict__ Bt, int ldb,
    const float* __restrict__ bias,
    float* __restrict__ O, int ldo,
    int M, int K, int flags,
    const float* __restrict__ gates, float* __restrict__ aggw,
    const float* __restrict__ eps, int epsidx)
{
    __shared__ uint32_t As[128 * LDA2];
    __shared__ uint32_t Bs[128 * LDA2];
    const int tid = threadIdx.x;
    const int wid = tid >> 5, lane = tid & 31;
    const int lr = lane >> 2, lc = lane & 3;
    const int row0 = blockIdx.x * 128;
    const int col0 = blockIdx.y * 128;
    const int rw = (wid & 3) * 32;
    const int cw = (wid >> 2) * 64;
    const int r_ = tid >> 3, f4_ = tid & 7;

    float acc[2][8][4];
#pragma unroll
    for (int m = 0; m < 2; m++)
#pragma unroll
        for (int n = 0; n < 8; n++)
#pragma unroll
            for (int c = 0; c < 4; c++) acc[m][n][c] = 0.f;

    float4 aR[4];
    {
        const float* srcA = (0 < K1) ? A : A2;
        int ldx = (0 < K1) ? lda : lda2;
#pragma unroll
        for (int i = 0; i < 4; i++) {
            int row = row0 + r_ + i * 32;
            aR[i] = make_float4(0.f, 0.f, 0.f, 0.f);
            if (row < M) aR[i] = *(const float4*)&srcA[(size_t)row * ldx + f4_ * 4];
        }
    }

    for (int k0 = 0; k0 < K; k0 += 32) {
        stage_B(Bs, Bt, ldb, col0, k0, tid);
        asm volatile("cp.async.commit_group;" ::: "memory");
#pragma unroll
        for (int i = 0; i < 4; i++) {
            int r = r_ + i * 32;
            uint32_t* p = &As[r * LDA2 + f4_ * 2];
            p[0] = h2pack(aR[i].x, aR[i].y);
            p[1] = h2pack(aR[i].z, aR[i].w);
        }
        int kn = k0 + 32;
        if (kn < K) {
            const float* srcA = (kn < K1) ? A : A2;
            int koff = (kn < K1) ? kn : kn - K1;
            int ldx = (kn < K1) ? lda : lda2;
#pragma unroll
            for (int i = 0; i < 4; i++) {
                int row = row0 + r_ + i * 32;
                aR[i] = make_float4(0.f, 0.f, 0.f, 0.f);
                if (row < M) aR[i] = *(const float4*)&srcA[(size_t)row * ldx + koff + f4_ * 4];
            }
        }
        asm volatile("cp.async.wait_group 0;" ::: "memory");
        __syncthreads();
        mma_block(As, Bs, acc, rw, cw, lr, lc);
        __syncthreads();
    }

    if (flags & 4) {
        float escale = (epsidx >= 0) ? (1.f + eps[epsidx]) : 0.f;
#pragma unroll
        for (int m = 0; m < 2; m++) {
#pragma unroll
            for (int n = 0; n < 8; n++) {
                int col = cw + n * 8 + lc * 2;
                float b0 = bias[col], b1 = bias[col + 1];
#pragma unroll
                for (int half = 0; half < 2; half++) {
                    int row = row0 + rw + m * 16 + lr + half * 8;
                    if (row < M) {
                        float nh0 = acc[m][n][half * 2] + b0;
                        float nh1 = acc[m][n][half * 2 + 1] + b1;
                        const float* gr = &gates[(size_t)row * 384];
                        float2 rr = *(const float2*)&gr[col];
                        float2 zz = *(const float2*)&gr[col + 128];
                        float2 ni = *(const float2*)&gr[col + 256];
                        float* hp = &O[(size_t)row * ldo + col];
                        float2 hv = *(float2*)hp;
                        float r0 = sigf(rr.x), z0 = sigf(zz.x);
                        float nn0 = tanhf(ni.x + r0 * nh0);
                        float h0 = (1.f - z0) * nn0 + z0 * hv.x;
                        float r1 = sigf(rr.y), z1 = sigf(zz.y);
                        float nn1 = tanhf(ni.y + r1 * nh1);
                        float h1 = (1.f - z1) * nn1 + z1 * hv.y;
                        float2 ho = {h0, h1};
                        *(float2*)hp = ho;
                        if (epsidx >= 0) {
                            float2 ao = {escale * h0, escale * h1};
                            *(float2*)&aggw[(size_t)row * 128 + col] = ao;
                        }
                    }
                }
            }
        }
        return;
    }

#pragma unroll
    for (int m = 0; m < 2; m++) {
#pragma unroll
        for (int n = 0; n < 8; n++) {
            int col = col0 + cw + n * 8 + lc * 2;
            float b0 = bias[col], b1 = bias[col + 1];
            int r1 = row0 + rw + m * 16 + lr;
            int r2 = r1 + 8;
            if (r1 < M) {
                float v0 = acc[m][n][0] + b0, v1 = acc[m][n][1] + b1;
                float* op = &O[(size_t)r1 * ldo + col];
                if (flags & 2) { v0 += op[0]; v1 += op[1]; }
                if (flags & 1) { v0 = fmaxf(v0, 0.f); v1 = fmaxf(v1, 0.f); }
                float2 ov = {v0, v1};
                *(float2*)op = ov;
            }
            if (r2 < M) {
                float v0 = acc[m][n][2] + b0, v1 = acc[m][n][3] + b1;
                float* op = &O[(size_t)r2 * ldo + col];
                if (flags & 2) { v0 += op[0]; v1 += op[1]; }
                if (flags & 1) { v0 = fmaxf(v0, 0.f); v1 = fmaxf(v1, 0.f); }
                float2 ov = {v0, v1};
                *(float2*)op = ov;
            }
        }
    }
}

// ---------------- fused 2-layer MLP core ----------------
__device__ __forceinline__ void mlp2_core(
    const float* __restrict__ A, int lda,
    const __half* __restrict__ W1t, const float* __restrict__ b1,
    const __half* __restrict__ W2t, int M, int row0,
    uint32_t* As, uint32_t* Bs, uint32_t* As2, float acc[2][8][4])
{
    const int tid = threadIdx.x;
    const int wid = tid >> 5, lane = tid & 31;
    const int lr = lane >> 2, lc = lane & 3;
    const int rw = (wid & 3) * 32;
    const int cw = (wid >> 2) * 64;
    const int r_ = tid >> 3, f4_ = tid & 7;

#pragma unroll
    for (int m = 0; m < 2; m++)
#pragma unroll
        for (int n = 0; n < 8; n++)
#pragma unroll
            for (int c = 0; c < 4; c++) acc[m][n][c] = 0.f;

    float4 aR[4];
#pragma unroll
    for (int i = 0; i < 4; i++) {
        int row = row0 + r_ + i * 32;
        aR[i] = make_float4(0.f, 0.f, 0.f, 0.f);
        if (row < M) aR[i] = *(const float4*)&A[(size_t)row * lda + f4_ * 4];
    }

    // GEMM1
    for (int k0 = 0; k0 < 128; k0 += 32) {
        stage_B(Bs, W1t, 128, 0, k0, tid);
        asm volatile("cp.async.commit_group;" ::: "memory");
#pragma unroll
        for (int i = 0; i < 4; i++) {
            int r = r_ + i * 32;
            uint32_t* p = &As[r * LDA2 + f4_ * 2];
            p[0] = h2pack(aR[i].x, aR[i].y);
            p[1] = h2pack(aR[i].z, aR[i].w);
        }
        int kn = k0 + 32;
        if (kn < 128) {
#pragma unroll
            for (int i = 0; i < 4; i++) {
                int row = row0 + r_ + i * 32;
                aR[i] = make_float4(0.f, 0.f, 0.f, 0.f);
                if (row < M) aR[i] = *(const float4*)&A[(size_t)row * lda + kn + f4_ * 4];
            }
        }
        asm volatile("cp.async.wait_group 0;" ::: "memory");
        __syncthreads();
        mma_block(As, Bs, acc, rw, cw, lr, lc);
        __syncthreads();
    }

    // mid epilogue: relu(+b1) -> As2 (half2 per col pair)
#pragma unroll
    for (int m = 0; m < 2; m++) {
#pragma unroll
        for (int n = 0; n < 8; n++) {
            int c2 = (cw >> 1) + n * 4 + lc;       // half2 column index
            int col = cw + n * 8 + lc * 2;
            float b0 = b1[col], bb1 = b1[col + 1];
            int r1 = rw + m * 16 + lr, r2 = r1 + 8;
            As2[r1 * LD2H + c2] = h2pack(fmaxf(acc[m][n][0] + b0, 0.f),
                                         fmaxf(acc[m][n][1] + bb1, 0.f));
            As2[r2 * LD2H + c2] = h2pack(fmaxf(acc[m][n][2] + b0, 0.f),
                                         fmaxf(acc[m][n][3] + bb1, 0.f));
            acc[m][n][0] = acc[m][n][1] = acc[m][n][2] = acc[m][n][3] = 0.f;
        }
    }
    __syncthreads();

    // GEMM2: As2 @ W2t
    for (int k0 = 0; k0 < 128; k0 += 32) {
        stage_B(Bs, W2t, 128, 0, k0, tid);
        asm volatile("cp.async.commit_group;" ::: "memory");
        asm volatile("cp.async.wait_group 0;" ::: "memory");
        __syncthreads();
        const int k2b = k0 >> 1;
#pragma unroll
        for (int kk2 = 0; kk2 < 16; kk2 += 8) {
            uint32_t af[2][4];
#pragma unroll
            for (int m = 0; m < 2; m++) {
                int base = (rw + m * 16 + lr) * LD2H + k2b + kk2 + lc;
                af[m][0] = As2[base];
                af[m][1] = As2[base + 8 * LD2H];
                af[m][2] = As2[base + 4];
                af[m][3] = As2[base + 8 * LD2H + 4];
            }
            uint32_t bf[8][2];
#pragma unroll
            for (int n = 0; n < 8; n++) {
                int base = (cw + n * 8 + lr) * LDA2 + kk2 + lc;
                bf[n][0] = Bs[base];
                bf[n][1] = Bs[base + 4];
            }
#pragma unroll
            for (int m = 0; m < 2; m++)
#pragma unroll
                for (int n = 0; n < 8; n++) mma16(acc[m][n], af[m], bf[n]);
        }
        __syncthreads();
    }
}

// GIN MLP: plain output
__global__ void __launch_bounds__(256, 2) k_mlp2(
    const float* __restrict__ A, int lda,
    const __half* __restrict__ W1t, const float* __restrict__ b1,
    const __half* __restrict__ W2t, const float* __restrict__ b2,
    float* __restrict__ O, int ldo, int M)
{
    extern __shared__ uint32_t sm[];
    uint32_t* As  = sm;
    uint32_t* Bs  = sm + 128 * LDA2;
    uint32_t* As2 = sm + 2 * 128 * LDA2;
    float acc[2][8][4];
    const int row0 = blockIdx.x * 128;
    mlp2_core(A, lda, W1t, b1, W2t, M, row0, As, Bs, As2, acc);

    const int tid = threadIdx.x;
    const int wid = tid >> 5, lane = tid & 31;
    const int lr = lane >> 2, lc = lane & 3;
    const int rw = (wid & 3) * 32, cw = (wid >> 2) * 64;
#pragma unroll
    for (int m = 0; m < 2; m++) {
#pragma unroll
        for (int n = 0; n < 8; n++) {
            int col = cw + n * 8 + lc * 2;
            float b0 = b2[col], bb1 = b2[col + 1];
            int r1 = row0 + rw + m * 16 + lr;
            int r2 = r1 + 8;
            if (r1 < M) {
                float2 ov = {acc[m][n][0] + b0, acc[m][n][1] + bb1};
                *(float2*)&O[(size_t)r1 * ldo + col] = ov;
            }
            if (r2 < M) {
                float2 ov = {acc[m][n][2] + b0, acc[m][n][3] + bb1};
                *(float2*)&O[(size_t)r2 * ldo + col] = ov;
            }
        }
    }
}

// edge MLP + fused GINE scatter
__global__ void __launch_bounds__(256, 2) k_mlp2s(
    const float* __restrict__ A, int lda,
    const __half* __restrict__ W1t, const float* __restrict__ b1,
    const __half* __restrict__ W2t, const float* __restrict__ b2,
    const int* __restrict__ src, const int* __restrict__ dst,
    const float* __restrict__ node, float* __restrict__ agg, int M)
{
    extern __shared__ uint32_t sm[];
    uint32_t* As  = sm;
    uint32_t* Bs  = sm + 128 * LDA2;
    uint32_t* As2 = sm + 2 * 128 * LDA2;
    float acc[2][8][4];
    const int row0 = blockIdx.x * 128;
    mlp2_core(A, lda, W1t, b1, W2t, M, row0, As, Bs, As2, acc);

    const int tid = threadIdx.x;
    const int wid = tid >> 5, lane = tid & 31;
    const int lr = lane >> 2, lc = lane & 3;
    const int rw = (wid & 3) * 32, cw = (wid >> 2) * 64;
#pragma unroll
    for (int m = 0; m < 2; m++) {
#pragma unroll
        for (int n = 0; n < 8; n++) {
            int col = cw + n * 8 + lc * 2;
            float b0 = b2[col], bb1 = b2[col + 1];
#pragma unroll
            for (int half = 0; half < 2; half++) {
                int e = row0 + rw + m * 16 + lr + half * 8;
                if (e < M) {
                    float v0 = acc[m][n][half * 2] + b0;
                    float v1 = acc[m][n][half * 2 + 1] + bb1;
                    int s = src[e], d = dst[e];
                    float2 nv = *(const float2*)&node[(size_t)s * 128 + col];
                    float m0 = fmaxf(nv.x + v0, 0.f);
                    float m1 = fmaxf(nv.y + v1, 0.f);
                    redv2(&agg[(size_t)d * 128 + col], m0, m1);
                }
            }
        }
    }
}

// ---------------- FFMA2 GEMM for embeddings; mode 0: node(+agg init), mode 1: edge(+scatter)
__global__ void __launch_bounds__(256) k_gemm(
    const float* __restrict__ A, int lda,
    const float* __restrict__ W, int ldw,
    const float* __restrict__ bias,
    float* __restrict__ O, int M, int K, int mode,
    const float* __restrict__ eps, float* __restrict__ agg,
    const int* __restrict__ src, const int* __restrict__ dst,
    const float* __restrict__ node)
{
    __shared__ __align__(16) unsigned long long Asd[16][65];
    __shared__ __align__(16) float Ws[16][128];
    const int tid = threadIdx.x;
    const int tx = tid & 31, ty = tid >> 5;
    const int row0 = blockIdx.x * 64;

    unsigned long long acc[8][2];
#pragma unroll
    for (int r = 0; r < 8; r++) { acc[r][0] = 0ULL; acc[r][1] = 0ULL; }

    for (int k0 = 0; k0 < K; k0 += 16) {
#pragma unroll
        for (int i = tid; i < 1024; i += 256) {
            int r = i >> 4, k = i & 15;
            int row = row0 + r, kk = k0 + k;
            float v = (row < M && kk < K) ? A[(size_t)row * lda + kk] : 0.f;
            U64F2 p; p.f.x = v; p.f.y = v;
            Asd[k][r] = p.u;
        }
#pragma unroll
        for (int i = tid; i < 2048; i += 256) {
            int k = i >> 7, j = i & 127;
            int kk = k0 + k;
            Ws[k][j] = (kk < K) ? W[(size_t)kk * ldw + j] : 0.f;
        }
        __syncthreads();
#pragma unroll
        for (int k = 0; k < 16; k++) {
            U128 w; w.v = *(const float4*)&Ws[k][tx << 2];
#pragma unroll
            for (int r = 0; r < 8; r++) {
                unsigned long long a = Asd[k][(ty << 3) + r];
                acc[r][0] = fma2(a, w.u[0], acc[r][0]);
                acc[r][1] = fma2(a, w.u[1], acc[r][1]);
            }
        }
        __syncthreads();
    }
    const int col = tx << 2;
    float4 b4 = *(const float4*)&bias[col];
    float escale = (mode == 0) ? (1.f + eps[0]) : 0.f;
#pragma unroll
    for (int r = 0; r < 8; r++) {
        int row = row0 + (ty << 3) + r;
        if (row < M) {
            U64F2 p0, p1; p0.u = acc[r][0]; p1.u = acc[r][1];
            float v0 = p0.f.x + b4.x, v1 = p0.f.y + b4.y;
            float v2 = p1.f.x + b4.z, v3 = p1.f.y + b4.w;
            float4 ov = {v0, v1, v2, v3};
            *(float4*)&O[(size_t)row * 128 + col] = ov;
            if (mode == 0) {
                float4 av = {escale * v0, escale * v1, escale * v2, escale * v3};
                *(float4*)&agg[(size_t)row * 128 + col] = av;
            } else {
                int s = src[row], d = dst[row];
                float4 nv = *(const float4*)&node[(size_t)s * 128 + col];
                redv4(&agg[(size_t)d * 128 + col],
                      fmaxf(nv.x + v0, 0.f), fmaxf(nv.y + v1, 0.f),
                      fmaxf(nv.z + v2, 0.f), fmaxf(nv.w + v3, 0.f));
            }
        }
    }
}

// ---------------- prep: weight transposes/stacks -> fp16 ----------------
__global__ void k_prep(const float* __restrict__ gin1, const float* __restrict__ gin2,
                       const float* __restrict__ em1, const float* __restrict__ em2,
                       const float* __restrict__ fcw1,
                       const float* __restrict__ gwih, const float* __restrict__ gwhh,
                       const float* __restrict__ gbih, const float* __restrict__ gbhh,
                       const float* __restrict__ lwih, const float* __restrict__ lwhh,
                       const float* __restrict__ lbih, const float* __restrict__ lbhh,
                       __half* __restrict__ tg1, __half* __restrict__ tg2,
                       __half* __restrict__ te1, __half* __restrict__ te2,
                       __half* __restrict__ tf1,
                       __half* __restrict__ tgall, float* __restrict__ tgallb,
                       __half* __restrict__ tgnh,
                       __half* __restrict__ tlw, float* __restrict__ tlb)
{
    int i = blockIdx.x * blockDim.x + threadIdx.x;
    if (i < 131072) {
        int m = i >> 14, j = i & 16383;
        int r = j >> 7, c = j & 127;
        int l = m & 1, which = m >> 1;
        const float* s = (which == 0) ? gin1 : (which == 1) ? gin2 : (which == 2) ? em1 : em2;
        __half* d = (which == 0) ? tg1 : (which == 1) ? tg2 : (which == 2) ? te1 : te2;
        d[(size_t)l * 16384 + c * 128 + r] = __float2half_rn(s[(size_t)l * 16384 + j]);
    } else if (i < 163840) {
        int j = i - 131072;
        int r = j >> 7, c = j & 127;
        tf1[(size_t)c * 256 + r] = __float2half_rn(fcw1[j]);
    } else if (i < 262144) {
        int j = i - 163840;                 // t_gall [384][256]
        int c = j >> 8, k = j & 255;
        float v = (k < 128) ? gwih[c * 128 + k]
                            : ((c < 256) ? gwhh[c * 128 + (k - 128)] : 0.f);
        tgall[j] = __float2half_rn(v);
    } else if (i < 458752) {
        int j = i - 262144;                 // t_lw [512][384]
        int c = j / 384, k = j % 384;
        tlw[j] = __float2half_rn((k < 256) ? lwih[c * 256 + k] : lwhh[c * 128 + (k - 256)]);
    } else if (i < 475136) {
        int j = i - 458752;                 // t_gnh [128][128]
        tgnh[j] = __float2half_rn(gwhh[256 * 128 + j]);
    } else if (i < 475520) {
        int j = i - 475136;
        tgallb[j] = (j < 256) ? gbih[j] + gbhh[j] : gbih[j];
    } else if (i < 476032) {
        int j = i - 475520;
        tlb[j] = lbih[j] + lbhh[j];
    }
}

__global__ void k_zero3(float4* __restrict__ a, int na, float4* __restrict__ b, int nb,
                        float4* __restrict__ c, int nc)
{
    int i = blockIdx.x * blockDim.x + threadIdx.x;
    float4 z = make_float4(0.f, 0.f, 0.f, 0.f);
    if (i < na) a[i] = z;
    if (i < nb) b[i] = z;
    if (i < nc) c[i] = z;
}

__device__ __forceinline__ void lstm1(float i_, float f_, float g_, float o_,
                                      float& c, float& hh) {
    c = sigf(f_) * c + sigf(i_) * tanhf(g_);
    hh = sigf(o_) * tanhf(c);
}

__global__ void k_lstm(const float* __restrict__ gl, float* __restrict__ hl,
                       float* __restrict__ cl, int nw)
{
    int idx = blockIdx.x * blockDim.x + threadIdx.x;
    if (idx >= nw) return;
    int g = idx >> 5, j = (idx & 31) * 4;
    const float* gr = &gl[(size_t)g * 512];
    float4 i_ = *(const float4*)&gr[j];
    float4 f_ = *(const float4*)&gr[j + 128];
    float4 g_ = *(const float4*)&gr[j + 256];
    float4 o_ = *(const float4*)&gr[j + 384];
    float4* cp = (float4*)&cl[(size_t)g * 128 + j];
    float4* hp = (float4*)&hl[(size_t)g * 128 + j];
    float4 c = *cp, hh;
    lstm1(i_.x, f_.x, g_.x, o_.x, c.x, hh.x);
    lstm1(i_.y, f_.y, g_.y, o_.y, c.y, hh.y);
    lstm1(i_.z, f_.z, g_.z, o_.z, c.z, hh.z);
    lstm1(i_.w, f_.w, g_.w, o_.w, c.w, hh.w);
    *cp = c;
    *hp = hh;
}

__global__ void k_set2set(const int* __restrict__ batch, const float* __restrict__ node,
                          const float* __restrict__ hl, float* __restrict__ qs,
                          int N, int G)
{
    int warp = (blockIdx.x * blockDim.x + threadIdx.x) >> 5;
    if (warp >= G) return;
    const int lane = threadIdx.x & 31;
    const int g = warp;

    int lo = 0, hi = N;
    while (lo < hi) { int mid = (lo + hi) >> 1; if (batch[mid] < g) lo = mid + 1; else hi = mid; }
    const int s0 = lo;
    hi = N;
    while (lo < hi) { int mid = (lo + hi) >> 1; if (batch[mid] < g + 1) lo = mid + 1; else hi = mid; }
    const int s1 = lo;

    float4 qv = *(const float4*)&hl[(size_t)g * H + lane * 4];

    float mx = -INFINITY, den = 0.f;
    float4 racc = make_float4(0.f, 0.f, 0.f, 0.f);
    for (int i = s0; i < s1; i++) {
        float4 nv = *(const float4*)&node[(size_t)i * H + lane * 4];
        float d = nv.x * qv.x + nv.y * qv.y + nv.z * qv.z + nv.w * qv.w;
#pragma unroll
        for (int o = 16; o; o >>= 1) d += __shfl_xor_sync(0xffffffffu, d, o);
        float nm = fmaxf(mx, d);
        float sc = expf(mx - nm);
        float ex = expf(d - nm);
        den = den * sc + ex;
        racc.x = racc.x * sc + ex * nv.x;
        racc.y = racc.y * sc + ex * nv.y;
        racc.z = racc.z * sc + ex * nv.z;
        racc.w = racc.w * sc + ex * nv.w;
        mx = nm;
    }
    float inv = 1.f / fmaxf(den, 1e-9f);
    float* qrow = &qs[(size_t)g * 2 * H];
    *(float4*)&qrow[lane * 4] = qv;
    float4 rv = {racc.x * inv, racc.y * inv, racc.z * inv, racc.w * inv};
    *(float4*)&qrow[H + lane * 4] = rv;
}

__global__ void k_fc2(const float* __restrict__ fcin, const float* __restrict__ w2,
                      const float* __restrict__ b2, float* __restrict__ out, int G)
{
    int tid = blockIdx.x * blockDim.x + threadIdx.x;
    int g = tid >> 5;
    if (g >= G) return;
    int lane = tid & 31;
    float s = 0.f;
#pragma unroll
    for (int t = 0; t < 4; t++) {
        int j = lane + t * 32;
        s += fcin[(size_t)g * H + j] * w2[j];
    }
#pragma unroll
    for (int off = 16; off; off >>= 1) s += __shfl_xor_sync(0xffffffffu, s, off);
    if (lane == 0) out[g] = s + b2[0];
}

// ---------------- host launcher ----------------
extern "C" void kernel_launch(void* const* d_in, const int* in_sizes, int n_in,
                              void* d_out, int out_size)
{
    const float* x       = (const float*)d_in[0];
    const float* eattr   = (const float*)d_in[1];
    const int*   eindex  = (const int*)d_in[2];
    const int*   batch   = (const int*)d_in[3];
    const float* node_w  = (const float*)d_in[4];
    const float* node_b  = (const float*)d_in[5];
    const float* edge_w  = (const float*)d_in[6];
    const float* edge_b  = (const float*)d_in[7];
    const float* eps     = (const float*)d_in[8];
    const float* gin_w1  = (const float*)d_in[9];
    const float* gin_b1  = (const float*)d_in[10];
    const float* gin_w2  = (const float*)d_in[11];
    const float* gin_b2  = (const float*)d_in[12];
    const float* em_w1   = (const float*)d_in[13];
    const float* em_b1   = (const float*)d_in[14];
    const float* em_w2   = (const float*)d_in[15];
    const float* em_b2   = (const float*)d_in[16];
    const float* gru_wih = (const float*)d_in[17];
    const float* gru_whh = (const float*)d_in[18];
    const float* gru_bih = (const float*)d_in[19];
    const float* gru_bhh = (const float*)d_in[20];
    const float* lstm_wih= (const float*)d_in[21];
    const float* lstm_whh= (const float*)d_in[22];
    const float* lstm_bih= (const float*)d_in[23];
    const float* lstm_bhh= (const float*)d_in[24];
    const float* fc_w1   = (const float*)d_in[25];
    const float* fc_b1   = (const float*)d_in[26];
    const float* fc_w2   = (const float*)d_in[27];
    const float* fc_b2   = (const float*)d_in[28];

    const int N = in_sizes[0] / 14;
    const int E = in_sizes[1] / 4;
    const int G = out_size;

    float *p_node, *p_edge, *p_agg, *p_m, *p_gates;
    float *p_qs, *p_hl, *p_cl, *p_gl, *p_fc;
    __half *p_tg1, *p_tg2, *p_te1, *p_te2, *p_tf1, *p_tgall, *p_tgnh, *p_tlw;
    float *p_tgallb, *p_tlb;
    cudaGetSymbolAddress((void**)&p_node, g_node);
    cudaGetSymbolAddress((void**)&p_edge, g_edge);
    cudaGetSymbolAddress((void**)&p_agg,  g_agg);
    cudaGetSymbolAddress((void**)&p_m,    g_m);
    cudaGetSymbolAddress((void**)&p_gates, g_gates);
    cudaGetSymbolAddress((void**)&p_qs,   g_qs);
    cudaGetSymbolAddress((void**)&p_hl,   g_hl);
    cudaGetSymbolAddress((void**)&p_cl,   g_cl);
    cudaGetSymbolAddress((void**)&p_gl,   g_gl);
    cudaGetSymbolAddress((void**)&p_fc,   g_fc);
    cudaGetSymbolAddress((void**)&p_tg1,  t_gin1);
    cudaGetSymbolAddress((void**)&p_tg2,  t_gin2);
    cudaGetSymbolAddress((void**)&p_te1,  t_em1);
    cudaGetSymbolAddress((void**)&p_te2,  t_em2);
    cudaGetSymbolAddress((void**)&p_tf1,  t_fc1);
    cudaGetSymbolAddress((void**)&p_tgall, t_gall);
    cudaGetSymbolAddress((void**)&p_tgallb, t_gallb);
    cudaGetSymbolAddress((void**)&p_tgnh, t_gnh);
    cudaGetSymbolAddress((void**)&p_tlw,  t_lw);
    cudaGetSymbolAddress((void**)&p_tlb,  t_lb);

    const int TB = 256;
    const int SMEM_MLP2 = (2 * 128 * LDA2 + 128 * LD2H) * 4;
    cudaFuncSetAttribute(k_mlp2, cudaFuncAttributeMaxDynamicSharedMemorySize, SMEM_MLP2);
    cudaFuncSetAttribute(k_mlp2s, cudaFuncAttributeMaxDynamicSharedMemorySize, SMEM_MLP2);

    k_prep<<<CDIV(476032, TB), TB>>>(gin_w1, gin_w2, em_w1, em_w2, fc_w1,
                                     gru_wih, gru_whh, gru_bih, gru_bhh,
                                     lstm_wih, lstm_whh, lstm_bih, lstm_bhh,
                                     p_tg1, p_tg2, p_te1, p_te2, p_tf1,
                                     p_tgall, p_tgallb, p_tgnh, p_tlw, p_tlb);

    const int* src = eindex;
    const int* dst = eindex + E;

    k_gemm<<<CDIV(N, 64), 256>>>(x, 14, node_w, 128, node_b, p_node, N, 14, 0,
                                 eps, p_agg, nullptr, nullptr, nullptr);
    k_gemm<<<CDIV(E, 64), 256>>>(eattr, 4, edge_w, 128, edge_b, p_edge, E, 4, 1,
                                 eps, p_agg, src, dst, p_node);

    const int NT = CDIV(N, 128), ET = CDIV(E, 128), GT = CDIV(G, 128);

    for (int l = 0; l < 2; l++) {
        k_mlp2<<<NT, 256, SMEM_MLP2>>>(p_agg, 128, p_tg1 + l * 16384, gin_b1 + l * H,
                                       p_tg2 + l * 16384, gin_b2 + l * H, p_m, 128, N);
        k_tmma<<<dim3(NT, 3), 256>>>(p_m, 128, 128, p_node, 128, p_tgall, 256, p_tgallb,
                                     p_gates, 384, N, 256, 0, nullptr, nullptr, nullptr, 0);
        k_tmma<<<dim3(NT, 1), 256>>>(p_node, 128, 128, p_node, 128, p_tgnh, 128,
                                     gru_bhh + 256, p_node, 128, N, 128, 4,
                                     p_gates, p_agg, eps, (l == 0) ? 1 : -1);
        if (l == 0) {
            k_mlp2s<<<ET, 256, SMEM_MLP2>>>(p_edge, 128, p_te1, em_b1, p_te2, em_b2,
                                            src, dst, p_node, p_agg, E);
        }
    }

    // Set2Set
    k_zero3<<<CDIV(G * 64, TB), TB>>>((float4*)p_qs, G * 64, (float4*)p_hl, G * 32, (float4*)p_cl, G * 32);
    for (int step = 0; step < 3; step++) {
        k_tmma<<<dim3(GT, 4), 256>>>(p_qs, 256, 256, p_hl, 128, p_tlw, 384, p_tlb,
                                     p_gl, 512, G, 384, 0, nullptr, nullptr, nullptr, 0);
        k_lstm<<<CDIV(G * 32, TB), TB>>>(p_gl, p_hl, p_cl, G * 32);
        k_set2set<<<CDIV(G * 32, TB), TB>>>(batch, p_node, p_hl, p_qs, N, G);
    }

    // final MLP
    k_tmma<<<dim3(GT, 1), 256>>>(p_qs, 256, 256, p_qs, 256, p_tf1, 256, fc_b1,
                                 p_fc, 128, G, 256, 1, nullptr, nullptr, nullptr, 0);
    k_fc2<<<CDIV(G * 32, TB), TB>>>(p_fc, fc_w2, fc_b2, (float*)d_out, G);
}